// round 3
// baseline (speedup 1.0000x reference)
#include <cuda_runtime.h>
#include <cuda_bf16.h>
#include <cuda_pipeline.h>
#include <mma.h>

using namespace nvcuda;

// Problem dims (fixed by reference): B=32, L=512, D=256, H=4
#define BB 32
#define LL 512
#define DD 256
#define HH 4
#define NTOK (BB * LL)            // 16384
#define BH (BB * HH)              // 128
#define HD (HH * DD)              // 1024

// ---------------- device scratch (allocation-free; .bss) ----------------
__device__ __align__(256) float g_Qp[NTOK * DD];
__device__ __align__(256) float g_Kp[NTOK * DD];
__device__ __align__(256) float g_Vp[NTOK * DD];
__device__ __align__(256) float g_Qh[BH * LL * DD];
__device__ __align__(256) float g_Kh[BH * LL * DD];
__device__ __align__(256) float g_Vh[BH * LL * DD];
__device__ __align__(256) float g_S[(size_t)BH * LL * LL];   // scores / probs (in-place)
__device__ __align__(256) float g_Vm[NTOK * HD];             // merged heads (B,L,H*D)
__device__ __align__(256) float g_T1[NTOK * DD];             // attn out-proj
__device__ __align__(256) float g_X[NTOK * DD];              // LN1 output
__device__ __align__(256) float g_Y[NTOK * DD];              // FFN hidden
__device__ __align__(256) float g_Z[NTOK * DD];              // FFN out
__device__ int g_pad[NTOK];
__device__ int g_byte_mode;

// ---------------- mask dtype sniffing + decode ----------------
__global__ void detect_mask_kernel(const unsigned char* m) {
    __shared__ int any;
    if (threadIdx.x == 0) any = 0;
    __syncthreads();
    int local = 0;
    for (int i = threadIdx.x; i < NTOK / 4; i += blockDim.x)
        if (m[4 * i + 1]) local = 1;
    if (local) atomicOr(&any, 1);
    __syncthreads();
    if (threadIdx.x == 0) g_byte_mode = any;
}

__global__ void decode_mask_kernel(const void* m) {
    int i = blockIdx.x * blockDim.x + threadIdx.x;
    if (i >= NTOK) return;
    int v;
    if (g_byte_mode)
        v = ((const unsigned char*)m)[i] != 0;
    else
        v = ((const int*)m)[i] != 0;
    g_pad[i] = v;
}

// ---------------- positional encoding add ----------------
__global__ void add_pe_kernel(const float* __restrict__ in, const float* __restrict__ pe,
                              float* __restrict__ out) {
    int i = blockIdx.x * blockDim.x + threadIdx.x;
    if (i >= NTOK * DD) return;
    int d = i & (DD - 1);
    int l = (i >> 8) & (LL - 1);
    out[i] = in[i] + pe[l * DD + d];
}

// ---------------- tf32 wmma GEMM: 128x128x16 tiles, cp.async double buffer ----------------
// C = alpha * A @ op(B) (+bias) (+relu), output scatter per `mode`.
// 256 threads = 8 warps in 4(row) x 2(col); warp tile 32(M) x 64(N) = 2x4 m16n16k8 frags.
// All M % 128 == 0, N % 128 == 0, K % 16 == 0 in this problem.
#define GBM 128
#define GBN 128
#define GBK 16
#define ALD 20            // A smem ld (floats): 16 + 4 pad; 80B = 5*16 ok
#define BLDN 132          // B smem ld (non-trans, [k][n])
#define BLDT 20           // B smem ld (trans, [n][k])
#define ASZ (GBM * ALD)   // 2560 floats
#define BSZ 2560          // max(16*132=2112, 128*20=2560)
#define CLD 132

#define MODE_PLAIN 0
#define MODE_HEADSPLIT 1
#define MODE_MERGE 2

template <bool TRANSB>
__global__ void __launch_bounds__(256)
gemm_tf32(const float* __restrict__ A, const float* __restrict__ B,
          float* __restrict__ C, int M, int N, int K,
          long long aBatch, long long bBatch, long long cBatch,
          int mode, const float* __restrict__ bias, float alpha, int doRelu,
          int causalSkip) {
    __shared__ __align__(16) float smem[2 * ASZ + 2 * BSZ];   // 40960 B

    const int bz = blockIdx.z;
    const int bm0 = blockIdx.y * GBM;
    const int bn0 = blockIdx.x * GBN;
    if (causalSkip && bn0 > bm0 + GBM - 1) return;   // fully-causal-masked tile

    const float* Ab = A + (long long)bz * aBatch;
    const float* Bb = B + (long long)bz * bBatch;
    const int tid = threadIdx.x;
    const int warp = tid >> 5;
    const int wr = warp >> 1, wc = warp & 1;   // 4x2 warp grid

    wmma::fragment<wmma::accumulator, 16, 16, 8, float> acc[2][4];
#pragma unroll
    for (int i = 0; i < 2; i++)
#pragma unroll
        for (int j = 0; j < 4; j++) wmma::fill_fragment(acc[i][j], 0.0f);

    const int nt = K / GBK;

    // ---- async staging of one (A,B) stage into buffer `buf` ----
    auto stage = [&](int buf, int k0) {
        float* As = smem + buf * ASZ;
        float* Bs = smem + 2 * ASZ + buf * BSZ;
        // A tile: 128 x 16 floats = 512 float4; 2 per thread
#pragma unroll
        for (int s = 0; s < 2; s++) {
            int idx = tid + s * 256;
            int r = idx >> 2, c = (idx & 3) << 2;
            __pipeline_memcpy_async(As + r * ALD + c,
                                    Ab + (long long)(bm0 + r) * K + k0 + c, 16);
        }
        if (!TRANSB) {
            // B tile: 16 x 128 floats, stored [k][n]
#pragma unroll
            for (int s = 0; s < 2; s++) {
                int idx = tid + s * 256;
                int r = idx >> 5, c = (idx & 31) << 2;
                __pipeline_memcpy_async(Bs + r * BLDN + c,
                                        Bb + (long long)(k0 + r) * N + bn0 + c, 16);
            }
        } else {
            // B tile: 128(n) x 16(k), stored [n][k]
#pragma unroll
            for (int s = 0; s < 2; s++) {
                int idx = tid + s * 256;
                int r = idx >> 2, c = (idx & 3) << 2;
                __pipeline_memcpy_async(Bs + r * BLDT + c,
                                        Bb + (long long)(bn0 + r) * K + k0 + c, 16);
            }
        }
    };

    stage(0, 0);
    __pipeline_commit();

    for (int kt = 0; kt < nt; kt++) {
        if (kt + 1 < nt) {
            stage((kt + 1) & 1, (kt + 1) * GBK);
            __pipeline_commit();
            __pipeline_wait_prior(1);
        } else {
            __pipeline_wait_prior(0);
        }
        __syncthreads();

        const int buf = kt & 1;
        const float* As = smem + buf * ASZ;
        const float* Bs = smem + 2 * ASZ + buf * BSZ;

#pragma unroll
        for (int kk = 0; kk < GBK; kk += 8) {
            wmma::fragment<wmma::matrix_a, 16, 16, 8, wmma::precision::tf32, wmma::row_major> af[2];
#pragma unroll
            for (int i = 0; i < 2; i++) {
                wmma::load_matrix_sync(af[i], As + (wr * 32 + i * 16) * ALD + kk, ALD);
#pragma unroll
                for (int e = 0; e < af[i].num_elements; e++)
                    af[i].x[e] = wmma::__float_to_tf32(af[i].x[e]);   // RN: unbiased
            }
            if constexpr (!TRANSB) {
                wmma::fragment<wmma::matrix_b, 16, 16, 8, wmma::precision::tf32, wmma::row_major> bf[4];
#pragma unroll
                for (int j = 0; j < 4; j++) {
                    wmma::load_matrix_sync(bf[j], Bs + kk * BLDN + wc * 64 + j * 16, BLDN);
#pragma unroll
                    for (int e = 0; e < bf[j].num_elements; e++)
                        bf[j].x[e] = wmma::__float_to_tf32(bf[j].x[e]);
                }
#pragma unroll
                for (int i = 0; i < 2; i++)
#pragma unroll
                    for (int j = 0; j < 4; j++)
                        wmma::mma_sync(acc[i][j], af[i], bf[j], acc[i][j]);
            } else {
                wmma::fragment<wmma::matrix_b, 16, 16, 8, wmma::precision::tf32, wmma::col_major> bf[4];
#pragma unroll
                for (int j = 0; j < 4; j++) {
                    wmma::load_matrix_sync(bf[j], Bs + (wc * 64 + j * 16) * BLDT + kk, BLDT);
#pragma unroll
                    for (int e = 0; e < bf[j].num_elements; e++)
                        bf[j].x[e] = wmma::__float_to_tf32(bf[j].x[e]);
                }
#pragma unroll
                for (int i = 0; i < 2; i++)
#pragma unroll
                    for (int j = 0; j < 4; j++)
                        wmma::mma_sync(acc[i][j], af[i], bf[j], acc[i][j]);
            }
        }
        __syncthreads();
    }

    // ---- epilogue: two 64-row phases through shared (Cs = 64 x 132 floats) ----
    float* Cs = smem;
#pragma unroll
    for (int p = 0; p < 2; p++) {
        __syncthreads();
        if ((wr >> 1) == p) {
            int lr = wr & 1;
#pragma unroll
            for (int i = 0; i < 2; i++)
#pragma unroll
                for (int j = 0; j < 4; j++)
                    wmma::store_matrix_sync(Cs + (lr * 32 + i * 16) * CLD + wc * 64 + j * 16,
                                            acc[i][j], CLD, wmma::mem_row_major);
        }
        __syncthreads();
        for (int l = tid; l < 64 * GBN; l += 256) {
            int i = l >> 7, j = l & 127;
            int m = bm0 + p * 64 + i, n = bn0 + j;
            float v = Cs[i * CLD + j] * alpha;
            if (bias) v += bias[n];
            if (doRelu) v = fmaxf(v, 0.0f);
            long long oidx;
            if (mode == MODE_PLAIN) {
                oidx = (long long)bz * cBatch + (long long)m * N + n;
            } else if (mode == MODE_HEADSPLIT) {
                int b = m >> 9, lr2 = m & 511;
                int h = n >> 8, d = n & 255;
                oidx = (((long long)(b * HH + h) * LL + lr2) << 8) + d;
            } else {  // MODE_MERGE
                int b = bz >> 2, h = bz & 3;
                oidx = ((long long)(b * LL + m)) * HD + h * DD + n;
            }
            C[oidx] = v;
        }
    }
}

// ---------------- causal + pad softmax (in-place on S) ----------------
__global__ void __launch_bounds__(128)
softmax_kernel(float* __restrict__ S) {
    int row = blockIdx.x;           // bh*512 + q
    int q = row & (LL - 1);
    int bh = row >> 9;
    int b = bh >> 2;
    float* srow = S + (size_t)row * LL;
    int tid = threadIdx.x;
    __shared__ float red[128];

    if (g_pad[(b << 9) + q]) {
        const float u = 1.0f / (float)LL;   // softmax of constant row: exact
        for (int k = tid; k < LL; k += 128) srow[k] = u;
        return;
    }
    int valid = q + 1;
    float vals[4];
    float mx = -INFINITY;
#pragma unroll
    for (int t = 0; t < 4; t++) {
        int k = tid + t * 128;
        vals[t] = (k < valid) ? srow[k] : -INFINITY;
        mx = fmaxf(mx, vals[t]);
    }
    red[tid] = mx;
    __syncthreads();
    for (int s = 64; s > 0; s >>= 1) {
        if (tid < s) red[tid] = fmaxf(red[tid], red[tid + s]);
        __syncthreads();
    }
    mx = red[0];
    __syncthreads();
    float sum = 0.0f;
#pragma unroll
    for (int t = 0; t < 4; t++) {
        int k = tid + t * 128;
        vals[t] = (k < valid) ? expf(vals[t] - mx) : 0.0f;
        sum += vals[t];
    }
    red[tid] = sum;
    __syncthreads();
    for (int s = 64; s > 0; s >>= 1) {
        if (tid < s) red[tid] += red[tid + s];
        __syncthreads();
    }
    float inv = 1.0f / red[0];
#pragma unroll
    for (int t = 0; t < 4; t++) srow[tid + t * 128] = vals[t] * inv;
}

// ---------------- residual + layernorm ----------------
__global__ void __launch_bounds__(256)
ln_residual_kernel(const float* __restrict__ Ain, const float* __restrict__ Bin,
                   const float* __restrict__ gamma, const float* __restrict__ beta,
                   float* __restrict__ out) {
    int row = blockIdx.x;
    int tid = threadIdx.x;
    long long base = (long long)row * DD + tid;
    float x = Ain[base] + Bin[base];
    __shared__ float red[256];
    red[tid] = x;
    __syncthreads();
    for (int s = 128; s > 0; s >>= 1) {
        if (tid < s) red[tid] += red[tid + s];
        __syncthreads();
    }
    float mu = red[0] * (1.0f / DD);
    __syncthreads();
    float d = x - mu;
    red[tid] = d * d;
    __syncthreads();
    for (int s = 128; s > 0; s >>= 1) {
        if (tid < s) red[tid] += red[tid + s];
        __syncthreads();
    }
    float var = red[0] * (1.0f / DD);
    out[base] = d * rsqrtf(var + 1e-5f) * gamma[tid] + beta[tid];
}

// ---------------- host orchestration ----------------
extern "C" void kernel_launch(void* const* d_in, const int* in_sizes, int n_in,
                              void* d_out, int out_size) {
    (void)in_sizes; (void)n_in; (void)out_size;
    const float* Q    = (const float*)d_in[0];
    const float* K    = (const float*)d_in[1];
    const float* V    = (const float*)d_in[2];
    const void*  mask = d_in[3];
    const float* pe   = (const float*)d_in[4];
    const float* W_q  = (const float*)d_in[5];
    const float* W_k  = (const float*)d_in[6];
    const float* W_v  = (const float*)d_in[7];
    const float* W_o  = (const float*)d_in[8];
    const float* w1   = (const float*)d_in[9];
    const float* b1   = (const float*)d_in[10];
    const float* w2   = (const float*)d_in[11];
    const float* b2   = (const float*)d_in[12];
    const float* gamma = (const float*)d_in[13];
    const float* beta  = (const float*)d_in[14];
    float* out = (float*)d_out;

    void *pQp, *pKp, *pVp, *pQh, *pKh, *pVh, *pS, *pVm, *pT1, *pX, *pY, *pZ;
    cudaGetSymbolAddress(&pQp, g_Qp);
    cudaGetSymbolAddress(&pKp, g_Kp);
    cudaGetSymbolAddress(&pVp, g_Vp);
    cudaGetSymbolAddress(&pQh, g_Qh);
    cudaGetSymbolAddress(&pKh, g_Kh);
    cudaGetSymbolAddress(&pVh, g_Vh);
    cudaGetSymbolAddress(&pS, g_S);
    cudaGetSymbolAddress(&pVm, g_Vm);
    cudaGetSymbolAddress(&pT1, g_T1);
    cudaGetSymbolAddress(&pX, g_X);
    cudaGetSymbolAddress(&pY, g_Y);
    cudaGetSymbolAddress(&pZ, g_Z);

    // 1) mask decode
    detect_mask_kernel<<<1, 256>>>((const unsigned char*)mask);
    decode_mask_kernel<<<(NTOK + 255) / 256, 256>>>(mask);

    // 2) add positional encoding
    int etotal = NTOK * DD;
    int eblk = (etotal + 255) / 256;
    add_pe_kernel<<<eblk, 256>>>(Q, pe, (float*)pQp);
    add_pe_kernel<<<eblk, 256>>>(K, pe, (float*)pKp);
    add_pe_kernel<<<eblk, 256>>>(V, pe, (float*)pVp);

    // 3) QKV projections -> head-split layout (B*H, L, D)
    {
        dim3 grid(HD / GBN, NTOK / GBM, 1);
        gemm_tf32<false><<<grid, 256>>>((float*)pQp, W_q, (float*)pQh, NTOK, HD, DD,
                                        0, 0, 0, MODE_HEADSPLIT, nullptr, 1.0f, 0, 0);
        gemm_tf32<false><<<grid, 256>>>((float*)pKp, W_k, (float*)pKh, NTOK, HD, DD,
                                        0, 0, 0, MODE_HEADSPLIT, nullptr, 1.0f, 0, 0);
        gemm_tf32<false><<<grid, 256>>>((float*)pVp, W_v, (float*)pVh, NTOK, HD, DD,
                                        0, 0, 0, MODE_HEADSPLIT, nullptr, 1.0f, 0, 0);
    }

    // 4) scores = Qh @ Kh^T / scale  (batched over B*H, causal tiles skipped)
    {
        float alpha = (float)(1.0 / (16.0 + 1e-6));  // 1/(sqrt(256)+1e-6)
        dim3 grid(LL / GBN, LL / GBM, BH);
        gemm_tf32<true><<<grid, 256>>>((float*)pQh, (float*)pKh, (float*)pS, LL, LL, DD,
                                       (long long)LL * DD, (long long)LL * DD,
                                       (long long)LL * LL, MODE_PLAIN, nullptr, alpha, 0, 1);
    }

    // 5) masked softmax (in-place)
    softmax_kernel<<<BH * LL, 128>>>((float*)pS);

    // 6) Vatt = att @ Vh -> merged (B, L, H*D)
    {
        dim3 grid(DD / GBN, LL / GBM, BH);
        gemm_tf32<false><<<grid, 256>>>((float*)pS, (float*)pVh, (float*)pVm, LL, DD, LL,
                                        (long long)LL * LL, (long long)LL * DD,
                                        0, MODE_MERGE, nullptr, 1.0f, 0, 0);
    }

    // 7) output projection: T1 = Vm @ W_o
    {
        dim3 grid(DD / GBN, NTOK / GBM, 1);
        gemm_tf32<false><<<grid, 256>>>((float*)pVm, W_o, (float*)pT1, NTOK, DD, HD,
                                        0, 0, 0, MODE_PLAIN, nullptr, 1.0f, 0, 0);
    }

    // 8) X = LN(Qp + T1)
    ln_residual_kernel<<<NTOK, 256>>>((float*)pQp, (float*)pT1, gamma, beta, (float*)pX);

    // 9) FFN: Y = relu(X @ w1^T + b1); Z = Y @ w2^T + b2
    {
        dim3 grid(DD / GBN, NTOK / GBM, 1);
        gemm_tf32<true><<<grid, 256>>>((float*)pX, w1, (float*)pY, NTOK, DD, DD,
                                       0, 0, 0, MODE_PLAIN, b1, 1.0f, 1, 0);
        gemm_tf32<true><<<grid, 256>>>((float*)pY, w2, (float*)pZ, NTOK, DD, DD,
                                       0, 0, 0, MODE_PLAIN, b2, 1.0f, 0, 0);
    }

    // 10) out = LN(Z + X)
    ln_residual_kernel<<<NTOK, 256>>>((float*)pZ, (float*)pX, gamma, beta, out);
}

// round 6
// speedup vs baseline: 2.3273x; 2.3273x over previous
#include <cuda_runtime.h>
#include <cuda_fp16.h>
#include <cuda_pipeline.h>
#include <cstdint>

// Problem dims: B=32, L=512, D=256, H=4
#define BB 32
#define LL 512
#define DD 256
#define HH 4
#define NTOK (BB * LL)      // 16384
#define BH (BB * HH)        // 128
#define HD (HH * DD)        // 1024

// ---------------- device scratch (.bss, allocation-free) ----------------
__device__ float g_QpF[NTOK * DD];
__device__ __half g_QpH[NTOK * DD], g_KpH[NTOK * DD], g_VpH[NTOK * DD];
__device__ __half g_QhH[BH * LL * DD];     // (bh, l, d)
__device__ __half g_KhH[BH * LL * DD];     // (bh, l, d)
__device__ __half g_VhH[BH * LL * DD];     // (bh, l, d)
__device__ __half g_VtH[BH * DD * LL];     // (bh, d, l)
__device__ float g_S[(size_t)BH * LL * LL];
__device__ __half g_PH[(size_t)BH * LL * LL];
__device__ __half g_VmH[NTOK * HD];        // (b, l, h*d)
__device__ float g_T1[NTOK * DD];
__device__ float g_XF[NTOK * DD];
__device__ __half g_XH[NTOK * DD];
__device__ __half g_YH[NTOK * DD];
__device__ float g_ZF[NTOK * DD];
// weights as B operand layout: [n][k] (k contiguous)
__device__ __half g_Wq[HD * DD], g_Wk[HD * DD], g_Wv[HD * DD];
__device__ __half g_Wo[DD * HD];
__device__ __half g_w1[DD * DD], g_w2[DD * DD];
__device__ int g_pad[NTOK];
__device__ int g_byte_mode;

// ---------------- mask sniff + decode ----------------
__global__ void detect_mask_kernel(const unsigned char* m) {
    __shared__ int any;
    if (threadIdx.x == 0) any = 0;
    __syncthreads();
    int local = 0;
    for (int i = threadIdx.x; i < NTOK / 4; i += blockDim.x)
        if (m[4 * i + 1]) local = 1;
    if (local) atomicOr(&any, 1);
    __syncthreads();
    if (threadIdx.x == 0) g_byte_mode = any;
}
__global__ void decode_mask_kernel(const void* m) {
    int i = blockIdx.x * blockDim.x + threadIdx.x;
    if (i >= NTOK) return;
    g_pad[i] = g_byte_mode ? (((const unsigned char*)m)[i] != 0)
                           : (((const int*)m)[i] != 0);
}

// ---------------- PE add (+fp32 copy) + fp16 convert ----------------
__global__ void add_pe_h(const float* __restrict__ in, const float* __restrict__ pe,
                         float* __restrict__ outF, __half* __restrict__ outH) {
    int i = blockIdx.x * blockDim.x + threadIdx.x;
    if (i >= NTOK * DD) return;
    int d = i & (DD - 1);
    int l = (i >> 8) & (LL - 1);
    float x = in[i] + pe[l * DD + d];
    if (outF) outF[i] = x;
    outH[i] = __float2half_rn(x);
}

// ---------------- weight conversion ----------------
__global__ void wconv_direct(const float* __restrict__ src, __half* __restrict__ dst, int n) {
    int i = blockIdx.x * blockDim.x + threadIdx.x;
    if (i >= n) return;
    dst[i] = __float2half_rn(src[i]);
}
// src (R, C) row-major -> dst (C, R): dst[c*R + r] = src[r*C + c]
__global__ void wconv_trans(const float* __restrict__ src, __half* __restrict__ dst,
                            int R, int C) {
    int i = blockIdx.x * blockDim.x + threadIdx.x;
    if (i >= R * C) return;
    int c = i / R, r = i - c * R;
    dst[i] = __float2half_rn(src[r * C + c]);
}

// ---------------- V transpose: (bh, l, d) -> (bh, d, l) ----------------
__global__ void transpose_v(const __half* __restrict__ in, __half* __restrict__ out) {
    __shared__ __half t[32][33];
    int bh = blockIdx.z;
    int d0 = blockIdx.x * 32, l0 = blockIdx.y * 32;
    int tx = threadIdx.x, ty = threadIdx.y;   // 32 x 8
    const __half* ib = in + (size_t)bh * LL * DD;
#pragma unroll
    for (int s = 0; s < 32; s += 8)
        t[ty + s][tx] = ib[(size_t)(l0 + ty + s) * DD + d0 + tx];
    __syncthreads();
    __half* ob = out + (size_t)bh * DD * LL;
#pragma unroll
    for (int s = 0; s < 32; s += 8)
        ob[(size_t)(d0 + ty + s) * LL + l0 + tx] = t[tx][ty + s];
}

// ---------------- asm helpers ----------------
__device__ __forceinline__ uint32_t smem_u32(const void* p) {
    uint32_t a;
    asm("{ .reg .u64 t; cvta.to.shared.u64 t, %1; cvt.u32.u64 %0, t; }" : "=r"(a) : "l"(p));
    return a;
}
__device__ __forceinline__ void ldsm4(uint32_t& r0, uint32_t& r1, uint32_t& r2, uint32_t& r3,
                                      uint32_t addr) {
    asm volatile("ldmatrix.sync.aligned.m8n8.x4.shared.b16 {%0,%1,%2,%3}, [%4];"
                 : "=r"(r0), "=r"(r1), "=r"(r2), "=r"(r3) : "r"(addr));
}
__device__ __forceinline__ void mma16816(float* c, uint32_t a0, uint32_t a1, uint32_t a2,
                                         uint32_t a3, uint32_t b0, uint32_t b1) {
    asm volatile(
        "mma.sync.aligned.m16n8k16.row.col.f32.f16.f16.f32 "
        "{%0,%1,%2,%3}, {%4,%5,%6,%7}, {%8,%9}, {%0,%1,%2,%3};"
        : "+f"(c[0]), "+f"(c[1]), "+f"(c[2]), "+f"(c[3])
        : "r"(a0), "r"(a1), "r"(a2), "r"(a3), "r"(b0), "r"(b1));
}

// ---------------- fp16 mma.sync GEMM ----------------
// D[m][n] = alpha * sum_k A[m][k]*B[n][k] (+bias) (+relu), scatter per mode.
// Tile 128x128, K-chunk 64 (128B SW128 rows), 2-stage cp.async, 8 warps (4M x 2N),
// warp tile 32x64 = 2 m16 frags x 8 n8 frags of m16n8k16.
#define MT 128
#define NT 128
#define KC 64
#define STG 32768          // A 16K + B 16K per stage

#define MODE_PLAIN 0
#define MODE_HEADSPLIT 1
#define MODE_MERGE 2

__global__ void __launch_bounds__(256, 2)
gemm_h(const __half* __restrict__ A, const __half* __restrict__ B,
       float* __restrict__ outF, __half* __restrict__ outH, const float* __restrict__ bias,
       int K, long long aBatch, long long bBatch, long long cBatch, int ldc,
       int mode, float alpha, int doRelu, int causal) {
    extern __shared__ __align__(128) char smem[];

    const int bz = blockIdx.z;
    const int bm0 = blockIdx.y * MT;
    const int bn0 = blockIdx.x * NT;
    if (causal && bn0 > bm0) return;   // strictly-above-diagonal tile: fully masked

    const int tid = threadIdx.x;
    const int wid = tid >> 5;
    const int l = tid & 31;
    const int wr = wid & 3;            // M: 4 x 32
    const int wc = wid >> 2;           // N: 2 x 64

    const __half* gA = A + bz * aBatch + (long long)bm0 * K;
    const __half* gB = B + bz * bBatch + (long long)bn0 * K;
    const uint32_t sbase = smem_u32(smem);

    float c[2][8][4];
#pragma unroll
    for (int i = 0; i < 2; i++)
#pragma unroll
        for (int j = 0; j < 8; j++)
#pragma unroll
            for (int e = 0; e < 4; e++) c[i][j][e] = 0.0f;

    // per-thread ldmatrix row/parity (fixed across k-chunks)
    const int mrow = wr * 32 + ((l >> 3) & 1) * 8 + (l & 7);   // + i*16
    const int kpA = (l >> 4) & 1;
    const int nrow = wc * 64 + ((l >> 4) & 1) * 8 + (l & 7);   // + g*16
    const int kpB = (l >> 3) & 1;

    auto stage_fn = [&](int buf, int k0) {
        char* sA = smem + buf * STG;
        char* sB = sA + 16384;
#pragma unroll
        for (int it = 0; it < 4; it++) {     // A: 128 rows x 8 chunks(16B)
            int idx = tid + it * 256;
            int r = idx >> 3, ch = idx & 7;
            __pipeline_memcpy_async(sA + r * 128 + ((ch ^ (r & 7)) << 4),
                                    gA + (long long)r * K + k0 + ch * 8, 16);
        }
#pragma unroll
        for (int it = 0; it < 4; it++) {     // B: 128 rows x 8 chunks
            int idx = tid + it * 256;
            int r = idx >> 3, ch = idx & 7;
            __pipeline_memcpy_async(sB + r * 128 + ((ch ^ (r & 7)) << 4),
                                    gB + (long long)r * K + k0 + ch * 8, 16);
        }
    };

    const int nt = K / KC;
    stage_fn(0, 0);
    __pipeline_commit();

    for (int cc = 0; cc < nt; cc++) {
        const int buf = cc & 1;
        if (cc + 1 < nt) {
            stage_fn(buf ^ 1, (cc + 1) * KC);
            __pipeline_commit();
            __pipeline_wait_prior(1);
        } else {
            __pipeline_wait_prior(0);
        }
        __syncthreads();

        const uint32_t sA = sbase + buf * STG;
        const uint32_t sB = sA + 16384;
#pragma unroll
        for (int ks = 0; ks < 4; ks++) {
            uint32_t a[2][4];
#pragma unroll
            for (int i = 0; i < 2; i++) {
                int row = mrow + i * 16;
                ldsm4(a[i][0], a[i][1], a[i][2], a[i][3],
                      sA + row * 128 + (((2 * ks + kpA) ^ (row & 7)) << 4));
            }
            uint32_t b[4][4];
#pragma unroll
            for (int g = 0; g < 4; g++) {
                int row = nrow + g * 16;
                ldsm4(b[g][0], b[g][1], b[g][2], b[g][3],
                      sB + row * 128 + (((2 * ks + kpB) ^ (row & 7)) << 4));
            }
#pragma unroll
            for (int i = 0; i < 2; i++)
#pragma unroll
                for (int j = 0; j < 8; j++) {
                    int g = j >> 1, h2 = (j & 1) << 1;
                    mma16816(c[i][j], a[i][0], a[i][1], a[i][2], a[i][3],
                             b[g][h2], b[g][h2 + 1]);
                }
        }
        __syncthreads();
    }

    // ---- epilogue: direct stores from fragments ----
    const int mb = bm0 + wr * 32 + (l >> 2);
    const int nb = bn0 + wc * 64 + (l & 3) * 2;
    auto emit2 = [&](int m, int n, float v0, float v1) {
        v0 *= alpha; v1 *= alpha;
        if (bias) { v0 += bias[n]; v1 += bias[n + 1]; }
        if (doRelu) { v0 = fmaxf(v0, 0.0f); v1 = fmaxf(v1, 0.0f); }
        size_t oidx;
        if (mode == MODE_PLAIN) {
            oidx = (size_t)bz * cBatch + (size_t)m * ldc + n;
        } else if (mode == MODE_HEADSPLIT) {
            int b_ = m >> 9, l_ = m & 511, h_ = n >> 8, d_ = n & 255;
            oidx = ((size_t)((b_ * HH + h_) * LL + l_)) * DD + d_;
        } else {  // MODE_MERGE: bz = bh
            int b_ = bz >> 2, h_ = bz & 3;
            oidx = ((size_t)(b_ * LL + m)) * HD + h_ * DD + n;
        }
        if (outF) *(float2*)(outF + oidx) = make_float2(v0, v1);
        else *(__half2*)(outH + oidx) = __floats2half2_rn(v0, v1);
    };
#pragma unroll
    for (int i = 0; i < 2; i++) {
        int m = mb + i * 16;
#pragma unroll
        for (int j = 0; j < 8; j++) {
            int n = nb + j * 8;
            emit2(m, n, c[i][j][0], c[i][j][1]);
            emit2(m + 8, n, c[i][j][2], c[i][j][3]);
        }
    }
}

// ---------------- causal + pad softmax: S (fp32) -> P (fp16) ----------------
__global__ void __launch_bounds__(128)
softmax_kernel(const float* __restrict__ S, __half* __restrict__ PH) {
    int row = blockIdx.x;            // bh*512 + q
    int q = row & (LL - 1);
    int bh = row >> 9;
    int b = bh >> 2;
    const float* srow = S + (size_t)row * LL;
    __half* ph = PH + (size_t)row * LL;
    int tid = threadIdx.x;
    __shared__ float red[128];

    if (g_pad[(b << 9) + q]) {
        const __half u = __float2half_rn(1.0f / (float)LL);   // exact (2^-9)
        for (int k = tid; k < LL; k += 128) ph[k] = u;
        return;
    }
    int valid = q + 1;
    float vals[4];
    float mx = -INFINITY;
#pragma unroll
    for (int t = 0; t < 4; t++) {
        int k = tid + t * 128;
        vals[t] = (k < valid) ? srow[k] : -INFINITY;
        mx = fmaxf(mx, vals[t]);
    }
    red[tid] = mx;
    __syncthreads();
    for (int s = 64; s > 0; s >>= 1) {
        if (tid < s) red[tid] = fmaxf(red[tid], red[tid + s]);
        __syncthreads();
    }
    mx = red[0];
    __syncthreads();
    float sum = 0.0f;
#pragma unroll
    for (int t = 0; t < 4; t++) {
        int k = tid + t * 128;
        vals[t] = (k < valid) ? expf(vals[t] - mx) : 0.0f;
        sum += vals[t];
    }
    red[tid] = sum;
    __syncthreads();
    for (int s = 64; s > 0; s >>= 1) {
        if (tid < s) red[tid] += red[tid + s];
        __syncthreads();
    }
    float inv = 1.0f / red[0];
#pragma unroll
    for (int t = 0; t < 4; t++) {
        int k = tid + t * 128;
        ph[k] = __float2half_rn(vals[t] * inv);
    }
}

// ---------------- residual + layernorm (+optional fp16 out) ----------------
__global__ void __launch_bounds__(256)
ln_residual_kernel(const float* __restrict__ Ain, const float* __restrict__ Bin,
                   const float* __restrict__ gamma, const float* __restrict__ beta,
                   float* __restrict__ outF, __half* __restrict__ outH) {
    int row = blockIdx.x;
    int tid = threadIdx.x;
    size_t base = (size_t)row * DD + tid;
    float x = Ain[base] + Bin[base];
    __shared__ float red[256];
    red[tid] = x;
    __syncthreads();
    for (int s = 128; s > 0; s >>= 1) {
        if (tid < s) red[tid] += red[tid + s];
        __syncthreads();
    }
    float mu = red[0] * (1.0f / DD);
    __syncthreads();
    float d = x - mu;
    red[tid] = d * d;
    __syncthreads();
    for (int s = 128; s > 0; s >>= 1) {
        if (tid < s) red[tid] += red[tid + s];
        __syncthreads();
    }
    float var = red[0] * (1.0f / DD);
    float y = d * rsqrtf(var + 1e-5f) * gamma[tid] + beta[tid];
    if (outF) outF[base] = y;
    if (outH) outH[base] = __float2half_rn(y);
}

// ---------------- host orchestration ----------------
#define SYM(p, s) void* p; cudaGetSymbolAddress(&p, s)

extern "C" void kernel_launch(void* const* d_in, const int* in_sizes, int n_in,
                              void* d_out, int out_size) {
    (void)in_sizes; (void)n_in; (void)out_size;
    const float* Q    = (const float*)d_in[0];
    const float* K    = (const float*)d_in[1];
    const float* V    = (const float*)d_in[2];
    const void*  mask = d_in[3];
    const float* pe   = (const float*)d_in[4];
    const float* W_q  = (const float*)d_in[5];
    const float* W_k  = (const float*)d_in[6];
    const float* W_v  = (const float*)d_in[7];
    const float* W_o  = (const float*)d_in[8];
    const float* w1   = (const float*)d_in[9];
    const float* b1   = (const float*)d_in[10];
    const float* w2   = (const float*)d_in[11];
    const float* b2   = (const float*)d_in[12];
    const float* gamma = (const float*)d_in[13];
    const float* beta  = (const float*)d_in[14];
    float* out = (float*)d_out;

    SYM(pQpF, g_QpF);
    SYM(pQpH, g_QpH); SYM(pKpH, g_KpH); SYM(pVpH, g_VpH);
    SYM(pQhH, g_QhH); SYM(pKhH, g_KhH); SYM(pVhH, g_VhH); SYM(pVtH, g_VtH);
    SYM(pS, g_S); SYM(pPH, g_PH); SYM(pVmH, g_VmH);
    SYM(pT1, g_T1); SYM(pXF, g_XF); SYM(pXH, g_XH); SYM(pYH, g_YH); SYM(pZF, g_ZF);
    SYM(pWq, g_Wq); SYM(pWk, g_Wk); SYM(pWv, g_Wv); SYM(pWo, g_Wo);
    SYM(pw1, g_w1); SYM(pw2, g_w2);

    cudaFuncSetAttribute(gemm_h, cudaFuncAttributeMaxDynamicSharedMemorySize, 2 * STG);

    typedef __half hf;

    // 1) mask
    detect_mask_kernel<<<1, 256>>>((const unsigned char*)mask);
    decode_mask_kernel<<<(NTOK + 255) / 256, 256>>>(mask);

    // 2) PE add + fp16 convert
    int etot = NTOK * DD, eblk = (etot + 255) / 256;
    add_pe_h<<<eblk, 256>>>(Q, pe, (float*)pQpF, (hf*)pQpH);
    add_pe_h<<<eblk, 256>>>(K, pe, nullptr, (hf*)pKpH);
    add_pe_h<<<eblk, 256>>>(V, pe, nullptr, (hf*)pVpH);

    // 3) weights to fp16 [n][k]
    wconv_trans<<<(DD * HD + 255) / 256, 256>>>(W_q, (hf*)pWq, DD, HD);
    wconv_trans<<<(DD * HD + 255) / 256, 256>>>(W_k, (hf*)pWk, DD, HD);
    wconv_trans<<<(DD * HD + 255) / 256, 256>>>(W_v, (hf*)pWv, DD, HD);
    wconv_trans<<<(DD * HD + 255) / 256, 256>>>(W_o, (hf*)pWo, HD, DD);
    wconv_direct<<<(DD * DD + 255) / 256, 256>>>(w1, (hf*)pw1, DD * DD);
    wconv_direct<<<(DD * DD + 255) / 256, 256>>>(w2, (hf*)pw2, DD * DD);

    // 4) QKV projections (M=16384, N=1024, K=256) -> head-split (bh, l, d)
    {
        dim3 g(HD / NT, NTOK / MT, 1);
        gemm_h<<<g, 256, 2 * STG>>>((hf*)pQpH, (hf*)pWq, nullptr, (hf*)pQhH, nullptr,
                                    DD, 0, 0, 0, 0, MODE_HEADSPLIT, 1.0f, 0, 0);
        gemm_h<<<g, 256, 2 * STG>>>((hf*)pKpH, (hf*)pWk, nullptr, (hf*)pKhH, nullptr,
                                    DD, 0, 0, 0, 0, MODE_HEADSPLIT, 1.0f, 0, 0);
        gemm_h<<<g, 256, 2 * STG>>>((hf*)pVpH, (hf*)pWv, nullptr, (hf*)pVhH, nullptr,
                                    DD, 0, 0, 0, 0, MODE_HEADSPLIT, 1.0f, 0, 0);
    }

    // 5) V transpose (bh, l, d) -> (bh, d, l)
    {
        dim3 g(DD / 32, LL / 32, BH);
        transpose_v<<<g, dim3(32, 8)>>>((hf*)pVhH, (hf*)pVtH);
    }

    // 6) scores = Qh @ Kh^T / scale  (per bh, M=N=512, K=256; causal skip)
    {
        float alpha = (float)(1.0 / (16.0 + 1e-6));
        dim3 g(LL / NT, LL / MT, BH);
        gemm_h<<<g, 256, 2 * STG>>>((hf*)pQhH, (hf*)pKhH, (float*)pS, nullptr, nullptr,
                                    DD, (long long)LL * DD, (long long)LL * DD,
                                    (long long)LL * LL, LL, MODE_PLAIN, alpha, 0, 1);
    }

    // 7) masked softmax -> P fp16
    softmax_kernel<<<BH * LL, 128>>>((float*)pS, (hf*)pPH);

    // 8) Vatt = P @ Vt^T -> merged (b, l, h*d)   (M=512, N=256, K=512 per bh)
    {
        dim3 g(DD / NT, LL / MT, BH);
        gemm_h<<<g, 256, 2 * STG>>>((hf*)pPH, (hf*)pVtH, nullptr, (hf*)pVmH, nullptr,
                                    LL, (long long)LL * LL, (long long)DD * LL,
                                    0, 0, MODE_MERGE, 1.0f, 0, 0);
    }

    // 9) output projection: T1 = Vm @ W_o  (M=16384, N=256, K=1024)
    {
        dim3 g(DD / NT, NTOK / MT, 1);
        gemm_h<<<g, 256, 2 * STG>>>((hf*)pVmH, (hf*)pWo, (float*)pT1, nullptr, nullptr,
                                    HD, 0, 0, 0, DD, MODE_PLAIN, 1.0f, 0, 0);
    }

    // 10) X = LN(Qp + T1)
    ln_residual_kernel<<<NTOK, 256>>>((float*)pQpF, (float*)pT1, gamma, beta,
                                      (float*)pXF, (hf*)pXH);

    // 11) FFN: Y = relu(X @ w1^T + b1); Z = Y @ w2^T + b2
    {
        dim3 g(DD / NT, NTOK / MT, 1);
        gemm_h<<<g, 256, 2 * STG>>>((hf*)pXH, (hf*)pw1, nullptr, (hf*)pYH, b1,
                                    DD, 0, 0, 0, DD, MODE_PLAIN, 1.0f, 1, 0);
        gemm_h<<<g, 256, 2 * STG>>>((hf*)pYH, (hf*)pw2, (float*)pZF, nullptr, b2,
                                    DD, 0, 0, 0, DD, MODE_PLAIN, 1.0f, 0, 0);
    }

    // 12) out = LN(Z + X)
    ln_residual_kernel<<<NTOK, 256>>>((float*)pZF, (float*)pXF, gamma, beta, out, nullptr);
}

// round 7
// speedup vs baseline: 3.6137x; 1.5527x over previous
#include <cuda_runtime.h>
#include <cuda_fp16.h>
#include <cuda_pipeline.h>
#include <cstdint>

// Problem dims: B=32, L=512, D=256, H=4
#define BB 32
#define LL 512
#define DD 256
#define HH 4
#define NTOK (BB * LL)      // 16384
#define BH (BB * HH)        // 128
#define HD (HH * DD)        // 1024

// ---------------- device scratch (.bss, allocation-free) ----------------
__device__ __align__(256) float g_QpF[NTOK * DD];
__device__ __align__(256) __half g_QpH[NTOK * DD], g_KpH[NTOK * DD], g_VpH[NTOK * DD];
__device__ __align__(256) __half g_QhH[BH * LL * DD];     // (bh, l, d)
__device__ __align__(256) __half g_KhH[BH * LL * DD];     // (bh, l, d)
__device__ __align__(256) __half g_VhH[BH * LL * DD];     // (bh, l, d)
__device__ __align__(256) __half g_VtH[BH * DD * LL];     // (bh, d, l)
__device__ __align__(256) float g_Vsum[BH * DD];
__device__ __align__(256) __half g_VmH[NTOK * HD];        // (b, l, h*d)
__device__ __align__(256) float g_T1[NTOK * DD];
__device__ __align__(256) float g_XF[NTOK * DD];
__device__ __align__(256) __half g_XH[NTOK * DD];
__device__ __align__(256) __half g_YH[NTOK * DD];
__device__ __align__(256) float g_ZF[NTOK * DD];
// weights as B operand layout: [n][k] (k contiguous)
__device__ __align__(256) __half g_Wq[HD * DD], g_Wk[HD * DD], g_Wv[HD * DD];
__device__ __align__(256) __half g_Wo[DD * HD];
__device__ __align__(256) __half g_w1[DD * DD], g_w2[DD * DD];
__device__ int g_pad[NTOK];
__device__ int g_byte_mode;

// ---------------- mask sniff + decode ----------------
__global__ void detect_mask_kernel(const unsigned char* m) {
    __shared__ int any;
    if (threadIdx.x == 0) any = 0;
    __syncthreads();
    int local = 0;
    for (int i = threadIdx.x; i < NTOK / 4; i += blockDim.x)
        if (m[4 * i + 1]) local = 1;
    if (local) atomicOr(&any, 1);
    __syncthreads();
    if (threadIdx.x == 0) g_byte_mode = any;
}
__global__ void decode_mask_kernel(const void* m) {
    int i = blockIdx.x * blockDim.x + threadIdx.x;
    if (i >= NTOK) return;
    g_pad[i] = g_byte_mode ? (((const unsigned char*)m)[i] != 0)
                           : (((const int*)m)[i] != 0);
}

// ---------------- PE add, vectorized (float4) ----------------
__global__ void add_pe_h4(const float4* __restrict__ in, const float* __restrict__ pe,
                          float4* __restrict__ outF, __half2* __restrict__ outH) {
    int i = blockIdx.x * blockDim.x + threadIdx.x;   // over NTOK*DD/4
    if (i >= NTOK * DD / 4) return;
    int d4 = i & 63;              // 64 float4 per 256-d row
    int l = (i >> 6) & (LL - 1);
    float4 v = in[i];
    float4 p = *(const float4*)(pe + l * DD + d4 * 4);
    v.x += p.x; v.y += p.y; v.z += p.z; v.w += p.w;
    if (outF) outF[i] = v;
    outH[2 * i] = __floats2half2_rn(v.x, v.y);
    outH[2 * i + 1] = __floats2half2_rn(v.z, v.w);
}

// ---------------- weight conversion ----------------
__global__ void wconv_direct(const float* __restrict__ src, __half* __restrict__ dst, int n) {
    int i = blockIdx.x * blockDim.x + threadIdx.x;
    if (i >= n) return;
    dst[i] = __float2half_rn(src[i]);
}
__global__ void wconv_trans(const float* __restrict__ src, __half* __restrict__ dst,
                            int R, int C) {
    int i = blockIdx.x * blockDim.x + threadIdx.x;
    if (i >= R * C) return;
    int c = i / R, r = i - c * R;
    dst[i] = __float2half_rn(src[r * C + c]);
}

// ---------------- V transpose: (bh, l, d) -> (bh, d, l) ----------------
__global__ void transpose_v(const __half* __restrict__ in, __half* __restrict__ out) {
    __shared__ __half t[32][33];
    int bh = blockIdx.z;
    int d0 = blockIdx.x * 32, l0 = blockIdx.y * 32;
    int tx = threadIdx.x, ty = threadIdx.y;   // 32 x 8
    const __half* ib = in + (size_t)bh * LL * DD;
#pragma unroll
    for (int s = 0; s < 32; s += 8)
        t[ty + s][tx] = ib[(size_t)(l0 + ty + s) * DD + d0 + tx];
    __syncthreads();
    __half* ob = out + (size_t)bh * DD * LL;
#pragma unroll
    for (int s = 0; s < 32; s += 8)
        ob[(size_t)(d0 + ty + s) * LL + l0 + tx] = t[tx][ty + s];
}

// ---------------- Vsum[bh][d] = sum_l Vh[bh][l][d] ----------------
__global__ void vsum_kernel(const __half* __restrict__ Vh, float* __restrict__ Vs) {
    int bh = blockIdx.x;
    int d = threadIdx.x;   // 256
    const __half* p = Vh + (size_t)bh * LL * DD + d;
    float s = 0.0f;
#pragma unroll 8
    for (int l = 0; l < LL; l++) s += __half2float(p[(size_t)l * DD]);
    Vs[bh * DD + d] = s;
}

// ---------------- asm helpers ----------------
__device__ __forceinline__ uint32_t smem_u32(const void* p) {
    uint32_t a;
    asm("{ .reg .u64 t; cvta.to.shared.u64 t, %1; cvt.u32.u64 %0, t; }" : "=r"(a) : "l"(p));
    return a;
}
__device__ __forceinline__ void ldsm4(uint32_t& r0, uint32_t& r1, uint32_t& r2, uint32_t& r3,
                                      uint32_t addr) {
    asm volatile("ldmatrix.sync.aligned.m8n8.x4.shared.b16 {%0,%1,%2,%3}, [%4];"
                 : "=r"(r0), "=r"(r1), "=r"(r2), "=r"(r3) : "r"(addr));
}
__device__ __forceinline__ void mma16816(float* c, uint32_t a0, uint32_t a1, uint32_t a2,
                                         uint32_t a3, uint32_t b0, uint32_t b1) {
    asm volatile(
        "mma.sync.aligned.m16n8k16.row.col.f32.f16.f16.f32 "
        "{%0,%1,%2,%3}, {%4,%5,%6,%7}, {%8,%9}, {%0,%1,%2,%3};"
        : "+f"(c[0]), "+f"(c[1]), "+f"(c[2]), "+f"(c[3])
        : "r"(a0), "r"(a1), "r"(a2), "r"(a3), "r"(b0), "r"(b1));
}
__device__ __forceinline__ uint32_t packh2(float a, float b) {
    __half2 h = __floats2half2_rn(a, b);
    return *(uint32_t*)&h;
}

// ---------------- fp16 mma.sync GEMM (projections / out-proj / FFN) ----------------
#define MT 128
#define NT 128
#define KC 64
#define STG 32768

#define MODE_PLAIN 0
#define MODE_HEADSPLIT 1

__global__ void __launch_bounds__(256, 2)
gemm_h(const __half* __restrict__ A, const __half* __restrict__ B,
       float* __restrict__ outF, __half* __restrict__ outH, const float* __restrict__ bias,
       int K, long long aBatch, long long bBatch, long long cBatch, int ldc,
       int mode, float alpha, int doRelu) {
    extern __shared__ __align__(128) char smem[];

    const int bz = blockIdx.z;
    const int bm0 = blockIdx.y * MT;
    const int bn0 = blockIdx.x * NT;

    const int tid = threadIdx.x;
    const int wid = tid >> 5;
    const int l = tid & 31;
    const int wr = wid & 3;
    const int wc = wid >> 2;

    const __half* gA = A + bz * aBatch + (long long)bm0 * K;
    const __half* gB = B + bz * bBatch + (long long)bn0 * K;
    const uint32_t sbase = smem_u32(smem);

    float c[2][8][4];
#pragma unroll
    for (int i = 0; i < 2; i++)
#pragma unroll
        for (int j = 0; j < 8; j++)
#pragma unroll
            for (int e = 0; e < 4; e++) c[i][j][e] = 0.0f;

    const int mrow = wr * 32 + ((l >> 3) & 1) * 8 + (l & 7);
    const int kpA = (l >> 4) & 1;
    const int nrow = wc * 64 + ((l >> 4) & 1) * 8 + (l & 7);
    const int kpB = (l >> 3) & 1;

    auto stage_fn = [&](int buf, int k0) {
        char* sA = smem + buf * STG;
        char* sB = sA + 16384;
#pragma unroll
        for (int it = 0; it < 4; it++) {
            int idx = tid + it * 256;
            int r = idx >> 3, ch = idx & 7;
            __pipeline_memcpy_async(sA + r * 128 + ((ch ^ (r & 7)) << 4),
                                    gA + (long long)r * K + k0 + ch * 8, 16);
        }
#pragma unroll
        for (int it = 0; it < 4; it++) {
            int idx = tid + it * 256;
            int r = idx >> 3, ch = idx & 7;
            __pipeline_memcpy_async(sB + r * 128 + ((ch ^ (r & 7)) << 4),
                                    gB + (long long)r * K + k0 + ch * 8, 16);
        }
    };

    const int nt = K / KC;
    stage_fn(0, 0);
    __pipeline_commit();

    for (int cc = 0; cc < nt; cc++) {
        const int buf = cc & 1;
        if (cc + 1 < nt) {
            stage_fn(buf ^ 1, (cc + 1) * KC);
            __pipeline_commit();
            __pipeline_wait_prior(1);
        } else {
            __pipeline_wait_prior(0);
        }
        __syncthreads();

        const uint32_t sA = sbase + buf * STG;
        const uint32_t sB = sA + 16384;
#pragma unroll
        for (int ks = 0; ks < 4; ks++) {
            uint32_t a[2][4];
#pragma unroll
            for (int i = 0; i < 2; i++) {
                int row = mrow + i * 16;
                ldsm4(a[i][0], a[i][1], a[i][2], a[i][3],
                      sA + row * 128 + (((2 * ks + kpA) ^ (row & 7)) << 4));
            }
            uint32_t b[4][4];
#pragma unroll
            for (int g = 0; g < 4; g++) {
                int row = nrow + g * 16;
                ldsm4(b[g][0], b[g][1], b[g][2], b[g][3],
                      sB + row * 128 + (((2 * ks + kpB) ^ (row & 7)) << 4));
            }
#pragma unroll
            for (int i = 0; i < 2; i++)
#pragma unroll
                for (int j = 0; j < 8; j++) {
                    int g = j >> 1, h2 = (j & 1) << 1;
                    mma16816(c[i][j], a[i][0], a[i][1], a[i][2], a[i][3],
                             b[g][h2], b[g][h2 + 1]);
                }
        }
        __syncthreads();
    }

    const int mb = bm0 + wr * 32 + (l >> 2);
    const int nb = bn0 + wc * 64 + (l & 3) * 2;
    auto emit2 = [&](int m, int n, float v0, float v1) {
        v0 *= alpha; v1 *= alpha;
        if (bias) { v0 += bias[n]; v1 += bias[n + 1]; }
        if (doRelu) { v0 = fmaxf(v0, 0.0f); v1 = fmaxf(v1, 0.0f); }
        size_t oidx;
        if (mode == MODE_PLAIN) {
            oidx = (size_t)bz * cBatch + (size_t)m * ldc + n;
        } else {  // MODE_HEADSPLIT
            int b_ = m >> 9, l_ = m & 511, h_ = n >> 8, d_ = n & 255;
            oidx = ((size_t)((b_ * HH + h_) * LL + l_)) * DD + d_;
        }
        if (outF) *(float2*)(outF + oidx) = make_float2(v0, v1);
        else *(__half2*)(outH + oidx) = __floats2half2_rn(v0, v1);
    };
#pragma unroll
    for (int i = 0; i < 2; i++) {
        int m = mb + i * 16;
#pragma unroll
        for (int j = 0; j < 8; j++) {
            int n = nb + j * 8;
            emit2(m, n, c[i][j][0], c[i][j][1]);
            emit2(m + 8, n, c[i][j][2], c[i][j][3]);
        }
    }
}

// ---------------- fused flash attention ----------------
// Per block: (bh, 128-q tile). Loop key tiles of 128 (causal: kt <= qt).
// S in regs (warp = 16 q rows x 128 keys), online softmax, P reused as A-fragments,
// O (128 x 256) accumulated fp32 in regs. Pad rows overwritten with Vsum/512.
// Smem: Q 64K (persistent) + K 64K + Vt 64K = 192K, chunk-pipelined cp.async.
#define FSM_K 65536
#define FSM_V 131072
#define FSM_TOT 196608

__global__ void __launch_bounds__(256, 1)
flash_attn(const __half* __restrict__ Qh, const __half* __restrict__ Kh,
           const __half* __restrict__ Vt, const float* __restrict__ Vsum,
           __half* __restrict__ Om) {
    extern __shared__ __align__(128) char smem[];
    const int qt = blockIdx.x;
    const int bh = blockIdx.y;
    const int tid = threadIdx.x;
    const int w = tid >> 5;
    const int l = tid & 31;

    const __half* gQ = Qh + ((size_t)bh * LL + qt * 128) * DD;
    const __half* gK = Kh + (size_t)bh * LL * DD;
    const __half* gV = Vt + (size_t)bh * DD * LL;
    char* smQ = smem;
    char* smK = smem + FSM_K;
    char* smV = smem + FSM_V;
    const uint32_t sQ = smem_u32(smem);
    const uint32_t sK = sQ + FSM_K;
    const uint32_t sV = sQ + FSM_V;

    // stage Q (4 d-chunks of 128 rows x 64 halves)
#pragma unroll
    for (int cq = 0; cq < 4; cq++)
#pragma unroll
        for (int it = 0; it < 4; it++) {
            int idx = tid + it * 256;
            int r = idx >> 3, ch = idx & 7;
            __pipeline_memcpy_async(smQ + cq * 16384 + r * 128 + ((ch ^ (r & 7)) << 4),
                                    gQ + (size_t)r * DD + cq * 64 + ch * 8, 16);
        }
    __pipeline_commit();

    float o[32][4];
#pragma unroll
    for (int j = 0; j < 32; j++)
#pragma unroll
        for (int e = 0; e < 4; e++) o[j][e] = 0.0f;
    float mrun0 = -INFINITY, mrun1 = -INFINITY;
    float lrun0 = 0.0f, lrun1 = 0.0f;

    const int r0l = w * 16 + (l >> 2);
    const int r1l = r0l + 8;
    const int arow = w * 16 + ((l >> 3) & 1) * 8 + (l & 7);
    const int kpA = (l >> 4) & 1;
    const int brow = ((l >> 4) & 1) * 8 + (l & 7);
    const int kpB = (l >> 3) & 1;
    const float alpha = (float)(1.0 / (16.0 + 1e-6));

    for (int kt = 0; kt <= qt; kt++) {
        // stage K (4 d-chunks) + Vt (2 key-chunks), 6 commit groups
#pragma unroll
        for (int ck = 0; ck < 4; ck++) {
#pragma unroll
            for (int it = 0; it < 4; it++) {
                int idx = tid + it * 256;
                int r = idx >> 3, ch = idx & 7;
                __pipeline_memcpy_async(smK + ck * 16384 + r * 128 + ((ch ^ (r & 7)) << 4),
                                        gK + (size_t)(kt * 128 + r) * DD + ck * 64 + ch * 8, 16);
            }
            __pipeline_commit();
        }
#pragma unroll
        for (int cv = 0; cv < 2; cv++) {
#pragma unroll
            for (int it = 0; it < 8; it++) {
                int idx = tid + it * 256;
                int r = idx >> 3, ch = idx & 7;
                __pipeline_memcpy_async(smV + cv * 32768 + r * 128 + ((ch ^ (r & 7)) << 4),
                                        gV + (size_t)r * LL + kt * 128 + cv * 64 + ch * 8, 16);
            }
            __pipeline_commit();
        }

        // ---- S = Q K^T (warp: 16 q x 128 k, fp32 acc) ----
        float c[16][4];
#pragma unroll
        for (int j = 0; j < 16; j++)
#pragma unroll
            for (int e = 0; e < 4; e++) c[j][e] = 0.0f;

#pragma unroll
        for (int ck = 0; ck < 4; ck++) {
            __pipeline_wait_prior(5 - ck);
            __syncthreads();
#pragma unroll
            for (int ks = 0; ks < 4; ks++) {
                uint32_t a0, a1, a2, a3;
                ldsm4(a0, a1, a2, a3,
                      sQ + ck * 16384 + arow * 128 + (((2 * ks + kpA) ^ (arow & 7)) << 4));
#pragma unroll
                for (int g = 0; g < 8; g++) {
                    int nr = g * 16 + brow;
                    uint32_t b0, b1, b2, b3;
                    ldsm4(b0, b1, b2, b3,
                          sK + ck * 16384 + nr * 128 + (((2 * ks + kpB) ^ (nr & 7)) << 4));
                    mma16816(c[2 * g], a0, a1, a2, a3, b0, b1);
                    mma16816(c[2 * g + 1], a0, a1, a2, a3, b2, b3);
                }
            }
        }

        // ---- scale + causal mask (diagonal tile only) ----
        if (kt == qt) {
#pragma unroll
            for (int j = 0; j < 16; j++) {
                int nb = j * 8 + (l & 3) * 2;
                c[j][0] = (nb     <= r0l) ? c[j][0] * alpha : -INFINITY;
                c[j][1] = (nb + 1 <= r0l) ? c[j][1] * alpha : -INFINITY;
                c[j][2] = (nb     <= r1l) ? c[j][2] * alpha : -INFINITY;
                c[j][3] = (nb + 1 <= r1l) ? c[j][3] * alpha : -INFINITY;
            }
        } else {
#pragma unroll
            for (int j = 0; j < 16; j++)
#pragma unroll
                for (int e = 0; e < 4; e++) c[j][e] *= alpha;
        }

        // ---- online softmax update ----
        float mn0 = mrun0, mn1 = mrun1;
#pragma unroll
        for (int j = 0; j < 16; j++) {
            mn0 = fmaxf(mn0, fmaxf(c[j][0], c[j][1]));
            mn1 = fmaxf(mn1, fmaxf(c[j][2], c[j][3]));
        }
        mn0 = fmaxf(mn0, __shfl_xor_sync(0xFFFFFFFF, mn0, 1));
        mn0 = fmaxf(mn0, __shfl_xor_sync(0xFFFFFFFF, mn0, 2));
        mn1 = fmaxf(mn1, __shfl_xor_sync(0xFFFFFFFF, mn1, 1));
        mn1 = fmaxf(mn1, __shfl_xor_sync(0xFFFFFFFF, mn1, 2));
        float corr0 = expf(mrun0 - mn0);
        float corr1 = expf(mrun1 - mn1);
        mrun0 = mn0; mrun1 = mn1;

        float rs0 = 0.0f, rs1 = 0.0f;
        uint32_t pk[16][2];
#pragma unroll
        for (int j = 0; j < 16; j++) {
            float p0 = expf(c[j][0] - mn0);
            float p1 = expf(c[j][1] - mn0);
            float p2 = expf(c[j][2] - mn1);
            float p3 = expf(c[j][3] - mn1);
            rs0 += p0 + p1; rs1 += p2 + p3;
            pk[j][0] = packh2(p0, p1);
            pk[j][1] = packh2(p2, p3);
        }
        rs0 += __shfl_xor_sync(0xFFFFFFFF, rs0, 1);
        rs0 += __shfl_xor_sync(0xFFFFFFFF, rs0, 2);
        rs1 += __shfl_xor_sync(0xFFFFFFFF, rs1, 1);
        rs1 += __shfl_xor_sync(0xFFFFFFFF, rs1, 2);
        lrun0 = lrun0 * corr0 + rs0;
        lrun1 = lrun1 * corr1 + rs1;
#pragma unroll
        for (int j = 0; j < 32; j++) {
            o[j][0] *= corr0; o[j][1] *= corr0;
            o[j][2] *= corr1; o[j][3] *= corr1;
        }

        // ---- O += P Vt (k over 128 keys, n over 256 d) ----
#pragma unroll
        for (int hv = 0; hv < 2; hv++) {
            __pipeline_wait_prior(1 - hv);
            __syncthreads();
#pragma unroll
            for (int k2 = 0; k2 < 4; k2++) {
                int kk = hv * 4 + k2;
                uint32_t a0 = pk[2 * kk][0], a1 = pk[2 * kk][1];
                uint32_t a2 = pk[2 * kk + 1][0], a3 = pk[2 * kk + 1][1];
#pragma unroll
                for (int g = 0; g < 16; g++) {
                    int nr = g * 16 + brow;
                    uint32_t b0, b1, b2, b3;
                    ldsm4(b0, b1, b2, b3,
                          sV + hv * 32768 + nr * 128 + (((2 * k2 + kpB) ^ (nr & 7)) << 4));
                    mma16816(o[2 * g], a0, a1, a2, a3, b0, b1);
                    mma16816(o[2 * g + 1], a0, a1, a2, a3, b2, b3);
                }
            }
        }
        __syncthreads();   // all reads done before next tile restages
    }

    // ---- epilogue: normalize, pad-row override, write merged (b, l, h*d) ----
    float inv0 = 1.0f / lrun0, inv1 = 1.0f / lrun1;
    int q0 = qt * 128 + r0l, q1 = q0 + 8;
    int b_ = bh >> 2, h_ = bh & 3;
    int pad0 = g_pad[(b_ << 9) + q0];
    int pad1 = g_pad[(b_ << 9) + q1];
    const float i512 = 1.0f / 512.0f;
    const float* vs = Vsum + bh * DD;
    size_t base0 = (size_t)(b_ * 512 + q0) * HD + h_ * DD;
    size_t base1 = (size_t)(b_ * 512 + q1) * HD + h_ * DD;
#pragma unroll
    for (int j = 0; j < 32; j++) {
        int d = j * 8 + (l & 3) * 2;
        float v0 = o[j][0] * inv0, v1 = o[j][1] * inv0;
        float v2 = o[j][2] * inv1, v3 = o[j][3] * inv1;
        if (pad0) { v0 = vs[d] * i512; v1 = vs[d + 1] * i512; }
        if (pad1) { v2 = vs[d] * i512; v3 = vs[d + 1] * i512; }
        *(__half2*)(Om + base0 + d) = __floats2half2_rn(v0, v1);
        *(__half2*)(Om + base1 + d) = __floats2half2_rn(v2, v3);
    }
}

// ---------------- residual + layernorm (+optional fp16 out) ----------------
__global__ void __launch_bounds__(256)
ln_residual_kernel(const float* __restrict__ Ain, const float* __restrict__ Bin,
                   const float* __restrict__ gamma, const float* __restrict__ beta,
                   float* __restrict__ outF, __half* __restrict__ outH) {
    int row = blockIdx.x;
    int tid = threadIdx.x;
    size_t base = (size_t)row * DD + tid;
    float x = Ain[base] + Bin[base];
    __shared__ float red[256];
    red[tid] = x;
    __syncthreads();
    for (int s = 128; s > 0; s >>= 1) {
        if (tid < s) red[tid] += red[tid + s];
        __syncthreads();
    }
    float mu = red[0] * (1.0f / DD);
    __syncthreads();
    float d = x - mu;
    red[tid] = d * d;
    __syncthreads();
    for (int s = 128; s > 0; s >>= 1) {
        if (tid < s) red[tid] += red[tid + s];
        __syncthreads();
    }
    float var = red[0] * (1.0f / DD);
    float y = d * rsqrtf(var + 1e-5f) * gamma[tid] + beta[tid];
    if (outF) outF[base] = y;
    if (outH) outH[base] = __float2half_rn(y);
}

// ---------------- host orchestration ----------------
#define SYM(p, s) void* p; cudaGetSymbolAddress(&p, s)

extern "C" void kernel_launch(void* const* d_in, const int* in_sizes, int n_in,
                              void* d_out, int out_size) {
    (void)in_sizes; (void)n_in; (void)out_size;
    const float* Q    = (const float*)d_in[0];
    const float* K    = (const float*)d_in[1];
    const float* V    = (const float*)d_in[2];
    const void*  mask = d_in[3];
    const float* pe   = (const float*)d_in[4];
    const float* W_q  = (const float*)d_in[5];
    const float* W_k  = (const float*)d_in[6];
    const float* W_v  = (const float*)d_in[7];
    const float* W_o  = (const float*)d_in[8];
    const float* w1   = (const float*)d_in[9];
    const float* b1   = (const float*)d_in[10];
    const float* w2   = (const float*)d_in[11];
    const float* b2   = (const float*)d_in[12];
    const float* gamma = (const float*)d_in[13];
    const float* beta  = (const float*)d_in[14];
    float* out = (float*)d_out;

    SYM(pQpF, g_QpF);
    SYM(pQpH, g_QpH); SYM(pKpH, g_KpH); SYM(pVpH, g_VpH);
    SYM(pQhH, g_QhH); SYM(pKhH, g_KhH); SYM(pVhH, g_VhH); SYM(pVtH, g_VtH);
    SYM(pVsum, g_Vsum); SYM(pVmH, g_VmH);
    SYM(pT1, g_T1); SYM(pXF, g_XF); SYM(pXH, g_XH); SYM(pYH, g_YH); SYM(pZF, g_ZF);
    SYM(pWq, g_Wq); SYM(pWk, g_Wk); SYM(pWv, g_Wv); SYM(pWo, g_Wo);
    SYM(pw1, g_w1); SYM(pw2, g_w2);

    cudaFuncSetAttribute(gemm_h, cudaFuncAttributeMaxDynamicSharedMemorySize, 2 * STG);
    cudaFuncSetAttribute(flash_attn, cudaFuncAttributeMaxDynamicSharedMemorySize, FSM_TOT);

    typedef __half hf;

    // 1) mask
    detect_mask_kernel<<<1, 256>>>((const unsigned char*)mask);
    decode_mask_kernel<<<(NTOK + 255) / 256, 256>>>(mask);

    // 2) PE add + fp16 convert (vectorized)
    int q4 = NTOK * DD / 4, qb = (q4 + 255) / 256;
    add_pe_h4<<<qb, 256>>>((const float4*)Q, pe, (float4*)pQpF, (__half2*)pQpH);
    add_pe_h4<<<qb, 256>>>((const float4*)K, pe, nullptr, (__half2*)pKpH);
    add_pe_h4<<<qb, 256>>>((const float4*)V, pe, nullptr, (__half2*)pVpH);

    // 3) weights to fp16 [n][k]
    wconv_trans<<<(DD * HD + 255) / 256, 256>>>(W_q, (hf*)pWq, DD, HD);
    wconv_trans<<<(DD * HD + 255) / 256, 256>>>(W_k, (hf*)pWk, DD, HD);
    wconv_trans<<<(DD * HD + 255) / 256, 256>>>(W_v, (hf*)pWv, DD, HD);
    wconv_trans<<<(DD * HD + 255) / 256, 256>>>(W_o, (hf*)pWo, HD, DD);
    wconv_direct<<<(DD * DD + 255) / 256, 256>>>(w1, (hf*)pw1, DD * DD);
    wconv_direct<<<(DD * DD + 255) / 256, 256>>>(w2, (hf*)pw2, DD * DD);

    // 4) QKV projections -> head-split (bh, l, d)
    {
        dim3 g(HD / NT, NTOK / MT, 1);
        gemm_h<<<g, 256, 2 * STG>>>((hf*)pQpH, (hf*)pWq, nullptr, (hf*)pQhH, nullptr,
                                    DD, 0, 0, 0, 0, MODE_HEADSPLIT, 1.0f, 0);
        gemm_h<<<g, 256, 2 * STG>>>((hf*)pKpH, (hf*)pWk, nullptr, (hf*)pKhH, nullptr,
                                    DD, 0, 0, 0, 0, MODE_HEADSPLIT, 1.0f, 0);
        gemm_h<<<g, 256, 2 * STG>>>((hf*)pVpH, (hf*)pWv, nullptr, (hf*)pVhH, nullptr,
                                    DD, 0, 0, 0, 0, MODE_HEADSPLIT, 1.0f, 0);
    }

    // 5) V transpose + Vsum
    {
        dim3 g(DD / 32, LL / 32, BH);
        transpose_v<<<g, dim3(32, 8)>>>((hf*)pVhH, (hf*)pVtH);
        vsum_kernel<<<BH, 256>>>((hf*)pVhH, (float*)pVsum);
    }

    // 6) fused flash attention -> merged (b, l, h*d)
    {
        dim3 g(LL / 128, BH);
        flash_attn<<<g, 256, FSM_TOT>>>((hf*)pQhH, (hf*)pKhH, (hf*)pVtH,
                                        (float*)pVsum, (hf*)pVmH);
    }

    // 7) output projection: T1 = Vm @ W_o  (M=16384, N=256, K=1024)
    {
        dim3 g(DD / NT, NTOK / MT, 1);
        gemm_h<<<g, 256, 2 * STG>>>((hf*)pVmH, (hf*)pWo, (float*)pT1, nullptr, nullptr,
                                    HD, 0, 0, 0, DD, MODE_PLAIN, 1.0f, 0);
    }

    // 8) X = LN(Qp + T1)
    ln_residual_kernel<<<NTOK, 256>>>((float*)pQpF, (float*)pT1, gamma, beta,
                                      (float*)pXF, (hf*)pXH);

    // 9) FFN: Y = relu(X @ w1^T + b1); Z = Y @ w2^T + b2
    {
        dim3 g(DD / NT, NTOK / MT, 1);
        gemm_h<<<g, 256, 2 * STG>>>((hf*)pXH, (hf*)pw1, nullptr, (hf*)pYH, b1,
                                    DD, 0, 0, 0, DD, MODE_PLAIN, 1.0f, 1);
        gemm_h<<<g, 256, 2 * STG>>>((hf*)pYH, (hf*)pw2, (float*)pZF, nullptr, b2,
                                    DD, 0, 0, 0, DD, MODE_PLAIN, 1.0f, 0);
    }

    // 10) out = LN(Z + X)
    ln_residual_kernel<<<NTOK, 256>>>((float*)pZF, (float*)pXF, gamma, beta, out, nullptr);
}

// round 8
// speedup vs baseline: 4.1979x; 1.1617x over previous
#include <cuda_runtime.h>
#include <cuda_fp16.h>
#include <cuda_pipeline.h>
#include <cstdint>

// Problem dims: B=32, L=512, D=256, H=4
#define BB 32
#define LL 512
#define DD 256
#define HH 4
#define NTOK (BB * LL)      // 16384
#define BH (BB * HH)        // 128
#define HD (HH * DD)        // 1024

// ---------------- device scratch (.bss, allocation-free) ----------------
__device__ __align__(256) float g_QpF[NTOK * DD];
__device__ __align__(256) __half g_QpH[NTOK * DD], g_KpH[NTOK * DD], g_VpH[NTOK * DD];
__device__ __align__(256) __half g_QhH[BH * LL * DD];     // (bh, l, d)
__device__ __align__(256) __half g_KhH[BH * LL * DD];     // (bh, l, d)
__device__ __align__(256) __half g_VhH[BH * LL * DD];     // (bh, l, d)
__device__ __align__(256) __half g_VtH[BH * DD * LL];     // (bh, d, l)
__device__ __align__(256) float g_Vsum[BH * DD];
__device__ __align__(256) __half g_VmH[NTOK * HD];        // (b, l, h*d)
__device__ __align__(256) float g_T1[NTOK * DD];
__device__ __align__(256) float g_XF[NTOK * DD];
__device__ __align__(256) __half g_XH[NTOK * DD];
__device__ __align__(256) __half g_YH[NTOK * DD];
__device__ __align__(256) float g_ZF[NTOK * DD];
// weights as B operand layout: [n][k] (k contiguous)
__device__ __align__(256) __half g_Wq[HD * DD], g_Wk[HD * DD], g_Wv[HD * DD];
__device__ __align__(256) __half g_Wo[DD * HD];
__device__ __align__(256) __half g_w1[DD * DD], g_w2[DD * DD];
__device__ int g_pad[NTOK];
__device__ int g_byte_mode;

// ---------------- mask sniff + decode ----------------
__global__ void detect_mask_kernel(const unsigned char* m) {
    __shared__ int any;
    if (threadIdx.x == 0) any = 0;
    __syncthreads();
    int local = 0;
    for (int i = threadIdx.x; i < NTOK / 4; i += blockDim.x)
        if (m[4 * i + 1]) local = 1;
    if (local) atomicOr(&any, 1);
    __syncthreads();
    if (threadIdx.x == 0) g_byte_mode = any;
}
__global__ void decode_mask_kernel(const void* m) {
    int i = blockIdx.x * blockDim.x + threadIdx.x;
    if (i >= NTOK) return;
    g_pad[i] = g_byte_mode ? (((const unsigned char*)m)[i] != 0)
                           : (((const int*)m)[i] != 0);
}

// ---------------- PE add for Q, K, V in one launch (grid.y selects) ----------------
__global__ void add_pe_all(const float4* __restrict__ Q, const float4* __restrict__ K,
                           const float4* __restrict__ V, const float* __restrict__ pe,
                           float4* __restrict__ QpF, __half2* __restrict__ QpH,
                           __half2* __restrict__ KpH, __half2* __restrict__ VpH) {
    int i = blockIdx.x * blockDim.x + threadIdx.x;   // over NTOK*DD/4
    if (i >= NTOK * DD / 4) return;
    int y = blockIdx.y;
    const float4* in = (y == 0) ? Q : (y == 1) ? K : V;
    __half2* outH = (y == 0) ? QpH : (y == 1) ? KpH : VpH;
    int d4 = i & 63;
    int l = (i >> 6) & (LL - 1);
    float4 v = in[i];
    float4 p = *(const float4*)(pe + l * DD + d4 * 4);
    v.x += p.x; v.y += p.y; v.z += p.z; v.w += p.w;
    if (y == 0) QpF[i] = v;
    outH[2 * i] = __floats2half2_rn(v.x, v.y);
    outH[2 * i + 1] = __floats2half2_rn(v.z, v.w);
}

// ---------------- all weight conversions in one launch (grid.y = 0..5) ----------------
__global__ void wconv_all(const float* __restrict__ Wq, const float* __restrict__ Wk,
                          const float* __restrict__ Wv, const float* __restrict__ Wo,
                          const float* __restrict__ w1, const float* __restrict__ w2,
                          __half* __restrict__ dWq, __half* __restrict__ dWk,
                          __half* __restrict__ dWv, __half* __restrict__ dWo,
                          __half* __restrict__ dw1, __half* __restrict__ dw2) {
    int i = blockIdx.x * blockDim.x + threadIdx.x;
    int y = blockIdx.y;
    if (y < 3) {
        // (DD, HD) -> [n][k]: dst[c*DD + r] = src[r*HD + c]
        if (i >= DD * HD) return;
        const float* s = (y == 0) ? Wq : (y == 1) ? Wk : Wv;
        __half* d = (y == 0) ? dWq : (y == 1) ? dWk : dWv;
        int c = i >> 8, r = i & 255;
        d[i] = __float2half_rn(s[r * HD + c]);
    } else if (y == 3) {
        // (HD, DD) -> dst[c*HD + r] = src[r*DD + c]
        if (i >= HD * DD) return;
        int c = i >> 10, r = i & 1023;
        dWo[i] = __float2half_rn(Wo[r * DD + c]);
    } else {
        if (i >= DD * DD) return;
        const float* s = (y == 4) ? w1 : w2;
        __half* d = (y == 4) ? dw1 : dw2;
        d[i] = __float2half_rn(s[i]);
    }
}

// ---------------- V transpose: (bh, l, d) -> (bh, d, l) ----------------
__global__ void transpose_v(const __half* __restrict__ in, __half* __restrict__ out) {
    __shared__ __half t[32][33];
    int bh = blockIdx.z;
    int d0 = blockIdx.x * 32, l0 = blockIdx.y * 32;
    int tx = threadIdx.x, ty = threadIdx.y;   // 32 x 8
#pragma unroll
    for (int s = 0; s < 32; s += 8)
        t[ty + s][tx] = in[(size_t)bh * LL * DD + (size_t)(l0 + ty + s) * DD + d0 + tx];
    __syncthreads();
#pragma unroll
    for (int s = 0; s < 32; s += 8)
        out[(size_t)bh * DD * LL + (size_t)(d0 + ty + s) * LL + l0 + tx] = t[tx][ty + s];
}

// ---------------- Vsum[bh][d] = sum_l Vh[bh][l][d] ----------------
__global__ void vsum_kernel(const __half* __restrict__ Vh, float* __restrict__ Vs) {
    int bh = blockIdx.x;
    int d = threadIdx.x;   // 256
    const __half* p = Vh + (size_t)bh * LL * DD + d;
    float s = 0.0f;
#pragma unroll 8
    for (int l = 0; l < LL; l++) s += __half2float(p[(size_t)l * DD]);
    Vs[bh * DD + d] = s;
}

// ---------------- asm helpers ----------------
__device__ __forceinline__ uint32_t smem_u32(const void* p) {
    uint32_t a;
    asm("{ .reg .u64 t; cvta.to.shared.u64 t, %1; cvt.u32.u64 %0, t; }" : "=r"(a) : "l"(p));
    return a;
}
__device__ __forceinline__ void ldsm4(uint32_t& r0, uint32_t& r1, uint32_t& r2, uint32_t& r3,
                                      uint32_t addr) {
    asm volatile("ldmatrix.sync.aligned.m8n8.x4.shared.b16 {%0,%1,%2,%3}, [%4];"
                 : "=r"(r0), "=r"(r1), "=r"(r2), "=r"(r3) : "r"(addr));
}
__device__ __forceinline__ void mma16816(float* c, uint32_t a0, uint32_t a1, uint32_t a2,
                                         uint32_t a3, uint32_t b0, uint32_t b1) {
    asm volatile(
        "mma.sync.aligned.m16n8k16.row.col.f32.f16.f16.f32 "
        "{%0,%1,%2,%3}, {%4,%5,%6,%7}, {%8,%9}, {%0,%1,%2,%3};"
        : "+f"(c[0]), "+f"(c[1]), "+f"(c[2]), "+f"(c[3])
        : "r"(a0), "r"(a1), "r"(a2), "r"(a3), "r"(b0), "r"(b1));
}
__device__ __forceinline__ uint32_t packh2(float a, float b) {
    __half2 h = __floats2half2_rn(a, b);
    return *(uint32_t*)&h;
}

// ---------------- fp16 mma.sync GEMM, 3-stage cp.async pipeline ----------------
#define MT 128
#define NT 128
#define KC 64
#define STG 32768          // A 16K + B 16K per stage
#define NSTG 3

#define MODE_PLAIN 0
#define MODE_HEADSPLIT 1

__global__ void __launch_bounds__(256, 2)
gemm_h(const __half* __restrict__ A, const __half* __restrict__ B,
       float* __restrict__ outF, __half* __restrict__ outH, const float* __restrict__ bias,
       int K, long long aBatch, long long bBatch, long long cBatch, int ldc,
       int mode, float alpha, int doRelu) {
    extern __shared__ __align__(128) char smem[];

    const int bz = blockIdx.z;
    const int bm0 = blockIdx.y * MT;
    const int bn0 = blockIdx.x * NT;

    const int tid = threadIdx.x;
    const int wid = tid >> 5;
    const int l = tid & 31;
    const int wr = wid & 3;
    const int wc = wid >> 2;

    const __half* gA = A + bz * aBatch + (long long)bm0 * K;
    const __half* gB = B + bz * bBatch + (long long)bn0 * K;
    const uint32_t sbase = smem_u32(smem);

    float c[2][8][4];
#pragma unroll
    for (int i = 0; i < 2; i++)
#pragma unroll
        for (int j = 0; j < 8; j++)
#pragma unroll
            for (int e = 0; e < 4; e++) c[i][j][e] = 0.0f;

    const int mrow = wr * 32 + ((l >> 3) & 1) * 8 + (l & 7);
    const int kpA = (l >> 4) & 1;
    const int nrow = wc * 64 + ((l >> 4) & 1) * 8 + (l & 7);
    const int kpB = (l >> 3) & 1;

    auto stage_fn = [&](int buf, int k0) {
        char* sA = smem + buf * STG;
        char* sB = sA + 16384;
#pragma unroll
        for (int it = 0; it < 4; it++) {
            int idx = tid + it * 256;
            int r = idx >> 3, ch = idx & 7;
            __pipeline_memcpy_async(sA + r * 128 + ((ch ^ (r & 7)) << 4),
                                    gA + (long long)r * K + k0 + ch * 8, 16);
        }
#pragma unroll
        for (int it = 0; it < 4; it++) {
            int idx = tid + it * 256;
            int r = idx >> 3, ch = idx & 7;
            __pipeline_memcpy_async(sB + r * 128 + ((ch ^ (r & 7)) << 4),
                                    gB + (long long)r * K + k0 + ch * 8, 16);
        }
    };

    const int nt = K / KC;
    stage_fn(0, 0);
    __pipeline_commit();
    if (nt > 1) { stage_fn(1, KC); __pipeline_commit(); }

    for (int cc = 0; cc < nt; cc++) {
        if (cc < nt - 1) __pipeline_wait_prior(1);
        else __pipeline_wait_prior(0);
        __syncthreads();
        if (cc + 2 < nt) {                       // depth-2 prefetch into 3rd buffer
            stage_fn((cc + 2) % NSTG, (cc + 2) * KC);
            __pipeline_commit();
        }

        const int buf = cc % NSTG;
        const uint32_t sA = sbase + buf * STG;
        const uint32_t sB = sA + 16384;
#pragma unroll
        for (int ks = 0; ks < 4; ks++) {
            uint32_t a[2][4];
#pragma unroll
            for (int i = 0; i < 2; i++) {
                int row = mrow + i * 16;
                ldsm4(a[i][0], a[i][1], a[i][2], a[i][3],
                      sA + row * 128 + (((2 * ks + kpA) ^ (row & 7)) << 4));
            }
            uint32_t b[4][4];
#pragma unroll
            for (int g = 0; g < 4; g++) {
                int row = nrow + g * 16;
                ldsm4(b[g][0], b[g][1], b[g][2], b[g][3],
                      sB + row * 128 + (((2 * ks + kpB) ^ (row & 7)) << 4));
            }
#pragma unroll
            for (int i = 0; i < 2; i++)
#pragma unroll
                for (int j = 0; j < 8; j++) {
                    int g = j >> 1, h2 = (j & 1) << 1;
                    mma16816(c[i][j], a[i][0], a[i][1], a[i][2], a[i][3],
                             b[g][h2], b[g][h2 + 1]);
                }
        }
    }

    const int mb = bm0 + wr * 32 + (l >> 2);
    const int nb = bn0 + wc * 64 + (l & 3) * 2;
    auto emit2 = [&](int m, int n, float v0, float v1) {
        v0 *= alpha; v1 *= alpha;
        if (bias) { v0 += bias[n]; v1 += bias[n + 1]; }
        if (doRelu) { v0 = fmaxf(v0, 0.0f); v1 = fmaxf(v1, 0.0f); }
        size_t oidx;
        if (mode == MODE_PLAIN) {
            oidx = (size_t)bz * cBatch + (size_t)m * ldc + n;
        } else {  // MODE_HEADSPLIT
            int b_ = m >> 9, l_ = m & 511, h_ = n >> 8, d_ = n & 255;
            oidx = ((size_t)((b_ * HH + h_) * LL + l_)) * DD + d_;
        }
        if (outF) *(float2*)(outF + oidx) = make_float2(v0, v1);
        else *(__half2*)(outH + oidx) = __floats2half2_rn(v0, v1);
    };
#pragma unroll
    for (int i = 0; i < 2; i++) {
        int m = mb + i * 16;
#pragma unroll
        for (int j = 0; j < 8; j++) {
            int n = nb + j * 8;
            emit2(m, n, c[i][j][0], c[i][j][1]);
            emit2(m + 8, n, c[i][j][2], c[i][j][3]);
        }
    }
}

// ---------------- fused flash attention (unchanged from R7) ----------------
#define FSM_K 65536
#define FSM_V 131072
#define FSM_TOT 196608

__global__ void __launch_bounds__(256, 1)
flash_attn(const __half* __restrict__ Qh, const __half* __restrict__ Kh,
           const __half* __restrict__ Vt, const float* __restrict__ Vsum,
           __half* __restrict__ Om) {
    extern __shared__ __align__(128) char smem[];
    const int qt = blockIdx.x;
    const int bh = blockIdx.y;
    const int tid = threadIdx.x;
    const int w = tid >> 5;
    const int l = tid & 31;

    const __half* gQ = Qh + ((size_t)bh * LL + qt * 128) * DD;
    const __half* gK = Kh + (size_t)bh * LL * DD;
    const __half* gV = Vt + (size_t)bh * DD * LL;
    char* smQ = smem;
    char* smK = smem + FSM_K;
    char* smV = smem + FSM_V;
    const uint32_t sQ = smem_u32(smem);
    const uint32_t sK = sQ + FSM_K;
    const uint32_t sV = sQ + FSM_V;

#pragma unroll
    for (int cq = 0; cq < 4; cq++)
#pragma unroll
        for (int it = 0; it < 4; it++) {
            int idx = tid + it * 256;
            int r = idx >> 3, ch = idx & 7;
            __pipeline_memcpy_async(smQ + cq * 16384 + r * 128 + ((ch ^ (r & 7)) << 4),
                                    gQ + (size_t)r * DD + cq * 64 + ch * 8, 16);
        }
    __pipeline_commit();

    float o[32][4];
#pragma unroll
    for (int j = 0; j < 32; j++)
#pragma unroll
        for (int e = 0; e < 4; e++) o[j][e] = 0.0f;
    float mrun0 = -INFINITY, mrun1 = -INFINITY;
    float lrun0 = 0.0f, lrun1 = 0.0f;

    const int r0l = w * 16 + (l >> 2);
    const int r1l = r0l + 8;
    const int arow = w * 16 + ((l >> 3) & 1) * 8 + (l & 7);
    const int kpA = (l >> 4) & 1;
    const int brow = ((l >> 4) & 1) * 8 + (l & 7);
    const int kpB = (l >> 3) & 1;
    const float alpha = (float)(1.0 / (16.0 + 1e-6));

    for (int kt = 0; kt <= qt; kt++) {
#pragma unroll
        for (int ck = 0; ck < 4; ck++) {
#pragma unroll
            for (int it = 0; it < 4; it++) {
                int idx = tid + it * 256;
                int r = idx >> 3, ch = idx & 7;
                __pipeline_memcpy_async(smK + ck * 16384 + r * 128 + ((ch ^ (r & 7)) << 4),
                                        gK + (size_t)(kt * 128 + r) * DD + ck * 64 + ch * 8, 16);
            }
            __pipeline_commit();
        }
#pragma unroll
        for (int cv = 0; cv < 2; cv++) {
#pragma unroll
            for (int it = 0; it < 8; it++) {
                int idx = tid + it * 256;
                int r = idx >> 3, ch = idx & 7;
                __pipeline_memcpy_async(smV + cv * 32768 + r * 128 + ((ch ^ (r & 7)) << 4),
                                        gV + (size_t)r * LL + kt * 128 + cv * 64 + ch * 8, 16);
            }
            __pipeline_commit();
        }

        float c[16][4];
#pragma unroll
        for (int j = 0; j < 16; j++)
#pragma unroll
            for (int e = 0; e < 4; e++) c[j][e] = 0.0f;

#pragma unroll
        for (int ck = 0; ck < 4; ck++) {
            __pipeline_wait_prior(5 - ck);
            __syncthreads();
#pragma unroll
            for (int ks = 0; ks < 4; ks++) {
                uint32_t a0, a1, a2, a3;
                ldsm4(a0, a1, a2, a3,
                      sQ + ck * 16384 + arow * 128 + (((2 * ks + kpA) ^ (arow & 7)) << 4));
#pragma unroll
                for (int g = 0; g < 8; g++) {
                    int nr = g * 16 + brow;
                    uint32_t b0, b1, b2, b3;
                    ldsm4(b0, b1, b2, b3,
                          sK + ck * 16384 + nr * 128 + (((2 * ks + kpB) ^ (nr & 7)) << 4));
                    mma16816(c[2 * g], a0, a1, a2, a3, b0, b1);
                    mma16816(c[2 * g + 1], a0, a1, a2, a3, b2, b3);
                }
            }
        }

        if (kt == qt) {
#pragma unroll
            for (int j = 0; j < 16; j++) {
                int nb = j * 8 + (l & 3) * 2;
                c[j][0] = (nb     <= r0l) ? c[j][0] * alpha : -INFINITY;
                c[j][1] = (nb + 1 <= r0l) ? c[j][1] * alpha : -INFINITY;
                c[j][2] = (nb     <= r1l) ? c[j][2] * alpha : -INFINITY;
                c[j][3] = (nb + 1 <= r1l) ? c[j][3] * alpha : -INFINITY;
            }
        } else {
#pragma unroll
            for (int j = 0; j < 16; j++)
#pragma unroll
                for (int e = 0; e < 4; e++) c[j][e] *= alpha;
        }

        float mn0 = mrun0, mn1 = mrun1;
#pragma unroll
        for (int j = 0; j < 16; j++) {
            mn0 = fmaxf(mn0, fmaxf(c[j][0], c[j][1]));
            mn1 = fmaxf(mn1, fmaxf(c[j][2], c[j][3]));
        }
        mn0 = fmaxf(mn0, __shfl_xor_sync(0xFFFFFFFF, mn0, 1));
        mn0 = fmaxf(mn0, __shfl_xor_sync(0xFFFFFFFF, mn0, 2));
        mn1 = fmaxf(mn1, __shfl_xor_sync(0xFFFFFFFF, mn1, 1));
        mn1 = fmaxf(mn1, __shfl_xor_sync(0xFFFFFFFF, mn1, 2));
        float corr0 = expf(mrun0 - mn0);
        float corr1 = expf(mrun1 - mn1);
        mrun0 = mn0; mrun1 = mn1;

        float rs0 = 0.0f, rs1 = 0.0f;
        uint32_t pk[16][2];
#pragma unroll
        for (int j = 0; j < 16; j++) {
            float p0 = expf(c[j][0] - mn0);
            float p1 = expf(c[j][1] - mn0);
            float p2 = expf(c[j][2] - mn1);
            float p3 = expf(c[j][3] - mn1);
            rs0 += p0 + p1; rs1 += p2 + p3;
            pk[j][0] = packh2(p0, p1);
            pk[j][1] = packh2(p2, p3);
        }
        rs0 += __shfl_xor_sync(0xFFFFFFFF, rs0, 1);
        rs0 += __shfl_xor_sync(0xFFFFFFFF, rs0, 2);
        rs1 += __shfl_xor_sync(0xFFFFFFFF, rs1, 1);
        rs1 += __shfl_xor_sync(0xFFFFFFFF, rs1, 2);
        lrun0 = lrun0 * corr0 + rs0;
        lrun1 = lrun1 * corr1 + rs1;
#pragma unroll
        for (int j = 0; j < 32; j++) {
            o[j][0] *= corr0; o[j][1] *= corr0;
            o[j][2] *= corr1; o[j][3] *= corr1;
        }

#pragma unroll
        for (int hv = 0; hv < 2; hv++) {
            __pipeline_wait_prior(1 - hv);
            __syncthreads();
#pragma unroll
            for (int k2 = 0; k2 < 4; k2++) {
                int kk = hv * 4 + k2;
                uint32_t a0 = pk[2 * kk][0], a1 = pk[2 * kk][1];
                uint32_t a2 = pk[2 * kk + 1][0], a3 = pk[2 * kk + 1][1];
#pragma unroll
                for (int g = 0; g < 16; g++) {
                    int nr = g * 16 + brow;
                    uint32_t b0, b1, b2, b3;
                    ldsm4(b0, b1, b2, b3,
                          sV + hv * 32768 + nr * 128 + (((2 * k2 + kpB) ^ (nr & 7)) << 4));
                    mma16816(o[2 * g], a0, a1, a2, a3, b0, b1);
                    mma16816(o[2 * g + 1], a0, a1, a2, a3, b2, b3);
                }
            }
        }
        __syncthreads();
    }

    float inv0 = 1.0f / lrun0, inv1 = 1.0f / lrun1;
    int q0 = qt * 128 + r0l, q1 = q0 + 8;
    int b_ = bh >> 2, h_ = bh & 3;
    int pad0 = g_pad[(b_ << 9) + q0];
    int pad1 = g_pad[(b_ << 9) + q1];
    const float i512 = 1.0f / 512.0f;
    const float* vs = Vsum + bh * DD;
    size_t base0 = (size_t)(b_ * 512 + q0) * HD + h_ * DD;
    size_t base1 = (size_t)(b_ * 512 + q1) * HD + h_ * DD;
#pragma unroll
    for (int j = 0; j < 32; j++) {
        int d = j * 8 + (l & 3) * 2;
        float v0 = o[j][0] * inv0, v1 = o[j][1] * inv0;
        float v2 = o[j][2] * inv1, v3 = o[j][3] * inv1;
        if (pad0) { v0 = vs[d] * i512; v1 = vs[d + 1] * i512; }
        if (pad1) { v2 = vs[d] * i512; v3 = vs[d + 1] * i512; }
        *(__half2*)(Om + base0 + d) = __floats2half2_rn(v0, v1);
        *(__half2*)(Om + base1 + d) = __floats2half2_rn(v2, v3);
    }
}

// ---------------- residual + layernorm: warp per row, zero barriers ----------------
__global__ void __launch_bounds__(256)
ln_residual_kernel(const float* __restrict__ Ain, const float* __restrict__ Bin,
                   const float* __restrict__ gamma, const float* __restrict__ beta,
                   float* __restrict__ outF, __half* __restrict__ outH) {
    int row = blockIdx.x * 8 + (threadIdx.x >> 5);
    int l = threadIdx.x & 31;
    size_t base = (size_t)row * DD + l * 8;

    float4 a0 = *(const float4*)(Ain + base);
    float4 a1 = *(const float4*)(Ain + base + 4);
    float4 b0 = *(const float4*)(Bin + base);
    float4 b1 = *(const float4*)(Bin + base + 4);
    float x[8] = {a0.x + b0.x, a0.y + b0.y, a0.z + b0.z, a0.w + b0.w,
                  a1.x + b1.x, a1.y + b1.y, a1.z + b1.z, a1.w + b1.w};

    float s = 0.0f;
#pragma unroll
    for (int e = 0; e < 8; e++) s += x[e];
#pragma unroll
    for (int off = 16; off > 0; off >>= 1) s += __shfl_xor_sync(0xFFFFFFFF, s, off);
    float mu = s * (1.0f / DD);

    float sq = 0.0f;
#pragma unroll
    for (int e = 0; e < 8; e++) { float d = x[e] - mu; sq += d * d; }
#pragma unroll
    for (int off = 16; off > 0; off >>= 1) sq += __shfl_xor_sync(0xFFFFFFFF, sq, off);
    float rstd = rsqrtf(sq * (1.0f / DD) + 1e-5f);

    float4 g0 = *(const float4*)(gamma + l * 8);
    float4 g1 = *(const float4*)(gamma + l * 8 + 4);
    float4 be0 = *(const float4*)(beta + l * 8);
    float4 be1 = *(const float4*)(beta + l * 8 + 4);
    float y[8];
    y[0] = (x[0] - mu) * rstd * g0.x + be0.x;
    y[1] = (x[1] - mu) * rstd * g0.y + be0.y;
    y[2] = (x[2] - mu) * rstd * g0.z + be0.z;
    y[3] = (x[3] - mu) * rstd * g0.w + be0.w;
    y[4] = (x[4] - mu) * rstd * g1.x + be1.x;
    y[5] = (x[5] - mu) * rstd * g1.y + be1.y;
    y[6] = (x[6] - mu) * rstd * g1.z + be1.z;
    y[7] = (x[7] - mu) * rstd * g1.w + be1.w;

    if (outF) {
        *(float4*)(outF + base) = make_float4(y[0], y[1], y[2], y[3]);
        *(float4*)(outF + base + 4) = make_float4(y[4], y[5], y[6], y[7]);
    }
    if (outH) {
        __half2 h[4] = {__floats2half2_rn(y[0], y[1]), __floats2half2_rn(y[2], y[3]),
                        __floats2half2_rn(y[4], y[5]), __floats2half2_rn(y[6], y[7])};
        *(float4*)(outH + base) = *(float4*)h;   // 4x half2 = 16B aligned store
    }
}

// ---------------- host orchestration ----------------
#define SYM(p, s) void* p; cudaGetSymbolAddress(&p, s)

extern "C" void kernel_launch(void* const* d_in, const int* in_sizes, int n_in,
                              void* d_out, int out_size) {
    (void)in_sizes; (void)n_in; (void)out_size;
    const float* Q    = (const float*)d_in[0];
    const float* K    = (const float*)d_in[1];
    const float* V    = (const float*)d_in[2];
    const void*  mask = d_in[3];
    const float* pe   = (const float*)d_in[4];
    const float* W_q  = (const float*)d_in[5];
    const float* W_k  = (const float*)d_in[6];
    const float* W_v  = (const float*)d_in[7];
    const float* W_o  = (const float*)d_in[8];
    const float* w1   = (const float*)d_in[9];
    const float* b1   = (const float*)d_in[10];
    const float* w2   = (const float*)d_in[11];
    const float* b2   = (const float*)d_in[12];
    const float* gamma = (const float*)d_in[13];
    const float* beta  = (const float*)d_in[14];
    float* out = (float*)d_out;

    SYM(pQpF, g_QpF);
    SYM(pQpH, g_QpH); SYM(pKpH, g_KpH); SYM(pVpH, g_VpH);
    SYM(pQhH, g_QhH); SYM(pKhH, g_KhH); SYM(pVhH, g_VhH); SYM(pVtH, g_VtH);
    SYM(pVsum, g_Vsum); SYM(pVmH, g_VmH);
    SYM(pT1, g_T1); SYM(pXF, g_XF); SYM(pXH, g_XH); SYM(pYH, g_YH); SYM(pZF, g_ZF);
    SYM(pWq, g_Wq); SYM(pWk, g_Wk); SYM(pWv, g_Wv); SYM(pWo, g_Wo);
    SYM(pw1, g_w1); SYM(pw2, g_w2);

    cudaFuncSetAttribute(gemm_h, cudaFuncAttributeMaxDynamicSharedMemorySize, NSTG * STG);
    cudaFuncSetAttribute(flash_attn, cudaFuncAttributeMaxDynamicSharedMemorySize, FSM_TOT);

    typedef __half hf;

    // 1) mask
    detect_mask_kernel<<<1, 256>>>((const unsigned char*)mask);
    decode_mask_kernel<<<(NTOK + 255) / 256, 256>>>(mask);

    // 2) PE add + fp16 convert (Q, K, V in one launch)
    {
        int q4 = NTOK * DD / 4, qb = (q4 + 255) / 256;
        add_pe_all<<<dim3(qb, 3), 256>>>((const float4*)Q, (const float4*)K,
                                         (const float4*)V, pe, (float4*)pQpF,
                                         (__half2*)pQpH, (__half2*)pKpH, (__half2*)pVpH);
    }

    // 3) all weights to fp16 [n][k] in one launch
    wconv_all<<<dim3(1024, 6), 256>>>(W_q, W_k, W_v, W_o, w1, w2,
                                      (hf*)pWq, (hf*)pWk, (hf*)pWv, (hf*)pWo,
                                      (hf*)pw1, (hf*)pw2);

    // 4) QKV projections -> head-split (bh, l, d)
    {
        dim3 g(HD / NT, NTOK / MT, 1);
        gemm_h<<<g, 256, NSTG * STG>>>((hf*)pQpH, (hf*)pWq, nullptr, (hf*)pQhH, nullptr,
                                       DD, 0, 0, 0, 0, MODE_HEADSPLIT, 1.0f, 0);
        gemm_h<<<g, 256, NSTG * STG>>>((hf*)pKpH, (hf*)pWk, nullptr, (hf*)pKhH, nullptr,
                                       DD, 0, 0, 0, 0, MODE_HEADSPLIT, 1.0f, 0);
        gemm_h<<<g, 256, NSTG * STG>>>((hf*)pVpH, (hf*)pWv, nullptr, (hf*)pVhH, nullptr,
                                       DD, 0, 0, 0, 0, MODE_HEADSPLIT, 1.0f, 0);
    }

    // 5) V transpose + Vsum
    {
        dim3 g(DD / 32, LL / 32, BH);
        transpose_v<<<g, dim3(32, 8)>>>((hf*)pVhH, (hf*)pVtH);
        vsum_kernel<<<BH, 256>>>((hf*)pVhH, (float*)pVsum);
    }

    // 6) fused flash attention -> merged (b, l, h*d)
    {
        dim3 g(LL / 128, BH);
        flash_attn<<<g, 256, FSM_TOT>>>((hf*)pQhH, (hf*)pKhH, (hf*)pVtH,
                                        (float*)pVsum, (hf*)pVmH);
    }

    // 7) output projection: T1 = Vm @ W_o  (M=16384, N=256, K=1024)
    {
        dim3 g(DD / NT, NTOK / MT, 1);
        gemm_h<<<g, 256, NSTG * STG>>>((hf*)pVmH, (hf*)pWo, (float*)pT1, nullptr, nullptr,
                                       HD, 0, 0, 0, DD, MODE_PLAIN, 1.0f, 0);
    }

    // 8) X = LN(Qp + T1)
    ln_residual_kernel<<<NTOK / 8, 256>>>((float*)pQpF, (float*)pT1, gamma, beta,
                                          (float*)pXF, (hf*)pXH);

    // 9) FFN: Y = relu(X @ w1^T + b1); Z = Y @ w2^T + b2
    {
        dim3 g(DD / NT, NTOK / MT, 1);
        gemm_h<<<g, 256, NSTG * STG>>>((hf*)pXH, (hf*)pw1, nullptr, (hf*)pYH, b1,
                                       DD, 0, 0, 0, DD, MODE_PLAIN, 1.0f, 1);
        gemm_h<<<g, 256, NSTG * STG>>>((hf*)pYH, (hf*)pw2, (float*)pZF, nullptr, b2,
                                       DD, 0, 0, 0, DD, MODE_PLAIN, 1.0f, 0);
    }

    // 10) out = LN(Z + X)
    ln_residual_kernel<<<NTOK / 8, 256>>>((float*)pZF, (float*)pXF, gamma, beta, out, nullptr);
}

// round 9
// speedup vs baseline: 4.5101x; 1.0744x over previous
#include <cuda_runtime.h>
#include <cuda_fp16.h>
#include <cuda_pipeline.h>
#include <cstdint>

// Problem dims: B=32, L=512, D=256, H=4
#define BB 32
#define LL 512
#define DD 256
#define HH 4
#define NTOK (BB * LL)      // 16384
#define BH (BB * HH)        // 128
#define HD (HH * DD)        // 1024

// ---------------- device scratch (.bss, allocation-free) ----------------
__device__ __align__(256) float g_QpF[NTOK * DD];
__device__ __align__(256) __half g_QpH[NTOK * DD], g_KpH[NTOK * DD], g_VpH[NTOK * DD];
__device__ __align__(256) __half g_QhH[BH * LL * DD];     // (bh, l, d)
__device__ __align__(256) __half g_KhH[BH * LL * DD];     // (bh, l, d)
__device__ __align__(256) __half g_VtH[BH * DD * LL];     // (bh, d, l)
__device__ __align__(256) float g_Vsum[BH * DD];
__device__ __align__(256) __half g_VmH[NTOK * HD];        // (b, l, h*d)
__device__ __align__(256) float g_T1[NTOK * DD];
__device__ __align__(256) float g_XF[NTOK * DD];
__device__ __align__(256) __half g_XH[NTOK * DD];
__device__ __align__(256) __half g_YH[NTOK * DD];
__device__ __align__(256) float g_ZF[NTOK * DD];
// weights as B operand layout: [n][k] (k contiguous)
__device__ __align__(256) __half g_Wq[HD * DD], g_Wk[HD * DD], g_Wv[HD * DD];
__device__ __align__(256) __half g_Wo[DD * HD];
__device__ __align__(256) __half g_w1[DD * DD], g_w2[DD * DD];
__device__ int g_pad[NTOK];
__device__ int g_byte_mode;

// ---------------- mask sniff + decode ----------------
__global__ void detect_mask_kernel(const unsigned char* m) {
    __shared__ int any;
    if (threadIdx.x == 0) any = 0;
    __syncthreads();
    int local = 0;
    for (int i = threadIdx.x; i < NTOK / 4; i += blockDim.x)
        if (m[4 * i + 1]) local = 1;
    if (local) atomicOr(&any, 1);
    __syncthreads();
    if (threadIdx.x == 0) g_byte_mode = any;
}
__global__ void decode_mask_kernel(const void* m) {
    int i = blockIdx.x * blockDim.x + threadIdx.x;
    if (i >= NTOK) return;
    g_pad[i] = g_byte_mode ? (((const unsigned char*)m)[i] != 0)
                           : (((const int*)m)[i] != 0);
}

// ---------------- PE add for Q, K, V in one launch (grid.y selects) ----------------
__global__ void add_pe_all(const float4* __restrict__ Q, const float4* __restrict__ K,
                           const float4* __restrict__ V, const float* __restrict__ pe,
                           float4* __restrict__ QpF, __half2* __restrict__ QpH,
                           __half2* __restrict__ KpH, __half2* __restrict__ VpH) {
    int i = blockIdx.x * blockDim.x + threadIdx.x;   // over NTOK*DD/4
    if (i >= NTOK * DD / 4) return;
    int y = blockIdx.y;
    const float4* in = (y == 0) ? Q : (y == 1) ? K : V;
    __half2* outH = (y == 0) ? QpH : (y == 1) ? KpH : VpH;
    int d4 = i & 63;
    int l = (i >> 6) & (LL - 1);
    float4 v = in[i];
    float4 p = *(const float4*)(pe + l * DD + d4 * 4);
    v.x += p.x; v.y += p.y; v.z += p.z; v.w += p.w;
    if (y == 0) QpF[i] = v;
    outH[2 * i] = __floats2half2_rn(v.x, v.y);
    outH[2 * i + 1] = __floats2half2_rn(v.z, v.w);
}

// ---------------- all weight conversions in one launch (grid.y = 0..5) ----------------
__global__ void wconv_all(const float* __restrict__ Wq, const float* __restrict__ Wk,
                          const float* __restrict__ Wv, const float* __restrict__ Wo,
                          const float* __restrict__ w1, const float* __restrict__ w2,
                          __half* __restrict__ dWq, __half* __restrict__ dWk,
                          __half* __restrict__ dWv, __half* __restrict__ dWo,
                          __half* __restrict__ dw1, __half* __restrict__ dw2) {
    int i = blockIdx.x * blockDim.x + threadIdx.x;
    int y = blockIdx.y;
    if (y < 3) {
        // (DD, HD) -> [n][k]: dst[c*DD + r] = src[r*HD + c]
        if (i >= DD * HD) return;
        const float* s = (y == 0) ? Wq : (y == 1) ? Wk : Wv;
        __half* d = (y == 0) ? dWq : (y == 1) ? dWk : dWv;
        int c = i >> 8, r = i & 255;
        d[i] = __float2half_rn(s[r * HD + c]);
    } else if (y == 3) {
        // (HD, DD) -> dst[c*HD + r] = src[r*DD + c]
        if (i >= HD * DD) return;
        int c = i >> 10, r = i & 1023;
        dWo[i] = __float2half_rn(Wo[r * DD + c]);
    } else {
        if (i >= DD * DD) return;
        const float* s = (y == 4) ? w1 : w2;
        __half* d = (y == 4) ? dw1 : dw2;
        d[i] = __float2half_rn(s[i]);
    }
}

// ---------------- Vsum[bh][d] = sum_l Vt[bh][d][l] (warp per row) ----------------
__global__ void vsum_kernel(const __half2* __restrict__ Vt, float* __restrict__ Vs) {
    int row = blockIdx.x * 8 + (threadIdx.x >> 5);   // over BH*DD = 32768 rows
    int lane = threadIdx.x & 31;
    const __half2* p = Vt + (size_t)row * (LL / 2);
    float s = 0.0f;
#pragma unroll
    for (int i = 0; i < 8; i++) {
        float2 v = __half22float2(p[i * 32 + lane]);
        s += v.x + v.y;
    }
#pragma unroll
    for (int off = 16; off > 0; off >>= 1) s += __shfl_xor_sync(0xFFFFFFFF, s, off);
    if (lane == 0) Vs[row] = s;
}

// ---------------- asm helpers ----------------
__device__ __forceinline__ uint32_t smem_u32(const void* p) {
    uint32_t a;
    asm("{ .reg .u64 t; cvta.to.shared.u64 t, %1; cvt.u32.u64 %0, t; }" : "=r"(a) : "l"(p));
    return a;
}
__device__ __forceinline__ void ldsm4(uint32_t& r0, uint32_t& r1, uint32_t& r2, uint32_t& r3,
                                      uint32_t addr) {
    asm volatile("ldmatrix.sync.aligned.m8n8.x4.shared.b16 {%0,%1,%2,%3}, [%4];"
                 : "=r"(r0), "=r"(r1), "=r"(r2), "=r"(r3) : "r"(addr));
}
__device__ __forceinline__ void mma16816(float* c, uint32_t a0, uint32_t a1, uint32_t a2,
                                         uint32_t a3, uint32_t b0, uint32_t b1) {
    asm volatile(
        "mma.sync.aligned.m16n8k16.row.col.f32.f16.f16.f32 "
        "{%0,%1,%2,%3}, {%4,%5,%6,%7}, {%8,%9}, {%0,%1,%2,%3};"
        : "+f"(c[0]), "+f"(c[1]), "+f"(c[2]), "+f"(c[3])
        : "r"(a0), "r"(a1), "r"(a2), "r"(a3), "r"(b0), "r"(b1));
}
__device__ __forceinline__ uint32_t packh2(float a, float b) {
    __half2 h = __floats2half2_rn(a, b);
    return *(uint32_t*)&h;
}

// ---------------- fp16 mma.sync GEMM, 3-stage cp.async pipeline ----------------
#define MT 128
#define NT 128
#define KC 64
#define STG 32768          // A 16K + B 16K per stage
#define NSTG 3

#define MODE_PLAIN 0
#define MODE_HEADSPLIT 1
#define MODE_VT 2

__global__ void __launch_bounds__(256, 2)
gemm_h(const __half* __restrict__ A, const __half* __restrict__ B,
       float* __restrict__ outF, __half* __restrict__ outH, const float* __restrict__ bias,
       int K, long long aBatch, long long bBatch, long long cBatch, int ldc,
       int mode, float alpha, int doRelu,
       const __half* __restrict__ A2, __half* __restrict__ outH2) {
    extern __shared__ __align__(128) char smem[];

    const int bz = blockIdx.z;
    const int bm0 = blockIdx.y * MT;
    const int bn0 = blockIdx.x * NT;

    const int tid = threadIdx.x;
    const int wid = tid >> 5;
    const int l = tid & 31;
    const int wr = wid & 3;
    const int wc = wid >> 2;

    // z=1 with A2 set selects second (A, out) pair (Q/K projection merge)
    const __half* Ab = (A2 && bz == 1) ? A2 : A;
    __half* outHb = (A2 && bz == 1) ? outH2 : outH;
    const __half* gA = Ab + (A2 ? 0 : bz * aBatch) + (long long)bm0 * K;
    const __half* gB = B + bz * bBatch + (long long)bn0 * K;
    const uint32_t sbase = smem_u32(smem);

    float c[2][8][4];
#pragma unroll
    for (int i = 0; i < 2; i++)
#pragma unroll
        for (int j = 0; j < 8; j++)
#pragma unroll
            for (int e = 0; e < 4; e++) c[i][j][e] = 0.0f;

    const int mrow = wr * 32 + ((l >> 3) & 1) * 8 + (l & 7);
    const int kpA = (l >> 4) & 1;
    const int nrow = wc * 64 + ((l >> 4) & 1) * 8 + (l & 7);
    const int kpB = (l >> 3) & 1;

    auto stage_fn = [&](int buf, int k0) {
        char* sA = smem + buf * STG;
        char* sB = sA + 16384;
#pragma unroll
        for (int it = 0; it < 4; it++) {
            int idx = tid + it * 256;
            int r = idx >> 3, ch = idx & 7;
            __pipeline_memcpy_async(sA + r * 128 + ((ch ^ (r & 7)) << 4),
                                    gA + (long long)r * K + k0 + ch * 8, 16);
        }
#pragma unroll
        for (int it = 0; it < 4; it++) {
            int idx = tid + it * 256;
            int r = idx >> 3, ch = idx & 7;
            __pipeline_memcpy_async(sB + r * 128 + ((ch ^ (r & 7)) << 4),
                                    gB + (long long)r * K + k0 + ch * 8, 16);
        }
    };

    const int nt = K / KC;
    stage_fn(0, 0);
    __pipeline_commit();
    if (nt > 1) { stage_fn(1, KC); __pipeline_commit(); }

    for (int cc = 0; cc < nt; cc++) {
        if (cc < nt - 1) __pipeline_wait_prior(1);
        else __pipeline_wait_prior(0);
        __syncthreads();
        if (cc + 2 < nt) {                       // depth-2 prefetch into 3rd buffer
            stage_fn((cc + 2) % NSTG, (cc + 2) * KC);
            __pipeline_commit();
        }

        const int buf = cc % NSTG;
        const uint32_t sA = sbase + buf * STG;
        const uint32_t sB = sA + 16384;
#pragma unroll
        for (int ks = 0; ks < 4; ks++) {
            uint32_t a[2][4];
#pragma unroll
            for (int i = 0; i < 2; i++) {
                int row = mrow + i * 16;
                ldsm4(a[i][0], a[i][1], a[i][2], a[i][3],
                      sA + row * 128 + (((2 * ks + kpA) ^ (row & 7)) << 4));
            }
            uint32_t b[4][4];
#pragma unroll
            for (int g = 0; g < 4; g++) {
                int row = nrow + g * 16;
                ldsm4(b[g][0], b[g][1], b[g][2], b[g][3],
                      sB + row * 128 + (((2 * ks + kpB) ^ (row & 7)) << 4));
            }
#pragma unroll
            for (int i = 0; i < 2; i++)
#pragma unroll
                for (int j = 0; j < 8; j++) {
                    int g = j >> 1, h2 = (j & 1) << 1;
                    mma16816(c[i][j], a[i][0], a[i][1], a[i][2], a[i][3],
                             b[g][h2], b[g][h2 + 1]);
                }
        }
    }

    const int mb = bm0 + wr * 32 + (l >> 2);
    const int nb = bn0 + wc * 64 + (l & 3) * 2;
    auto emit2 = [&](int m, int n, float v0, float v1) {
        v0 *= alpha; v1 *= alpha;
        if (bias) { v0 += bias[n]; v1 += bias[n + 1]; }
        if (doRelu) { v0 = fmaxf(v0, 0.0f); v1 = fmaxf(v1, 0.0f); }
        size_t oidx;
        if (mode == MODE_PLAIN) {
            oidx = (size_t)bz * cBatch + (size_t)m * ldc + n;
        } else if (mode == MODE_HEADSPLIT) {
            int b_ = m >> 9, l_ = m & 511, h_ = n >> 8, d_ = n & 255;
            oidx = ((size_t)((b_ * HH + h_) * LL + l_)) * DD + d_;
        } else {  // MODE_VT: m over HD (h,d), n over NTOK (b,l) -> Vt[(b*H+h)*D+d][l]
            int h_ = m >> 8, d_ = m & 255, b_ = n >> 9, l_ = n & 511;
            oidx = ((size_t)((b_ * HH + h_) * DD + d_)) * LL + l_;
        }
        if (outF) *(float2*)(outF + oidx) = make_float2(v0, v1);
        else *(__half2*)(outHb + oidx) = __floats2half2_rn(v0, v1);
    };
#pragma unroll
    for (int i = 0; i < 2; i++) {
        int m = mb + i * 16;
#pragma unroll
        for (int j = 0; j < 8; j++) {
            int n = nb + j * 8;
            emit2(m, n, c[i][j][0], c[i][j][1]);
            emit2(m + 8, n, c[i][j][2], c[i][j][3]);
        }
    }
}

// ---------------- fused flash attention ----------------
#define FSM_K 65536
#define FSM_V 131072
#define FSM_TOT 196608

__global__ void __launch_bounds__(256, 1)
flash_attn(const __half* __restrict__ Qh, const __half* __restrict__ Kh,
           const __half* __restrict__ Vt, const float* __restrict__ Vsum,
           __half* __restrict__ Om) {
    extern __shared__ __align__(128) char smem[];
    const int qt = blockIdx.x;
    const int bh = blockIdx.y;
    const int tid = threadIdx.x;
    const int w = tid >> 5;
    const int l = tid & 31;

    const __half* gQ = Qh + ((size_t)bh * LL + qt * 128) * DD;
    const __half* gK = Kh + (size_t)bh * LL * DD;
    const __half* gV = Vt + (size_t)bh * DD * LL;
    char* smQ = smem;
    char* smK = smem + FSM_K;
    char* smV = smem + FSM_V;
    const uint32_t sQ = smem_u32(smem);
    const uint32_t sK = sQ + FSM_K;
    const uint32_t sV = sQ + FSM_V;

#pragma unroll
    for (int cq = 0; cq < 4; cq++)
#pragma unroll
        for (int it = 0; it < 4; it++) {
            int idx = tid + it * 256;
            int r = idx >> 3, ch = idx & 7;
            __pipeline_memcpy_async(smQ + cq * 16384 + r * 128 + ((ch ^ (r & 7)) << 4),
                                    gQ + (size_t)r * DD + cq * 64 + ch * 8, 16);
        }
    __pipeline_commit();

    float o[32][4];
#pragma unroll
    for (int j = 0; j < 32; j++)
#pragma unroll
        for (int e = 0; e < 4; e++) o[j][e] = 0.0f;
    float mrun0 = -INFINITY, mrun1 = -INFINITY;
    float lrun0 = 0.0f, lrun1 = 0.0f;

    const int r0l = w * 16 + (l >> 2);
    const int r1l = r0l + 8;
    const int arow = w * 16 + ((l >> 3) & 1) * 8 + (l & 7);
    const int kpA = (l >> 4) & 1;
    const int brow = ((l >> 4) & 1) * 8 + (l & 7);
    const int kpB = (l >> 3) & 1;
    const float alpha = (float)(1.0 / (16.0 + 1e-6));

    for (int kt = 0; kt <= qt; kt++) {
#pragma unroll
        for (int ck = 0; ck < 4; ck++) {
#pragma unroll
            for (int it = 0; it < 4; it++) {
                int idx = tid + it * 256;
                int r = idx >> 3, ch = idx & 7;
                __pipeline_memcpy_async(smK + ck * 16384 + r * 128 + ((ch ^ (r & 7)) << 4),
                                        gK + (size_t)(kt * 128 + r) * DD + ck * 64 + ch * 8, 16);
            }
            __pipeline_commit();
        }
#pragma unroll
        for (int cv = 0; cv < 2; cv++) {
#pragma unroll
            for (int it = 0; it < 8; it++) {
                int idx = tid + it * 256;
                int r = idx >> 3, ch = idx & 7;
                __pipeline_memcpy_async(smV + cv * 32768 + r * 128 + ((ch ^ (r & 7)) << 4),
                                        gV + (size_t)r * LL + kt * 128 + cv * 64 + ch * 8, 16);
            }
            __pipeline_commit();
        }

        float c[16][4];
#pragma unroll
        for (int j = 0; j < 16; j++)
#pragma unroll
            for (int e = 0; e < 4; e++) c[j][e] = 0.0f;

#pragma unroll
        for (int ck = 0; ck < 4; ck++) {
            __pipeline_wait_prior(5 - ck);
            __syncthreads();
#pragma unroll
            for (int ks = 0; ks < 4; ks++) {
                uint32_t a0, a1, a2, a3;
                ldsm4(a0, a1, a2, a3,
                      sQ + ck * 16384 + arow * 128 + (((2 * ks + kpA) ^ (arow & 7)) << 4));
#pragma unroll
                for (int g = 0; g < 8; g++) {
                    int nr = g * 16 + brow;
                    uint32_t b0, b1, b2, b3;
                    ldsm4(b0, b1, b2, b3,
                          sK + ck * 16384 + nr * 128 + (((2 * ks + kpB) ^ (nr & 7)) << 4));
                    mma16816(c[2 * g], a0, a1, a2, a3, b0, b1);
                    mma16816(c[2 * g + 1], a0, a1, a2, a3, b2, b3);
                }
            }
        }

        if (kt == qt) {
#pragma unroll
            for (int j = 0; j < 16; j++) {
                int nb = j * 8 + (l & 3) * 2;
                c[j][0] = (nb     <= r0l) ? c[j][0] * alpha : -INFINITY;
                c[j][1] = (nb + 1 <= r0l) ? c[j][1] * alpha : -INFINITY;
                c[j][2] = (nb     <= r1l) ? c[j][2] * alpha : -INFINITY;
                c[j][3] = (nb + 1 <= r1l) ? c[j][3] * alpha : -INFINITY;
            }
        } else {
#pragma unroll
            for (int j = 0; j < 16; j++)
#pragma unroll
                for (int e = 0; e < 4; e++) c[j][e] *= alpha;
        }

        float mn0 = mrun0, mn1 = mrun1;
#pragma unroll
        for (int j = 0; j < 16; j++) {
            mn0 = fmaxf(mn0, fmaxf(c[j][0], c[j][1]));
            mn1 = fmaxf(mn1, fmaxf(c[j][2], c[j][3]));
        }
        mn0 = fmaxf(mn0, __shfl_xor_sync(0xFFFFFFFF, mn0, 1));
        mn0 = fmaxf(mn0, __shfl_xor_sync(0xFFFFFFFF, mn0, 2));
        mn1 = fmaxf(mn1, __shfl_xor_sync(0xFFFFFFFF, mn1, 1));
        mn1 = fmaxf(mn1, __shfl_xor_sync(0xFFFFFFFF, mn1, 2));
        float corr0 = __expf(mrun0 - mn0);
        float corr1 = __expf(mrun1 - mn1);
        mrun0 = mn0; mrun1 = mn1;

        float rs0 = 0.0f, rs1 = 0.0f;
        uint32_t pk[16][2];
#pragma unroll
        for (int j = 0; j < 16; j++) {
            float p0 = __expf(c[j][0] - mn0);
            float p1 = __expf(c[j][1] - mn0);
            float p2 = __expf(c[j][2] - mn1);
            float p3 = __expf(c[j][3] - mn1);
            rs0 += p0 + p1; rs1 += p2 + p3;
            pk[j][0] = packh2(p0, p1);
            pk[j][1] = packh2(p2, p3);
        }
        rs0 += __shfl_xor_sync(0xFFFFFFFF, rs0, 1);
        rs0 += __shfl_xor_sync(0xFFFFFFFF, rs0, 2);
        rs1 += __shfl_xor_sync(0xFFFFFFFF, rs1, 1);
        rs1 += __shfl_xor_sync(0xFFFFFFFF, rs1, 2);
        lrun0 = lrun0 * corr0 + rs0;
        lrun1 = lrun1 * corr1 + rs1;
#pragma unroll
        for (int j = 0; j < 32; j++) {
            o[j][0] *= corr0; o[j][1] *= corr0;
            o[j][2] *= corr1; o[j][3] *= corr1;
        }

#pragma unroll
        for (int hv = 0; hv < 2; hv++) {
            __pipeline_wait_prior(1 - hv);
            __syncthreads();
#pragma unroll
            for (int k2 = 0; k2 < 4; k2++) {
                int kk = hv * 4 + k2;
                uint32_t a0 = pk[2 * kk][0], a1 = pk[2 * kk][1];
                uint32_t a2 = pk[2 * kk + 1][0], a3 = pk[2 * kk + 1][1];
#pragma unroll
                for (int g = 0; g < 16; g++) {
                    int nr = g * 16 + brow;
                    uint32_t b0, b1, b2, b3;
                    ldsm4(b0, b1, b2, b3,
                          sV + hv * 32768 + nr * 128 + (((2 * k2 + kpB) ^ (nr & 7)) << 4));
                    mma16816(o[2 * g], a0, a1, a2, a3, b0, b1);
                    mma16816(o[2 * g + 1], a0, a1, a2, a3, b2, b3);
                }
            }
        }
        __syncthreads();
    }

    float inv0 = 1.0f / lrun0, inv1 = 1.0f / lrun1;
    int q0 = qt * 128 + r0l, q1 = q0 + 8;
    int b_ = bh >> 2, h_ = bh & 3;
    int pad0 = g_pad[(b_ << 9) + q0];
    int pad1 = g_pad[(b_ << 9) + q1];
    const float i512 = 1.0f / 512.0f;
    const float* vs = Vsum + bh * DD;
    size_t base0 = (size_t)(b_ * 512 + q0) * HD + h_ * DD;
    size_t base1 = (size_t)(b_ * 512 + q1) * HD + h_ * DD;
#pragma unroll
    for (int j = 0; j < 32; j++) {
        int d = j * 8 + (l & 3) * 2;
        float v0 = o[j][0] * inv0, v1 = o[j][1] * inv0;
        float v2 = o[j][2] * inv1, v3 = o[j][3] * inv1;
        if (pad0) { v0 = vs[d] * i512; v1 = vs[d + 1] * i512; }
        if (pad1) { v2 = vs[d] * i512; v3 = vs[d + 1] * i512; }
        *(__half2*)(Om + base0 + d) = __floats2half2_rn(v0, v1);
        *(__half2*)(Om + base1 + d) = __floats2half2_rn(v2, v3);
    }
}

// ---------------- residual + layernorm: warp per row, zero barriers ----------------
__global__ void __launch_bounds__(256)
ln_residual_kernel(const float* __restrict__ Ain, const float* __restrict__ Bin,
                   const float* __restrict__ gamma, const float* __restrict__ beta,
                   float* __restrict__ outF, __half* __restrict__ outH) {
    int row = blockIdx.x * 8 + (threadIdx.x >> 5);
    int l = threadIdx.x & 31;
    size_t base = (size_t)row * DD + l * 8;

    float4 a0 = *(const float4*)(Ain + base);
    float4 a1 = *(const float4*)(Ain + base + 4);
    float4 b0 = *(const float4*)(Bin + base);
    float4 b1 = *(const float4*)(Bin + base + 4);
    float x[8] = {a0.x + b0.x, a0.y + b0.y, a0.z + b0.z, a0.w + b0.w,
                  a1.x + b1.x, a1.y + b1.y, a1.z + b1.z, a1.w + b1.w};

    float s = 0.0f;
#pragma unroll
    for (int e = 0; e < 8; e++) s += x[e];
#pragma unroll
    for (int off = 16; off > 0; off >>= 1) s += __shfl_xor_sync(0xFFFFFFFF, s, off);
    float mu = s * (1.0f / DD);

    float sq = 0.0f;
#pragma unroll
    for (int e = 0; e < 8; e++) { float d = x[e] - mu; sq += d * d; }
#pragma unroll
    for (int off = 16; off > 0; off >>= 1) sq += __shfl_xor_sync(0xFFFFFFFF, sq, off);
    float rstd = rsqrtf(sq * (1.0f / DD) + 1e-5f);

    float4 g0 = *(const float4*)(gamma + l * 8);
    float4 g1 = *(const float4*)(gamma + l * 8 + 4);
    float4 be0 = *(const float4*)(beta + l * 8);
    float4 be1 = *(const float4*)(beta + l * 8 + 4);
    float y[8];
    y[0] = (x[0] - mu) * rstd * g0.x + be0.x;
    y[1] = (x[1] - mu) * rstd * g0.y + be0.y;
    y[2] = (x[2] - mu) * rstd * g0.z + be0.z;
    y[3] = (x[3] - mu) * rstd * g0.w + be0.w;
    y[4] = (x[4] - mu) * rstd * g1.x + be1.x;
    y[5] = (x[5] - mu) * rstd * g1.y + be1.y;
    y[6] = (x[6] - mu) * rstd * g1.z + be1.z;
    y[7] = (x[7] - mu) * rstd * g1.w + be1.w;

    if (outF) {
        *(float4*)(outF + base) = make_float4(y[0], y[1], y[2], y[3]);
        *(float4*)(outF + base + 4) = make_float4(y[4], y[5], y[6], y[7]);
    }
    if (outH) {
        __half2 h[4] = {__floats2half2_rn(y[0], y[1]), __floats2half2_rn(y[2], y[3]),
                        __floats2half2_rn(y[4], y[5]), __floats2half2_rn(y[6], y[7])};
        *(float4*)(outH + base) = *(float4*)h;
    }
}

// ---------------- host orchestration ----------------
#define SYM(p, s) void* p; cudaGetSymbolAddress(&p, s)

extern "C" void kernel_launch(void* const* d_in, const int* in_sizes, int n_in,
                              void* d_out, int out_size) {
    (void)in_sizes; (void)n_in; (void)out_size;
    const float* Q    = (const float*)d_in[0];
    const float* K    = (const float*)d_in[1];
    const float* V    = (const float*)d_in[2];
    const void*  mask = d_in[3];
    const float* pe   = (const float*)d_in[4];
    const float* W_q  = (const float*)d_in[5];
    const float* W_k  = (const float*)d_in[6];
    const float* W_v  = (const float*)d_in[7];
    const float* W_o  = (const float*)d_in[8];
    const float* w1   = (const float*)d_in[9];
    const float* b1   = (const float*)d_in[10];
    const float* w2   = (const float*)d_in[11];
    const float* b2   = (const float*)d_in[12];
    const float* gamma = (const float*)d_in[13];
    const float* beta  = (const float*)d_in[14];
    float* out = (float*)d_out;

    SYM(pQpF, g_QpF);
    SYM(pQpH, g_QpH); SYM(pKpH, g_KpH); SYM(pVpH, g_VpH);
    SYM(pQhH, g_QhH); SYM(pKhH, g_KhH); SYM(pVtH, g_VtH);
    SYM(pVsum, g_Vsum); SYM(pVmH, g_VmH);
    SYM(pT1, g_T1); SYM(pXF, g_XF); SYM(pXH, g_XH); SYM(pYH, g_YH); SYM(pZF, g_ZF);
    SYM(pWq, g_Wq); SYM(pWk, g_Wk); SYM(pWv, g_Wv); SYM(pWo, g_Wo);
    SYM(pw1, g_w1); SYM(pw2, g_w2);

    cudaFuncSetAttribute(gemm_h, cudaFuncAttributeMaxDynamicSharedMemorySize, NSTG * STG);
    cudaFuncSetAttribute(flash_attn, cudaFuncAttributeMaxDynamicSharedMemorySize, FSM_TOT);

    typedef __half hf;

    // 1) mask
    detect_mask_kernel<<<1, 256>>>((const unsigned char*)mask);
    decode_mask_kernel<<<(NTOK + 255) / 256, 256>>>(mask);

    // 2) PE add + fp16 convert (Q, K, V in one launch)
    {
        int q4 = NTOK * DD / 4, qb = (q4 + 255) / 256;
        add_pe_all<<<dim3(qb, 3), 256>>>((const float4*)Q, (const float4*)K,
                                         (const float4*)V, pe, (float4*)pQpF,
                                         (__half2*)pQpH, (__half2*)pKpH, (__half2*)pVpH);
    }

    // 3) all weights to fp16 [n][k] in one launch
    wconv_all<<<dim3(1024, 6), 256>>>(W_q, W_k, W_v, W_o, w1, w2,
                                      (hf*)pWq, (hf*)pWk, (hf*)pWv, (hf*)pWo,
                                      (hf*)pw1, (hf*)pw2);

    // 4a) Q + K projections, one launch (grid.z: 0 -> Q, 1 -> K)
    {
        dim3 g(HD / NT, NTOK / MT, 2);
        gemm_h<<<g, 256, NSTG * STG>>>((hf*)pQpH, (hf*)pWq, nullptr, (hf*)pQhH, nullptr,
                                       DD, 0, 0, 0, 0, MODE_HEADSPLIT, 1.0f, 0,
                                       (hf*)pKpH, (hf*)pKhH);
        // note: B operand differs per z? No — B must match. Wq vs Wk differ, handled below.
    }
    // The B operand differs between Q and K; the merged launch above used Wq for both.
    // Correctness fix: run K separately with Wk (the z=1 pass above is overwritten).
    {
        dim3 g(HD / NT, NTOK / MT, 1);
        gemm_h<<<g, 256, NSTG * STG>>>((hf*)pKpH, (hf*)pWk, nullptr, (hf*)pKhH, nullptr,
                                       DD, 0, 0, 0, 0, MODE_HEADSPLIT, 1.0f, 0,
                                       nullptr, nullptr);
    }

    // 4b) V projection, transposed output: A = Wv (M=1024), B = Vp (N=16384)
    {
        dim3 g(NTOK / NT, HD / MT, 1);
        gemm_h<<<g, 256, NSTG * STG>>>((hf*)pWv, (hf*)pVpH, nullptr, (hf*)pVtH, nullptr,
                                       DD, 0, 0, 0, 0, MODE_VT, 1.0f, 0,
                                       nullptr, nullptr);
    }

    // 5) Vsum from Vt (warp per row)
    vsum_kernel<<<BH * DD / 8, 256>>>((const __half2*)pVtH, (float*)pVsum);

    // 6) fused flash attention -> merged (b, l, h*d)
    {
        dim3 g(LL / 128, BH);
        flash_attn<<<g, 256, FSM_TOT>>>((hf*)pQhH, (hf*)pKhH, (hf*)pVtH,
                                        (float*)pVsum, (hf*)pVmH);
    }

    // 7) output projection: T1 = Vm @ W_o  (M=16384, N=256, K=1024)
    {
        dim3 g(DD / NT, NTOK / MT, 1);
        gemm_h<<<g, 256, NSTG * STG>>>((hf*)pVmH, (hf*)pWo, (float*)pT1, nullptr, nullptr,
                                       HD, 0, 0, 0, DD, MODE_PLAIN, 1.0f, 0,
                                       nullptr, nullptr);
    }

    // 8) X = LN(Qp + T1)
    ln_residual_kernel<<<NTOK / 8, 256>>>((float*)pQpF, (float*)pT1, gamma, beta,
                                          (float*)pXF, (hf*)pXH);

    // 9) FFN: Y = relu(X @ w1^T + b1); Z = Y @ w2^T + b2
    {
        dim3 g(DD / NT, NTOK / MT, 1);
        gemm_h<<<g, 256, NSTG * STG>>>((hf*)pXH, (hf*)pw1, nullptr, (hf*)pYH, b1,
                                       DD, 0, 0, 0, DD, MODE_PLAIN, 1.0f, 1,
                                       nullptr, nullptr);
        gemm_h<<<g, 256, NSTG * STG>>>((hf*)pYH, (hf*)pw2, (float*)pZF, nullptr, b2,
                                       DD, 0, 0, 0, DD, MODE_PLAIN, 1.0f, 0,
                                       nullptr, nullptr);
    }

    // 10) out = LN(Z + X)
    ln_residual_kernel<<<NTOK / 8, 256>>>((float*)pZF, (float*)pXF, gamma, beta, out, nullptr);
}

// round 10
// speedup vs baseline: 4.9990x; 1.1084x over previous
#include <cuda_runtime.h>
#include <cuda_fp16.h>
#include <cuda_pipeline.h>
#include <cstdint>

// Problem dims: B=32, L=512, D=256, H=4
#define BB 32
#define LL 512
#define DD 256
#define HH 4
#define NTOK (BB * LL)      // 16384
#define BH (BB * HH)        // 128
#define HD (HH * DD)        // 1024

// ---------------- device scratch (.bss, allocation-free) ----------------
__device__ __align__(256) float g_QpF[NTOK * DD];
__device__ __align__(256) __half g_QpH[NTOK * DD], g_KpH[NTOK * DD], g_VpH[NTOK * DD];
__device__ __align__(256) __half g_QhH[BH * LL * DD];     // (bh, l, d)
__device__ __align__(256) __half g_KhH[BH * LL * DD];     // (bh, l, d)
__device__ __align__(256) __half g_VtH[BH * DD * LL];     // (bh, d, l)
__device__ __align__(256) float g_Vsum[BH * DD];
__device__ __align__(256) __half g_VmH[NTOK * HD];        // (b, l, h*d)
__device__ __align__(256) float g_T1[NTOK * DD];
__device__ __align__(256) float g_XF[NTOK * DD];
__device__ __align__(256) __half g_XH[NTOK * DD];
__device__ __align__(256) __half g_YH[NTOK * DD];
__device__ __align__(256) float g_ZF[NTOK * DD];
// weights as B operand layout: [n][k] (k contiguous)
__device__ __align__(256) __half g_Wq[HD * DD], g_Wk[HD * DD], g_Wv[HD * DD];
__device__ __align__(256) __half g_Wo[DD * HD];
__device__ __align__(256) __half g_w1[DD * DD], g_w2[DD * DD];
__device__ int g_pad[NTOK];
__device__ int g_byte_mode;

// ---------------- mask sniff + decode ----------------
__global__ void detect_mask_kernel(const unsigned char* m) {
    __shared__ int any;
    if (threadIdx.x == 0) any = 0;
    __syncthreads();
    int local = 0;
    for (int i = threadIdx.x; i < NTOK / 4; i += blockDim.x)
        if (m[4 * i + 1]) local = 1;
    if (local) atomicOr(&any, 1);
    __syncthreads();
    if (threadIdx.x == 0) g_byte_mode = any;
}
__global__ void decode_mask_kernel(const void* m) {
    int i = blockIdx.x * blockDim.x + threadIdx.x;
    if (i >= NTOK) return;
    g_pad[i] = g_byte_mode ? (((const unsigned char*)m)[i] != 0)
                           : (((const int*)m)[i] != 0);
}

// ---------------- PE add for Q, K, V in one launch (grid.y selects) ----------------
__global__ void add_pe_all(const float4* __restrict__ Q, const float4* __restrict__ K,
                           const float4* __restrict__ V, const float* __restrict__ pe,
                           float4* __restrict__ QpF, __half2* __restrict__ QpH,
                           __half2* __restrict__ KpH, __half2* __restrict__ VpH) {
    int i = blockIdx.x * blockDim.x + threadIdx.x;   // over NTOK*DD/4
    if (i >= NTOK * DD / 4) return;
    int y = blockIdx.y;
    const float4* in = (y == 0) ? Q : (y == 1) ? K : V;
    __half2* outH = (y == 0) ? QpH : (y == 1) ? KpH : VpH;
    int d4 = i & 63;
    int l = (i >> 6) & (LL - 1);
    float4 v = in[i];
    float4 p = *(const float4*)(pe + l * DD + d4 * 4);
    v.x += p.x; v.y += p.y; v.z += p.z; v.w += p.w;
    if (y == 0) QpF[i] = v;
    outH[2 * i] = __floats2half2_rn(v.x, v.y);
    outH[2 * i + 1] = __floats2half2_rn(v.z, v.w);
}

// ---------------- weight conversions: tiled transposes, coalesced ----------------
// grid.y 0..3: transpose jobs. y<3: src (DD,HD) rowmajor -> dst[c*DD + r]=src[r*HD + c]
//              y==3: src (HD,DD) -> dst[c*HD + r]=src[r*DD + c]
// Each block does a 32x32 tile via smem.
__global__ void wconv_trans_tiled(const float* __restrict__ Wq, const float* __restrict__ Wk,
                                  const float* __restrict__ Wv, const float* __restrict__ Wo,
                                  __half* __restrict__ dWq, __half* __restrict__ dWk,
                                  __half* __restrict__ dWv, __half* __restrict__ dWo) {
    __shared__ __half t[32][33];
    int y = blockIdx.y;
    const float* src = (y == 0) ? Wq : (y == 1) ? Wk : (y == 2) ? Wv : Wo;
    __half* dst = (y == 0) ? dWq : (y == 1) ? dWk : (y == 2) ? dWv : dWo;
    int R = (y < 3) ? DD : HD;     // src rows
    int C = (y < 3) ? HD : DD;     // src cols
    // tile index: blockIdx.x over (R/32)*(C/32)
    int tilesC = C >> 5;
    int tr = (blockIdx.x / tilesC) << 5;   // src row base
    int tc = (blockIdx.x % tilesC) << 5;   // src col base
    int tx = threadIdx.x & 31, ty = threadIdx.x >> 5;   // 32 x 8
#pragma unroll
    for (int s = 0; s < 32; s += 8)
        t[ty + s][tx] = __float2half_rn(src[(size_t)(tr + ty + s) * C + tc + tx]);
    __syncthreads();
    // dst[(tc+row)*R + tr+col] : coalesced over tx
#pragma unroll
    for (int s = 0; s < 32; s += 8)
        dst[(size_t)(tc + ty + s) * R + tr + tx] = t[tx][ty + s];
}
// direct fp32->fp16 for w1, w2 (no transpose), vectorized
__global__ void wconv_direct2(const float4* __restrict__ w1, const float4* __restrict__ w2,
                              __half2* __restrict__ dw1, __half2* __restrict__ dw2) {
    int i = blockIdx.x * blockDim.x + threadIdx.x;   // over DD*DD/4
    if (i >= DD * DD / 4) return;
    const float4* s = blockIdx.y ? w2 : w1;
    __half2* d = blockIdx.y ? dw2 : dw1;
    float4 v = s[i];
    d[2 * i] = __floats2half2_rn(v.x, v.y);
    d[2 * i + 1] = __floats2half2_rn(v.z, v.w);
}

// ---------------- Vsum[bh][d] = sum_l Vt[bh][d][l] (warp per row) ----------------
__global__ void vsum_kernel(const __half2* __restrict__ Vt, float* __restrict__ Vs) {
    int row = blockIdx.x * 8 + (threadIdx.x >> 5);   // over BH*DD = 32768 rows
    int lane = threadIdx.x & 31;
    const __half2* p = Vt + (size_t)row * (LL / 2);
    float s = 0.0f;
#pragma unroll
    for (int i = 0; i < 8; i++) {
        float2 v = __half22float2(p[i * 32 + lane]);
        s += v.x + v.y;
    }
#pragma unroll
    for (int off = 16; off > 0; off >>= 1) s += __shfl_xor_sync(0xFFFFFFFF, s, off);
    if (lane == 0) Vs[row] = s;
}

// ---------------- asm helpers ----------------
__device__ __forceinline__ uint32_t smem_u32(const void* p) {
    uint32_t a;
    asm("{ .reg .u64 t; cvta.to.shared.u64 t, %1; cvt.u32.u64 %0, t; }" : "=r"(a) : "l"(p));
    return a;
}
__device__ __forceinline__ void ldsm4(uint32_t& r0, uint32_t& r1, uint32_t& r2, uint32_t& r3,
                                      uint32_t addr) {
    asm volatile("ldmatrix.sync.aligned.m8n8.x4.shared.b16 {%0,%1,%2,%3}, [%4];"
                 : "=r"(r0), "=r"(r1), "=r"(r2), "=r"(r3) : "r"(addr));
}
__device__ __forceinline__ void mma16816(float* c, uint32_t a0, uint32_t a1, uint32_t a2,
                                         uint32_t a3, uint32_t b0, uint32_t b1) {
    asm volatile(
        "mma.sync.aligned.m16n8k16.row.col.f32.f16.f16.f32 "
        "{%0,%1,%2,%3}, {%4,%5,%6,%7}, {%8,%9}, {%0,%1,%2,%3};"
        : "+f"(c[0]), "+f"(c[1]), "+f"(c[2]), "+f"(c[3])
        : "r"(a0), "r"(a1), "r"(a2), "r"(a3), "r"(b0), "r"(b1));
}
__device__ __forceinline__ uint32_t packh2(float a, float b) {
    __half2 h = __floats2half2_rn(a, b);
    return *(uint32_t*)&h;
}

// ---------------- fp16 mma.sync GEMM, 3-stage cp.async pipeline ----------------
#define MT 128
#define NT 128
#define KC 64
#define STG 32768          // A 16K + B 16K per stage
#define NSTG 3

#define MODE_PLAIN 0
#define MODE_HEADSPLIT 1
#define MODE_VT 2

__global__ void __launch_bounds__(256, 2)
gemm_h(const __half* __restrict__ A, const __half* __restrict__ B,
       float* __restrict__ outF, __half* __restrict__ outH, const float* __restrict__ bias,
       int K, long long aBatch, long long bBatch, long long cBatch, int ldc,
       int mode, float alpha, int doRelu,
       const __half* __restrict__ A2, const __half* __restrict__ B2,
       __half* __restrict__ outH2) {
    extern __shared__ __align__(128) char smem[];

    const int bz = blockIdx.z;
    const int bm0 = blockIdx.y * MT;
    const int bn0 = blockIdx.x * NT;

    const int tid = threadIdx.x;
    const int wid = tid >> 5;
    const int l = tid & 31;
    const int wr = wid & 3;
    const int wc = wid >> 2;

    // dual-problem merge: z=1 with A2 set selects second (A, B, out) triple
    const bool second = (A2 != nullptr) && (bz == 1);
    const __half* Ab = second ? A2 : A;
    const __half* Bb = second ? B2 : B;
    __half* outHb = second ? outH2 : outH;
    const __half* gA = Ab + (A2 ? 0 : bz * aBatch) + (long long)bm0 * K;
    const __half* gB = Bb + (A2 ? 0 : bz * bBatch) + (long long)bn0 * K;
    const uint32_t sbase = smem_u32(smem);

    float c[2][8][4];
#pragma unroll
    for (int i = 0; i < 2; i++)
#pragma unroll
        for (int j = 0; j < 8; j++)
#pragma unroll
            for (int e = 0; e < 4; e++) c[i][j][e] = 0.0f;

    const int mrow = wr * 32 + ((l >> 3) & 1) * 8 + (l & 7);
    const int kpA = (l >> 4) & 1;
    const int nrow = wc * 64 + ((l >> 4) & 1) * 8 + (l & 7);
    const int kpB = (l >> 3) & 1;

    auto stage_fn = [&](int buf, int k0) {
        char* sA = smem + buf * STG;
        char* sB = sA + 16384;
#pragma unroll
        for (int it = 0; it < 4; it++) {
            int idx = tid + it * 256;
            int r = idx >> 3, ch = idx & 7;
            __pipeline_memcpy_async(sA + r * 128 + ((ch ^ (r & 7)) << 4),
                                    gA + (long long)r * K + k0 + ch * 8, 16);
        }
#pragma unroll
        for (int it = 0; it < 4; it++) {
            int idx = tid + it * 256;
            int r = idx >> 3, ch = idx & 7;
            __pipeline_memcpy_async(sB + r * 128 + ((ch ^ (r & 7)) << 4),
                                    gB + (long long)r * K + k0 + ch * 8, 16);
        }
    };

    const int nt = K / KC;
    stage_fn(0, 0);
    __pipeline_commit();
    if (nt > 1) { stage_fn(1, KC); __pipeline_commit(); }

    for (int cc = 0; cc < nt; cc++) {
        if (cc < nt - 1) __pipeline_wait_prior(1);
        else __pipeline_wait_prior(0);
        __syncthreads();
        if (cc + 2 < nt) {                       // depth-2 prefetch into 3rd buffer
            stage_fn((cc + 2) % NSTG, (cc + 2) * KC);
            __pipeline_commit();
        }

        const int buf = cc % NSTG;
        const uint32_t sA = sbase + buf * STG;
        const uint32_t sB = sA + 16384;
#pragma unroll
        for (int ks = 0; ks < 4; ks++) {
            uint32_t a[2][4];
#pragma unroll
            for (int i = 0; i < 2; i++) {
                int row = mrow + i * 16;
                ldsm4(a[i][0], a[i][1], a[i][2], a[i][3],
                      sA + row * 128 + (((2 * ks + kpA) ^ (row & 7)) << 4));
            }
            uint32_t b[4][4];
#pragma unroll
            for (int g = 0; g < 4; g++) {
                int row = nrow + g * 16;
                ldsm4(b[g][0], b[g][1], b[g][2], b[g][3],
                      sB + row * 128 + (((2 * ks + kpB) ^ (row & 7)) << 4));
            }
#pragma unroll
            for (int i = 0; i < 2; i++)
#pragma unroll
                for (int j = 0; j < 8; j++) {
                    int g = j >> 1, h2 = (j & 1) << 1;
                    mma16816(c[i][j], a[i][0], a[i][1], a[i][2], a[i][3],
                             b[g][h2], b[g][h2 + 1]);
                }
        }
    }

    const int mb = bm0 + wr * 32 + (l >> 2);
    const int nb = bn0 + wc * 64 + (l & 3) * 2;
    auto emit2 = [&](int m, int n, float v0, float v1) {
        v0 *= alpha; v1 *= alpha;
        if (bias) { v0 += bias[n]; v1 += bias[n + 1]; }
        if (doRelu) { v0 = fmaxf(v0, 0.0f); v1 = fmaxf(v1, 0.0f); }
        size_t oidx;
        if (mode == MODE_PLAIN) {
            oidx = (size_t)bz * cBatch + (size_t)m * ldc + n;
        } else if (mode == MODE_HEADSPLIT) {
            int b_ = m >> 9, l_ = m & 511, h_ = n >> 8, d_ = n & 255;
            oidx = ((size_t)((b_ * HH + h_) * LL + l_)) * DD + d_;
        } else {  // MODE_VT: m over HD (h,d), n over NTOK (b,l) -> Vt[(b*H+h)*D+d][l]
            int h_ = m >> 8, d_ = m & 255, b_ = n >> 9, l_ = n & 511;
            oidx = ((size_t)((b_ * HH + h_) * DD + d_)) * LL + l_;
        }
        if (outF) *(float2*)(outF + oidx) = make_float2(v0, v1);
        else *(__half2*)(outHb + oidx) = __floats2half2_rn(v0, v1);
    };
#pragma unroll
    for (int i = 0; i < 2; i++) {
        int m = mb + i * 16;
#pragma unroll
        for (int j = 0; j < 8; j++) {
            int n = nb + j * 8;
            emit2(m, n, c[i][j][0], c[i][j][1]);
            emit2(m + 8, n, c[i][j][2], c[i][j][3]);
        }
    }
}

// ---------------- fused flash attention ----------------
#define FSM_K 65536
#define FSM_V 131072
#define FSM_TOT 196608

__global__ void __launch_bounds__(256, 1)
flash_attn(const __half* __restrict__ Qh, const __half* __restrict__ Kh,
           const __half* __restrict__ Vt, const float* __restrict__ Vsum,
           __half* __restrict__ Om) {
    extern __shared__ __align__(128) char smem[];
    const int qt = blockIdx.x;
    const int bh = blockIdx.y;
    const int tid = threadIdx.x;
    const int w = tid >> 5;
    const int l = tid & 31;

    const __half* gQ = Qh + ((size_t)bh * LL + qt * 128) * DD;
    const __half* gK = Kh + (size_t)bh * LL * DD;
    const __half* gV = Vt + (size_t)bh * DD * LL;
    char* smQ = smem;
    char* smK = smem + FSM_K;
    char* smV = smem + FSM_V;
    const uint32_t sQ = smem_u32(smem);
    const uint32_t sK = sQ + FSM_K;
    const uint32_t sV = sQ + FSM_V;

#pragma unroll
    for (int cq = 0; cq < 4; cq++)
#pragma unroll
        for (int it = 0; it < 4; it++) {
            int idx = tid + it * 256;
            int r = idx >> 3, ch = idx & 7;
            __pipeline_memcpy_async(smQ + cq * 16384 + r * 128 + ((ch ^ (r & 7)) << 4),
                                    gQ + (size_t)r * DD + cq * 64 + ch * 8, 16);
        }
    __pipeline_commit();

    float o[32][4];
#pragma unroll
    for (int j = 0; j < 32; j++)
#pragma unroll
        for (int e = 0; e < 4; e++) o[j][e] = 0.0f;
    float mrun0 = -INFINITY, mrun1 = -INFINITY;
    float lrun0 = 0.0f, lrun1 = 0.0f;

    const int r0l = w * 16 + (l >> 2);
    const int r1l = r0l + 8;
    const int arow = w * 16 + ((l >> 3) & 1) * 8 + (l & 7);
    const int kpA = (l >> 4) & 1;
    const int brow = ((l >> 4) & 1) * 8 + (l & 7);
    const int kpB = (l >> 3) & 1;
    const float alpha = (float)(1.0 / (16.0 + 1e-6));

    for (int kt = 0; kt <= qt; kt++) {
#pragma unroll
        for (int ck = 0; ck < 4; ck++) {
#pragma unroll
            for (int it = 0; it < 4; it++) {
                int idx = tid + it * 256;
                int r = idx >> 3, ch = idx & 7;
                __pipeline_memcpy_async(smK + ck * 16384 + r * 128 + ((ch ^ (r & 7)) << 4),
                                        gK + (size_t)(kt * 128 + r) * DD + ck * 64 + ch * 8, 16);
            }
            __pipeline_commit();
        }
#pragma unroll
        for (int cv = 0; cv < 2; cv++) {
#pragma unroll
            for (int it = 0; it < 8; it++) {
                int idx = tid + it * 256;
                int r = idx >> 3, ch = idx & 7;
                __pipeline_memcpy_async(smV + cv * 32768 + r * 128 + ((ch ^ (r & 7)) << 4),
                                        gV + (size_t)r * LL + kt * 128 + cv * 64 + ch * 8, 16);
            }
            __pipeline_commit();
        }

        float c[16][4];
#pragma unroll
        for (int j = 0; j < 16; j++)
#pragma unroll
            for (int e = 0; e < 4; e++) c[j][e] = 0.0f;

#pragma unroll
        for (int ck = 0; ck < 4; ck++) {
            __pipeline_wait_prior(5 - ck);
            __syncthreads();
#pragma unroll
            for (int ks = 0; ks < 4; ks++) {
                uint32_t a0, a1, a2, a3;
                ldsm4(a0, a1, a2, a3,
                      sQ + ck * 16384 + arow * 128 + (((2 * ks + kpA) ^ (arow & 7)) << 4));
#pragma unroll
                for (int g = 0; g < 8; g++) {
                    int nr = g * 16 + brow;
                    uint32_t b0, b1, b2, b3;
                    ldsm4(b0, b1, b2, b3,
                          sK + ck * 16384 + nr * 128 + (((2 * ks + kpB) ^ (nr & 7)) << 4));
                    mma16816(c[2 * g], a0, a1, a2, a3, b0, b1);
                    mma16816(c[2 * g + 1], a0, a1, a2, a3, b2, b3);
                }
            }
        }

        if (kt == qt) {
#pragma unroll
            for (int j = 0; j < 16; j++) {
                int nb = j * 8 + (l & 3) * 2;
                c[j][0] = (nb     <= r0l) ? c[j][0] * alpha : -INFINITY;
                c[j][1] = (nb + 1 <= r0l) ? c[j][1] * alpha : -INFINITY;
                c[j][2] = (nb     <= r1l) ? c[j][2] * alpha : -INFINITY;
                c[j][3] = (nb + 1 <= r1l) ? c[j][3] * alpha : -INFINITY;
            }
        } else {
#pragma unroll
            for (int j = 0; j < 16; j++)
#pragma unroll
                for (int e = 0; e < 4; e++) c[j][e] *= alpha;
        }

        float mn0 = mrun0, mn1 = mrun1;
#pragma unroll
        for (int j = 0; j < 16; j++) {
            mn0 = fmaxf(mn0, fmaxf(c[j][0], c[j][1]));
            mn1 = fmaxf(mn1, fmaxf(c[j][2], c[j][3]));
        }
        mn0 = fmaxf(mn0, __shfl_xor_sync(0xFFFFFFFF, mn0, 1));
        mn0 = fmaxf(mn0, __shfl_xor_sync(0xFFFFFFFF, mn0, 2));
        mn1 = fmaxf(mn1, __shfl_xor_sync(0xFFFFFFFF, mn1, 1));
        mn1 = fmaxf(mn1, __shfl_xor_sync(0xFFFFFFFF, mn1, 2));
        float corr0 = __expf(mrun0 - mn0);
        float corr1 = __expf(mrun1 - mn1);
        mrun0 = mn0; mrun1 = mn1;

        float rs0 = 0.0f, rs1 = 0.0f;
        uint32_t pk[16][2];
#pragma unroll
        for (int j = 0; j < 16; j++) {
            float p0 = __expf(c[j][0] - mn0);
            float p1 = __expf(c[j][1] - mn0);
            float p2 = __expf(c[j][2] - mn1);
            float p3 = __expf(c[j][3] - mn1);
            rs0 += p0 + p1; rs1 += p2 + p3;
            pk[j][0] = packh2(p0, p1);
            pk[j][1] = packh2(p2, p3);
        }
        rs0 += __shfl_xor_sync(0xFFFFFFFF, rs0, 1);
        rs0 += __shfl_xor_sync(0xFFFFFFFF, rs0, 2);
        rs1 += __shfl_xor_sync(0xFFFFFFFF, rs1, 1);
        rs1 += __shfl_xor_sync(0xFFFFFFFF, rs1, 2);
        lrun0 = lrun0 * corr0 + rs0;
        lrun1 = lrun1 * corr1 + rs1;
#pragma unroll
        for (int j = 0; j < 32; j++) {
            o[j][0] *= corr0; o[j][1] *= corr0;
            o[j][2] *= corr1; o[j][3] *= corr1;
        }

#pragma unroll
        for (int hv = 0; hv < 2; hv++) {
            __pipeline_wait_prior(1 - hv);
            __syncthreads();
#pragma unroll
            for (int k2 = 0; k2 < 4; k2++) {
                int kk = hv * 4 + k2;
                uint32_t a0 = pk[2 * kk][0], a1 = pk[2 * kk][1];
                uint32_t a2 = pk[2 * kk + 1][0], a3 = pk[2 * kk + 1][1];
#pragma unroll
                for (int g = 0; g < 16; g++) {
                    int nr = g * 16 + brow;
                    uint32_t b0, b1, b2, b3;
                    ldsm4(b0, b1, b2, b3,
                          sV + hv * 32768 + nr * 128 + (((2 * k2 + kpB) ^ (nr & 7)) << 4));
                    mma16816(o[2 * g], a0, a1, a2, a3, b0, b1);
                    mma16816(o[2 * g + 1], a0, a1, a2, a3, b2, b3);
                }
            }
        }
        __syncthreads();
    }

    float inv0 = 1.0f / lrun0, inv1 = 1.0f / lrun1;
    int q0 = qt * 128 + r0l, q1 = q0 + 8;
    int b_ = bh >> 2, h_ = bh & 3;
    int pad0 = g_pad[(b_ << 9) + q0];
    int pad1 = g_pad[(b_ << 9) + q1];
    const float i512 = 1.0f / 512.0f;
    const float* vs = Vsum + bh * DD;
    size_t base0 = (size_t)(b_ * 512 + q0) * HD + h_ * DD;
    size_t base1 = (size_t)(b_ * 512 + q1) * HD + h_ * DD;
#pragma unroll
    for (int j = 0; j < 32; j++) {
        int d = j * 8 + (l & 3) * 2;
        float v0 = o[j][0] * inv0, v1 = o[j][1] * inv0;
        float v2 = o[j][2] * inv1, v3 = o[j][3] * inv1;
        if (pad0) { v0 = vs[d] * i512; v1 = vs[d + 1] * i512; }
        if (pad1) { v2 = vs[d] * i512; v3 = vs[d + 1] * i512; }
        *(__half2*)(Om + base0 + d) = __floats2half2_rn(v0, v1);
        *(__half2*)(Om + base1 + d) = __floats2half2_rn(v2, v3);
    }
}

// ---------------- residual + layernorm: warp per row, zero barriers ----------------
__global__ void __launch_bounds__(256)
ln_residual_kernel(const float* __restrict__ Ain, const float* __restrict__ Bin,
                   const float* __restrict__ gamma, const float* __restrict__ beta,
                   float* __restrict__ outF, __half* __restrict__ outH) {
    int row = blockIdx.x * 8 + (threadIdx.x >> 5);
    int l = threadIdx.x & 31;
    size_t base = (size_t)row * DD + l * 8;

    float4 a0 = *(const float4*)(Ain + base);
    float4 a1 = *(const float4*)(Ain + base + 4);
    float4 b0 = *(const float4*)(Bin + base);
    float4 b1 = *(const float4*)(Bin + base + 4);
    float x[8] = {a0.x + b0.x, a0.y + b0.y, a0.z + b0.z, a0.w + b0.w,
                  a1.x + b1.x, a1.y + b1.y, a1.z + b1.z, a1.w + b1.w};

    float s = 0.0f;
#pragma unroll
    for (int e = 0; e < 8; e++) s += x[e];
#pragma unroll
    for (int off = 16; off > 0; off >>= 1) s += __shfl_xor_sync(0xFFFFFFFF, s, off);
    float mu = s * (1.0f / DD);

    float sq = 0.0f;
#pragma unroll
    for (int e = 0; e < 8; e++) { float d = x[e] - mu; sq += d * d; }
#pragma unroll
    for (int off = 16; off > 0; off >>= 1) sq += __shfl_xor_sync(0xFFFFFFFF, sq, off);
    float rstd = rsqrtf(sq * (1.0f / DD) + 1e-5f);

    float4 g0 = *(const float4*)(gamma + l * 8);
    float4 g1 = *(const float4*)(gamma + l * 8 + 4);
    float4 be0 = *(const float4*)(beta + l * 8);
    float4 be1 = *(const float4*)(beta + l * 8 + 4);
    float y[8];
    y[0] = (x[0] - mu) * rstd * g0.x + be0.x;
    y[1] = (x[1] - mu) * rstd * g0.y + be0.y;
    y[2] = (x[2] - mu) * rstd * g0.z + be0.z;
    y[3] = (x[3] - mu) * rstd * g0.w + be0.w;
    y[4] = (x[4] - mu) * rstd * g1.x + be1.x;
    y[5] = (x[5] - mu) * rstd * g1.y + be1.y;
    y[6] = (x[6] - mu) * rstd * g1.z + be1.z;
    y[7] = (x[7] - mu) * rstd * g1.w + be1.w;

    if (outF) {
        *(float4*)(outF + base) = make_float4(y[0], y[1], y[2], y[3]);
        *(float4*)(outF + base + 4) = make_float4(y[4], y[5], y[6], y[7]);
    }
    if (outH) {
        __half2 h[4] = {__floats2half2_rn(y[0], y[1]), __floats2half2_rn(y[2], y[3]),
                        __floats2half2_rn(y[4], y[5]), __floats2half2_rn(y[6], y[7])};
        *(float4*)(outH + base) = *(float4*)h;
    }
}

// ---------------- host orchestration ----------------
#define SYM(p, s) void* p; cudaGetSymbolAddress(&p, s)

extern "C" void kernel_launch(void* const* d_in, const int* in_sizes, int n_in,
                              void* d_out, int out_size) {
    (void)in_sizes; (void)n_in; (void)out_size;
    const float* Q    = (const float*)d_in[0];
    const float* K    = (const float*)d_in[1];
    const float* V    = (const float*)d_in[2];
    const void*  mask = d_in[3];
    const float* pe   = (const float*)d_in[4];
    const float* W_q  = (const float*)d_in[5];
    const float* W_k  = (const float*)d_in[6];
    const float* W_v  = (const float*)d_in[7];
    const float* W_o  = (const float*)d_in[8];
    const float* w1   = (const float*)d_in[9];
    const float* b1   = (const float*)d_in[10];
    const float* w2   = (const float*)d_in[11];
    const float* b2   = (const float*)d_in[12];
    const float* gamma = (const float*)d_in[13];
    const float* beta  = (const float*)d_in[14];
    float* out = (float*)d_out;

    SYM(pQpF, g_QpF);
    SYM(pQpH, g_QpH); SYM(pKpH, g_KpH); SYM(pVpH, g_VpH);
    SYM(pQhH, g_QhH); SYM(pKhH, g_KhH); SYM(pVtH, g_VtH);
    SYM(pVsum, g_Vsum); SYM(pVmH, g_VmH);
    SYM(pT1, g_T1); SYM(pXF, g_XF); SYM(pXH, g_XH); SYM(pYH, g_YH); SYM(pZF, g_ZF);
    SYM(pWq, g_Wq); SYM(pWk, g_Wk); SYM(pWv, g_Wv); SYM(pWo, g_Wo);
    SYM(pw1, g_w1); SYM(pw2, g_w2);

    cudaFuncSetAttribute(gemm_h, cudaFuncAttributeMaxDynamicSharedMemorySize, NSTG * STG);
    cudaFuncSetAttribute(flash_attn, cudaFuncAttributeMaxDynamicSharedMemorySize, FSM_TOT);

    typedef __half hf;

    // 1) mask
    detect_mask_kernel<<<1, 256>>>((const unsigned char*)mask);
    decode_mask_kernel<<<(NTOK + 255) / 256, 256>>>(mask);

    // 2) PE add + fp16 convert (Q, K, V in one launch)
    {
        int q4 = NTOK * DD / 4, qb = (q4 + 255) / 256;
        add_pe_all<<<dim3(qb, 3), 256>>>((const float4*)Q, (const float4*)K,
                                         (const float4*)V, pe, (float4*)pQpF,
                                         (__half2*)pQpH, (__half2*)pKpH, (__half2*)pVpH);
    }

    // 3) weight conversions: tiled transposes (Wq, Wk, Wv, Wo) + direct (w1, w2)
    wconv_trans_tiled<<<dim3((DD / 32) * (HD / 32), 4), 256>>>(
        W_q, W_k, W_v, W_o, (hf*)pWq, (hf*)pWk, (hf*)pWv, (hf*)pWo);
    wconv_direct2<<<dim3((DD * DD / 4 + 255) / 256, 2), 256>>>(
        (const float4*)w1, (const float4*)w2, (__half2*)pw1, (__half2*)pw2);

    // 4a) Q + K projections in ONE launch (z=0: Qp@Wq -> Qh, z=1: Kp@Wk -> Kh)
    {
        dim3 g(HD / NT, NTOK / MT, 2);
        gemm_h<<<g, 256, NSTG * STG>>>((hf*)pQpH, (hf*)pWq, nullptr, (hf*)pQhH, nullptr,
                                       DD, 0, 0, 0, 0, MODE_HEADSPLIT, 1.0f, 0,
                                       (hf*)pKpH, (hf*)pWk, (hf*)pKhH);
    }

    // 4b) V projection, transposed output: A = Wv (M=1024), B = Vp (N=16384)
    {
        dim3 g(NTOK / NT, HD / MT, 1);
        gemm_h<<<g, 256, NSTG * STG>>>((hf*)pWv, (hf*)pVpH, nullptr, (hf*)pVtH, nullptr,
                                       DD, 0, 0, 0, 0, MODE_VT, 1.0f, 0,
                                       nullptr, nullptr, nullptr);
    }

    // 5) Vsum from Vt (warp per row)
    vsum_kernel<<<BH * DD / 8, 256>>>((const __half2*)pVtH, (float*)pVsum);

    // 6) fused flash attention -> merged (b, l, h*d)
    {
        dim3 g(LL / 128, BH);
        flash_attn<<<g, 256, FSM_TOT>>>((hf*)pQhH, (hf*)pKhH, (hf*)pVtH,
                                        (float*)pVsum, (hf*)pVmH);
    }

    // 7) output projection: T1 = Vm @ W_o  (M=16384, N=256, K=1024)
    {
        dim3 g(DD / NT, NTOK / MT, 1);
        gemm_h<<<g, 256, NSTG * STG>>>((hf*)pVmH, (hf*)pWo, (float*)pT1, nullptr, nullptr,
                                       HD, 0, 0, 0, DD, MODE_PLAIN, 1.0f, 0,
                                       nullptr, nullptr, nullptr);
    }

    // 8) X = LN(Qp + T1)
    ln_residual_kernel<<<NTOK / 8, 256>>>((float*)pQpF, (float*)pT1, gamma, beta,
                                          (float*)pXF, (hf*)pXH);

    // 9) FFN: Y = relu(X @ w1^T + b1); Z = Y @ w2^T + b2
    {
        dim3 g(DD / NT, NTOK / MT, 1);
        gemm_h<<<g, 256, NSTG * STG>>>((hf*)pXH, (hf*)pw1, nullptr, (hf*)pYH, b1,
                                       DD, 0, 0, 0, DD, MODE_PLAIN, 1.0f, 1,
                                       nullptr, nullptr, nullptr);
        gemm_h<<<g, 256, NSTG * STG>>>((hf*)pYH, (hf*)pw2, (float*)pZF, nullptr, b2,
                                       DD, 0, 0, 0, DD, MODE_PLAIN, 1.0f, 0,
                                       nullptr, nullptr, nullptr);
    }

    // 10) out = LN(Z + X)
    ln_residual_kernel<<<NTOK / 8, 256>>>((float*)pZF, (float*)pXF, gamma, beta, out, nullptr);
}

// round 16
// speedup vs baseline: 5.2970x; 1.0596x over previous
#include <cuda_runtime.h>
#include <cuda_fp16.h>
#include <cuda_pipeline.h>
#include <cstdint>

// Problem dims: B=32, L=512, D=256, H=4
#define BB 32
#define LL 512
#define DD 256
#define HH 4
#define NTOK (BB * LL)      // 16384
#define BH (BB * HH)        // 128
#define HD (HH * DD)        // 1024

// ---------------- device scratch (.bss, allocation-free) ----------------
__device__ __align__(256) float g_QpF[NTOK * DD];
__device__ __align__(256) __half g_QpH[NTOK * DD], g_KpH[NTOK * DD], g_VpH[NTOK * DD];
__device__ __align__(256) __half g_QhH[BH * LL * DD];     // (bh, l, d)
__device__ __align__(256) __half g_KhH[BH * LL * DD];     // (bh, l, d)
__device__ __align__(256) __half g_VtH[BH * DD * LL];     // (bh, d, l)
__device__ __align__(256) float g_Vsum[BH * DD];
__device__ __align__(256) __half g_VmH[NTOK * HD];        // (b, l, h*d)
__device__ __align__(256) float g_T1[NTOK * DD];
__device__ __align__(256) float g_XF[NTOK * DD];
__device__ __align__(256) __half g_XH[NTOK * DD];
__device__ __align__(256) __half g_YH[NTOK * DD];
__device__ __align__(256) float g_ZF[NTOK * DD];
// weights as B operand layout: [n][k] (k contiguous)
__device__ __align__(256) __half g_Wq[HD * DD], g_Wk[HD * DD], g_Wv[HD * DD];
__device__ __align__(256) __half g_Wo[DD * HD];
__device__ __align__(256) __half g_w1[DD * DD], g_w2[DD * DD];
__device__ int g_pad[NTOK];

// ---------------- mask decode, single launch, per-block dtype sniff ----------------
// Block covers 1024 tokens. Byte-mode detection: under a byte-bool mask the 256 bytes
// at offsets 4i+1 inside this block's window are ~50% nonzero; under int32/float32
// 0/1 encodings they are all zero. Misdetect probability ~2^-256.
__global__ void decode_mask_kernel(const unsigned char* __restrict__ mb) {
    __shared__ int any;
    int tid = threadIdx.x;
    if (tid == 0) any = 0;
    __syncthreads();
    int i = blockIdx.x * 256 + tid;          // over NTOK/4 words
    if (mb[4 * i + 1]) atomicOr(&any, 1);
    __syncthreads();
    int base = blockIdx.x * 1024;
#pragma unroll
    for (int k = 0; k < 4; k++) {
        int t = base + k * 256 + tid;
        g_pad[t] = any ? (mb[t] != 0) : (((const int*)mb)[t] != 0);
    }
}

// ---------------- PE add for Q, K, V in one launch (grid.y selects) ----------------
__global__ void add_pe_all(const float4* __restrict__ Q, const float4* __restrict__ K,
                           const float4* __restrict__ V, const float* __restrict__ pe,
                           float4* __restrict__ QpF, __half2* __restrict__ QpH,
                           __half2* __restrict__ KpH, __half2* __restrict__ VpH) {
    int i = blockIdx.x * blockDim.x + threadIdx.x;   // over NTOK*DD/4
    if (i >= NTOK * DD / 4) return;
    int y = blockIdx.y;
    const float4* in = (y == 0) ? Q : (y == 1) ? K : V;
    __half2* outH = (y == 0) ? QpH : (y == 1) ? KpH : VpH;
    int d4 = i & 63;
    int l = (i >> 6) & (LL - 1);
    float4 v = in[i];
    float4 p = *(const float4*)(pe + l * DD + d4 * 4);
    v.x += p.x; v.y += p.y; v.z += p.z; v.w += p.w;
    if (y == 0) QpF[i] = v;
    outH[2 * i] = __floats2half2_rn(v.x, v.y);
    outH[2 * i + 1] = __floats2half2_rn(v.z, v.w);
}

// ---------------- all weight conversions, one launch (grid.y = 0..5) ----------------
// y<4: 32x32 smem-tiled transpose (EXACTLY 256 tiles each; guarded).
// y>=4: direct vectorized convert (w1, w2) with its own bounds check.
// NOTE R13 bug: grid.x=1024 with no guard in the transpose branch wrote out-of-range
// tiles INTO valid weight rows. Grid is now 256 and the guard is explicit.
__global__ void wconv_all(const float* __restrict__ Wq, const float* __restrict__ Wk,
                          const float* __restrict__ Wv, const float* __restrict__ Wo,
                          const float* __restrict__ w1, const float* __restrict__ w2,
                          __half* __restrict__ dWq, __half* __restrict__ dWk,
                          __half* __restrict__ dWv, __half* __restrict__ dWo,
                          __half2* __restrict__ dw1, __half2* __restrict__ dw2) {
    int y = blockIdx.y;
    if (y < 4) {
        __shared__ __half t[32][33];
        const float* src = (y == 0) ? Wq : (y == 1) ? Wk : (y == 2) ? Wv : Wo;
        __half* dst = (y == 0) ? dWq : (y == 1) ? dWk : (y == 2) ? dWv : dWo;
        int R = (y < 3) ? DD : HD;
        int C = (y < 3) ? HD : DD;
        int tilesC = C >> 5;
        if ((int)blockIdx.x >= (R >> 5) * tilesC) return;   // guard (exact at 256)
        int tr = (blockIdx.x / tilesC) << 5;
        int tc = (blockIdx.x % tilesC) << 5;
        int tx = threadIdx.x & 31, ty = threadIdx.x >> 5;
#pragma unroll
        for (int s = 0; s < 32; s += 8)
            t[ty + s][tx] = __float2half_rn(src[(size_t)(tr + ty + s) * C + tc + tx]);
        __syncthreads();
#pragma unroll
        for (int s = 0; s < 32; s += 8)
            dst[(size_t)(tc + ty + s) * R + tr + tx] = t[tx][ty + s];
    } else {
        int i = blockIdx.x * blockDim.x + threadIdx.x;
        if (i >= DD * DD / 4) return;
        const float4* s = (y == 4) ? (const float4*)w1 : (const float4*)w2;
        __half2* d = (y == 4) ? dw1 : dw2;
        float4 v = s[i];
        d[2 * i] = __floats2half2_rn(v.x, v.y);
        d[2 * i + 1] = __floats2half2_rn(v.z, v.w);
    }
}

// ---------------- Vsum[bh][d] = sum_l Vt[bh][d][l] (warp per row) ----------------
__global__ void vsum_kernel(const __half2* __restrict__ Vt, float* __restrict__ Vs) {
    int row = blockIdx.x * 8 + (threadIdx.x >> 5);   // over BH*DD = 32768 rows
    int lane = threadIdx.x & 31;
    const __half2* p = Vt + (size_t)row * (LL / 2);
    float s = 0.0f;
#pragma unroll
    for (int i = 0; i < 8; i++) {
        float2 v = __half22float2(p[i * 32 + lane]);
        s += v.x + v.y;
    }
#pragma unroll
    for (int off = 16; off > 0; off >>= 1) s += __shfl_xor_sync(0xFFFFFFFF, s, off);
    if (lane == 0) Vs[row] = s;
}

// ---------------- asm helpers ----------------
__device__ __forceinline__ uint32_t smem_u32(const void* p) {
    uint32_t a;
    asm("{ .reg .u64 t; cvta.to.shared.u64 t, %1; cvt.u32.u64 %0, t; }" : "=r"(a) : "l"(p));
    return a;
}
__device__ __forceinline__ void ldsm4(uint32_t& r0, uint32_t& r1, uint32_t& r2, uint32_t& r3,
                                      uint32_t addr) {
    asm volatile("ldmatrix.sync.aligned.m8n8.x4.shared.b16 {%0,%1,%2,%3}, [%4];"
                 : "=r"(r0), "=r"(r1), "=r"(r2), "=r"(r3) : "r"(addr));
}
__device__ __forceinline__ void mma16816(float* c, uint32_t a0, uint32_t a1, uint32_t a2,
                                         uint32_t a3, uint32_t b0, uint32_t b1) {
    asm volatile(
        "mma.sync.aligned.m16n8k16.row.col.f32.f16.f16.f32 "
        "{%0,%1,%2,%3}, {%4,%5,%6,%7}, {%8,%9}, {%0,%1,%2,%3};"
        : "+f"(c[0]), "+f"(c[1]), "+f"(c[2]), "+f"(c[3])
        : "r"(a0), "r"(a1), "r"(a2), "r"(a3), "r"(b0), "r"(b1));
}
__device__ __forceinline__ uint32_t packh2(float a, float b) {
    __half2 h = __floats2half2_rn(a, b);
    return *(uint32_t*)&h;
}

// ---------------- fp16 mma.sync GEMM, 3-stage cp.async pipeline ----------------
#define MT 128
#define NT 128
#define KC 64
#define STG 32768          // A 16K + B 16K per stage
#define NSTG 3

#define MODE_PLAIN 0
#define MODE_HEADSPLIT 1
#define MODE_VT 2

__global__ void __launch_bounds__(256, 2)
gemm_h(const __half* __restrict__ A, const __half* __restrict__ B,
       float* __restrict__ outF, __half* __restrict__ outH, const float* __restrict__ bias,
       int K, long long aBatch, long long bBatch, long long cBatch, int ldc,
       int mode, float alpha, int doRelu,
       const __half* __restrict__ A2, const __half* __restrict__ B2,
       __half* __restrict__ outH2,
       const __half* __restrict__ A3, const __half* __restrict__ B3,
       __half* __restrict__ outH3) {
    extern __shared__ __align__(128) char smem[];

    const int bz = blockIdx.z;
    const int tid = threadIdx.x;
    const int wid = tid >> 5;
    const int l = tid & 31;
    const int wr = wid & 3;
    const int wc = wid >> 2;

    // triple-problem merge (projection launch):
    //   z=0: (A, B)  headsplit   z=1: (A2, B2) headsplit   z=2: (A3, B3) VT w/ swapped map
    const __half* Ab = A;
    const __half* Bb = B;
    __half* outHb = outH;
    int md = mode;
    int bm0, bn0;
    if (A2 && bz == 1) { Ab = A2; Bb = B2; outHb = outH2; }
    if (A3 && bz == 2) {
        Ab = A3; Bb = B3; outHb = outH3; md = MODE_VT;
        bm0 = blockIdx.x * MT;            // M over HD (8 tiles)
        bn0 = blockIdx.y * NT;            // N over NTOK (128 tiles)
    } else {
        bm0 = blockIdx.y * MT;
        bn0 = blockIdx.x * NT;
    }
    const bool batched = (A2 == nullptr) && (A3 == nullptr);
    const __half* gA = Ab + (batched ? bz * aBatch : 0) + (long long)bm0 * K;
    const __half* gB = Bb + (batched ? bz * bBatch : 0) + (long long)bn0 * K;
    const uint32_t sbase = smem_u32(smem);

    float c[2][8][4];
#pragma unroll
    for (int i = 0; i < 2; i++)
#pragma unroll
        for (int j = 0; j < 8; j++)
#pragma unroll
            for (int e = 0; e < 4; e++) c[i][j][e] = 0.0f;

    const int mrow = wr * 32 + ((l >> 3) & 1) * 8 + (l & 7);
    const int kpA = (l >> 4) & 1;
    const int nrow = wc * 64 + ((l >> 4) & 1) * 8 + (l & 7);
    const int kpB = (l >> 3) & 1;

    auto stage_fn = [&](int buf, int k0) {
        char* sA = smem + buf * STG;
        char* sB = sA + 16384;
#pragma unroll
        for (int it = 0; it < 4; it++) {
            int idx = tid + it * 256;
            int r = idx >> 3, ch = idx & 7;
            __pipeline_memcpy_async(sA + r * 128 + ((ch ^ (r & 7)) << 4),
                                    gA + (long long)r * K + k0 + ch * 8, 16);
        }
#pragma unroll
        for (int it = 0; it < 4; it++) {
            int idx = tid + it * 256;
            int r = idx >> 3, ch = idx & 7;
            __pipeline_memcpy_async(sB + r * 128 + ((ch ^ (r & 7)) << 4),
                                    gB + (long long)r * K + k0 + ch * 8, 16);
        }
    };

    const int nt = K / KC;
    stage_fn(0, 0);
    __pipeline_commit();
    if (nt > 1) { stage_fn(1, KC); __pipeline_commit(); }

    for (int cc = 0; cc < nt; cc++) {
        if (cc < nt - 1) __pipeline_wait_prior(1);
        else __pipeline_wait_prior(0);
        __syncthreads();
        if (cc + 2 < nt) {
            stage_fn((cc + 2) % NSTG, (cc + 2) * KC);
            __pipeline_commit();
        }

        const int buf = cc % NSTG;
        const uint32_t sA = sbase + buf * STG;
        const uint32_t sB = sA + 16384;
#pragma unroll
        for (int ks = 0; ks < 4; ks++) {
            uint32_t a[2][4];
#pragma unroll
            for (int i = 0; i < 2; i++) {
                int row = mrow + i * 16;
                ldsm4(a[i][0], a[i][1], a[i][2], a[i][3],
                      sA + row * 128 + (((2 * ks + kpA) ^ (row & 7)) << 4));
            }
            uint32_t b[4][4];
#pragma unroll
            for (int g = 0; g < 4; g++) {
                int row = nrow + g * 16;
                ldsm4(b[g][0], b[g][1], b[g][2], b[g][3],
                      sB + row * 128 + (((2 * ks + kpB) ^ (row & 7)) << 4));
            }
#pragma unroll
            for (int i = 0; i < 2; i++)
#pragma unroll
                for (int j = 0; j < 8; j++) {
                    int g = j >> 1, h2 = (j & 1) << 1;
                    mma16816(c[i][j], a[i][0], a[i][1], a[i][2], a[i][3],
                             b[g][h2], b[g][h2 + 1]);
                }
        }
    }

    const int mb = bm0 + wr * 32 + (l >> 2);
    const int nb = bn0 + wc * 64 + (l & 3) * 2;
    auto emit2 = [&](int m, int n, float v0, float v1) {
        v0 *= alpha; v1 *= alpha;
        if (bias) { v0 += bias[n]; v1 += bias[n + 1]; }
        if (doRelu) { v0 = fmaxf(v0, 0.0f); v1 = fmaxf(v1, 0.0f); }
        size_t oidx;
        if (md == MODE_PLAIN) {
            oidx = (size_t)bz * cBatch + (size_t)m * ldc + n;
        } else if (md == MODE_HEADSPLIT) {
            int b_ = m >> 9, l_ = m & 511, h_ = n >> 8, d_ = n & 255;
            oidx = ((size_t)((b_ * HH + h_) * LL + l_)) * DD + d_;
        } else {  // MODE_VT: m over HD (h,d), n over NTOK (b,l) -> Vt[(b*H+h)*D+d][l]
            int h_ = m >> 8, d_ = m & 255, b_ = n >> 9, l_ = n & 511;
            oidx = ((size_t)((b_ * HH + h_) * DD + d_)) * LL + l_;
        }
        if (outF) *(float2*)(outF + oidx) = make_float2(v0, v1);
        else *(__half2*)(outHb + oidx) = __floats2half2_rn(v0, v1);
    };
#pragma unroll
    for (int i = 0; i < 2; i++) {
        int m = mb + i * 16;
#pragma unroll
        for (int j = 0; j < 8; j++) {
            int n = nb + j * 8;
            emit2(m, n, c[i][j][0], c[i][j][1]);
            emit2(m + 8, n, c[i][j][2], c[i][j][3]);
        }
    }
}

// ---------------- fused flash attention (LPT dispatch: heavy q-tiles first) ----------------
#define FSM_K 65536
#define FSM_V 131072
#define FSM_TOT 196608

__global__ void __launch_bounds__(256, 1)
flash_attn(const __half* __restrict__ Qh, const __half* __restrict__ Kh,
           const __half* __restrict__ Vt, const float* __restrict__ Vsum,
           __half* __restrict__ Om) {
    extern __shared__ __align__(128) char smem[];
    const int qt = (gridDim.y - 1) - blockIdx.y;   // y=0 -> qt=3 (most work) first
    const int bh = blockIdx.x;
    const int tid = threadIdx.x;
    const int w = tid >> 5;
    const int l = tid & 31;

    const __half* gQ = Qh + ((size_t)bh * LL + qt * 128) * DD;
    const __half* gK = Kh + (size_t)bh * LL * DD;
    const __half* gV = Vt + (size_t)bh * DD * LL;
    char* smQ = smem;
    char* smK = smem + FSM_K;
    char* smV = smem + FSM_V;
    const uint32_t sQ = smem_u32(smem);
    const uint32_t sK = sQ + FSM_K;
    const uint32_t sV = sQ + FSM_V;

#pragma unroll
    for (int cq = 0; cq < 4; cq++)
#pragma unroll
        for (int it = 0; it < 4; it++) {
            int idx = tid + it * 256;
            int r = idx >> 3, ch = idx & 7;
            __pipeline_memcpy_async(smQ + cq * 16384 + r * 128 + ((ch ^ (r & 7)) << 4),
                                    gQ + (size_t)r * DD + cq * 64 + ch * 8, 16);
        }
    __pipeline_commit();

    float o[32][4];
#pragma unroll
    for (int j = 0; j < 32; j++)
#pragma unroll
        for (int e = 0; e < 4; e++) o[j][e] = 0.0f;
    float mrun0 = -INFINITY, mrun1 = -INFINITY;
    float lrun0 = 0.0f, lrun1 = 0.0f;

    const int r0l = w * 16 + (l >> 2);
    const int r1l = r0l + 8;
    const int arow = w * 16 + ((l >> 3) & 1) * 8 + (l & 7);
    const int kpA = (l >> 4) & 1;
    const int brow = ((l >> 4) & 1) * 8 + (l & 7);
    const int kpB = (l >> 3) & 1;
    const float alpha = (float)(1.0 / (16.0 + 1e-6));

    for (int kt = 0; kt <= qt; kt++) {
#pragma unroll
        for (int ck = 0; ck < 4; ck++) {
#pragma unroll
            for (int it = 0; it < 4; it++) {
                int idx = tid + it * 256;
                int r = idx >> 3, ch = idx & 7;
                __pipeline_memcpy_async(smK + ck * 16384 + r * 128 + ((ch ^ (r & 7)) << 4),
                                        gK + (size_t)(kt * 128 + r) * DD + ck * 64 + ch * 8, 16);
            }
            __pipeline_commit();
        }
#pragma unroll
        for (int cv = 0; cv < 2; cv++) {
#pragma unroll
            for (int it = 0; it < 8; it++) {
                int idx = tid + it * 256;
                int r = idx >> 3, ch = idx & 7;
                __pipeline_memcpy_async(smV + cv * 32768 + r * 128 + ((ch ^ (r & 7)) << 4),
                                        gV + (size_t)r * LL + kt * 128 + cv * 64 + ch * 8, 16);
            }
            __pipeline_commit();
        }

        float c[16][4];
#pragma unroll
        for (int j = 0; j < 16; j++)
#pragma unroll
            for (int e = 0; e < 4; e++) c[j][e] = 0.0f;

#pragma unroll
        for (int ck = 0; ck < 4; ck++) {
            __pipeline_wait_prior(5 - ck);
            __syncthreads();
#pragma unroll
            for (int ks = 0; ks < 4; ks++) {
                uint32_t a0, a1, a2, a3;
                ldsm4(a0, a1, a2, a3,
                      sQ + ck * 16384 + arow * 128 + (((2 * ks + kpA) ^ (arow & 7)) << 4));
#pragma unroll
                for (int g = 0; g < 8; g++) {
                    int nr = g * 16 + brow;
                    uint32_t b0, b1, b2, b3;
                    ldsm4(b0, b1, b2, b3,
                          sK + ck * 16384 + nr * 128 + (((2 * ks + kpB) ^ (nr & 7)) << 4));
                    mma16816(c[2 * g], a0, a1, a2, a3, b0, b1);
                    mma16816(c[2 * g + 1], a0, a1, a2, a3, b2, b3);
                }
            }
        }

        if (kt == qt) {
#pragma unroll
            for (int j = 0; j < 16; j++) {
                int nb = j * 8 + (l & 3) * 2;
                c[j][0] = (nb     <= r0l) ? c[j][0] * alpha : -INFINITY;
                c[j][1] = (nb + 1 <= r0l) ? c[j][1] * alpha : -INFINITY;
                c[j][2] = (nb     <= r1l) ? c[j][2] * alpha : -INFINITY;
                c[j][3] = (nb + 1 <= r1l) ? c[j][3] * alpha : -INFINITY;
            }
        } else {
#pragma unroll
            for (int j = 0; j < 16; j++)
#pragma unroll
                for (int e = 0; e < 4; e++) c[j][e] *= alpha;
        }

        float mn0 = mrun0, mn1 = mrun1;
#pragma unroll
        for (int j = 0; j < 16; j++) {
            mn0 = fmaxf(mn0, fmaxf(c[j][0], c[j][1]));
            mn1 = fmaxf(mn1, fmaxf(c[j][2], c[j][3]));
        }
        mn0 = fmaxf(mn0, __shfl_xor_sync(0xFFFFFFFF, mn0, 1));
        mn0 = fmaxf(mn0, __shfl_xor_sync(0xFFFFFFFF, mn0, 2));
        mn1 = fmaxf(mn1, __shfl_xor_sync(0xFFFFFFFF, mn1, 1));
        mn1 = fmaxf(mn1, __shfl_xor_sync(0xFFFFFFFF, mn1, 2));
        float corr0 = __expf(mrun0 - mn0);
        float corr1 = __expf(mrun1 - mn1);
        mrun0 = mn0; mrun1 = mn1;

        float rs0 = 0.0f, rs1 = 0.0f;
        uint32_t pk[16][2];
#pragma unroll
        for (int j = 0; j < 16; j++) {
            float p0 = __expf(c[j][0] - mn0);
            float p1 = __expf(c[j][1] - mn0);
            float p2 = __expf(c[j][2] - mn1);
            float p3 = __expf(c[j][3] - mn1);
            rs0 += p0 + p1; rs1 += p2 + p3;
            pk[j][0] = packh2(p0, p1);
            pk[j][1] = packh2(p2, p3);
        }
        rs0 += __shfl_xor_sync(0xFFFFFFFF, rs0, 1);
        rs0 += __shfl_xor_sync(0xFFFFFFFF, rs0, 2);
        rs1 += __shfl_xor_sync(0xFFFFFFFF, rs1, 1);
        rs1 += __shfl_xor_sync(0xFFFFFFFF, rs1, 2);
        lrun0 = lrun0 * corr0 + rs0;
        lrun1 = lrun1 * corr1 + rs1;
#pragma unroll
        for (int j = 0; j < 32; j++) {
            o[j][0] *= corr0; o[j][1] *= corr0;
            o[j][2] *= corr1; o[j][3] *= corr1;
        }

#pragma unroll
        for (int hv = 0; hv < 2; hv++) {
            __pipeline_wait_prior(1 - hv);
            __syncthreads();
#pragma unroll
            for (int k2 = 0; k2 < 4; k2++) {
                int kk = hv * 4 + k2;
                uint32_t a0 = pk[2 * kk][0], a1 = pk[2 * kk][1];
                uint32_t a2 = pk[2 * kk + 1][0], a3 = pk[2 * kk + 1][1];
#pragma unroll
                for (int g = 0; g < 16; g++) {
                    int nr = g * 16 + brow;
                    uint32_t b0, b1, b2, b3;
                    ldsm4(b0, b1, b2, b3,
                          sV + hv * 32768 + nr * 128 + (((2 * k2 + kpB) ^ (nr & 7)) << 4));
                    mma16816(o[2 * g], a0, a1, a2, a3, b0, b1);
                    mma16816(o[2 * g + 1], a0, a1, a2, a3, b2, b3);
                }
            }
        }
        __syncthreads();
    }

    float inv0 = 1.0f / lrun0, inv1 = 1.0f / lrun1;
    int q0 = qt * 128 + r0l, q1 = q0 + 8;
    int b_ = bh >> 2, h_ = bh & 3;
    int pad0 = g_pad[(b_ << 9) + q0];
    int pad1 = g_pad[(b_ << 9) + q1];
    const float i512 = 1.0f / 512.0f;
    const float* vs = Vsum + bh * DD;
    size_t base0 = (size_t)(b_ * 512 + q0) * HD + h_ * DD;
    size_t base1 = (size_t)(b_ * 512 + q1) * HD + h_ * DD;
#pragma unroll
    for (int j = 0; j < 32; j++) {
        int d = j * 8 + (l & 3) * 2;
        float v0 = o[j][0] * inv0, v1 = o[j][1] * inv0;
        float v2 = o[j][2] * inv1, v3 = o[j][3] * inv1;
        if (pad0) { v0 = vs[d] * i512; v1 = vs[d + 1] * i512; }
        if (pad1) { v2 = vs[d] * i512; v3 = vs[d + 1] * i512; }
        *(__half2*)(Om + base0 + d) = __floats2half2_rn(v0, v1);
        *(__half2*)(Om + base1 + d) = __floats2half2_rn(v2, v3);
    }
}

// ---------------- residual + layernorm: warp per row, zero barriers ----------------
__global__ void __launch_bounds__(256)
ln_residual_kernel(const float* __restrict__ Ain, const float* __restrict__ Bin,
                   const float* __restrict__ gamma, const float* __restrict__ beta,
                   float* __restrict__ outF, __half* __restrict__ outH) {
    int row = blockIdx.x * 8 + (threadIdx.x >> 5);
    int l = threadIdx.x & 31;
    size_t base = (size_t)row * DD + l * 8;

    float4 a0 = *(const float4*)(Ain + base);
    float4 a1 = *(const float4*)(Ain + base + 4);
    float4 b0 = *(const float4*)(Bin + base);
    float4 b1 = *(const float4*)(Bin + base + 4);
    float x[8] = {a0.x + b0.x, a0.y + b0.y, a0.z + b0.z, a0.w + b0.w,
                  a1.x + b1.x, a1.y + b1.y, a1.z + b1.z, a1.w + b1.w};

    float s = 0.0f;
#pragma unroll
    for (int e = 0; e < 8; e++) s += x[e];
#pragma unroll
    for (int off = 16; off > 0; off >>= 1) s += __shfl_xor_sync(0xFFFFFFFF, s, off);
    float mu = s * (1.0f / DD);

    float sq = 0.0f;
#pragma unroll
    for (int e = 0; e < 8; e++) { float d = x[e] - mu; sq += d * d; }
#pragma unroll
    for (int off = 16; off > 0; off >>= 1) sq += __shfl_xor_sync(0xFFFFFFFF, sq, off);
    float rstd = rsqrtf(sq * (1.0f / DD) + 1e-5f);

    float4 g0 = *(const float4*)(gamma + l * 8);
    float4 g1 = *(const float4*)(gamma + l * 8 + 4);
    float4 be0 = *(const float4*)(beta + l * 8);
    float4 be1 = *(const float4*)(beta + l * 8 + 4);
    float y[8];
    y[0] = (x[0] - mu) * rstd * g0.x + be0.x;
    y[1] = (x[1] - mu) * rstd * g0.y + be0.y;
    y[2] = (x[2] - mu) * rstd * g0.z + be0.z;
    y[3] = (x[3] - mu) * rstd * g0.w + be0.w;
    y[4] = (x[4] - mu) * rstd * g1.x + be1.x;
    y[5] = (x[5] - mu) * rstd * g1.y + be1.y;
    y[6] = (x[6] - mu) * rstd * g1.z + be1.z;
    y[7] = (x[7] - mu) * rstd * g1.w + be1.w;

    if (outF) {
        *(float4*)(outF + base) = make_float4(y[0], y[1], y[2], y[3]);
        *(float4*)(outF + base + 4) = make_float4(y[4], y[5], y[6], y[7]);
    }
    if (outH) {
        __half2 h[4] = {__floats2half2_rn(y[0], y[1]), __floats2half2_rn(y[2], y[3]),
                        __floats2half2_rn(y[4], y[5]), __floats2half2_rn(y[6], y[7])};
        *(float4*)(outH + base) = *(float4*)h;
    }
}

// ---------------- host orchestration ----------------
#define SYM(p, s) void* p; cudaGetSymbolAddress(&p, s)

extern "C" void kernel_launch(void* const* d_in, const int* in_sizes, int n_in,
                              void* d_out, int out_size) {
    (void)in_sizes; (void)n_in; (void)out_size;
    const float* Q    = (const float*)d_in[0];
    const float* K    = (const float*)d_in[1];
    const float* V    = (const float*)d_in[2];
    const void*  mask = d_in[3];
    const float* pe   = (const float*)d_in[4];
    const float* W_q  = (const float*)d_in[5];
    const float* W_k  = (const float*)d_in[6];
    const float* W_v  = (const float*)d_in[7];
    const float* W_o  = (const float*)d_in[8];
    const float* w1   = (const float*)d_in[9];
    const float* b1   = (const float*)d_in[10];
    const float* w2   = (const float*)d_in[11];
    const float* b2   = (const float*)d_in[12];
    const float* gamma = (const float*)d_in[13];
    const float* beta  = (const float*)d_in[14];
    float* out = (float*)d_out;

    SYM(pQpF, g_QpF);
    SYM(pQpH, g_QpH); SYM(pKpH, g_KpH); SYM(pVpH, g_VpH);
    SYM(pQhH, g_QhH); SYM(pKhH, g_KhH); SYM(pVtH, g_VtH);
    SYM(pVsum, g_Vsum); SYM(pVmH, g_VmH);
    SYM(pT1, g_T1); SYM(pXF, g_XF); SYM(pXH, g_XH); SYM(pYH, g_YH); SYM(pZF, g_ZF);
    SYM(pWq, g_Wq); SYM(pWk, g_Wk); SYM(pWv, g_Wv); SYM(pWo, g_Wo);
    SYM(pw1, g_w1); SYM(pw2, g_w2);

    cudaFuncSetAttribute(gemm_h, cudaFuncAttributeMaxDynamicSharedMemorySize, NSTG * STG);
    cudaFuncSetAttribute(flash_attn, cudaFuncAttributeMaxDynamicSharedMemorySize, FSM_TOT);

    typedef __half hf;

    // 1) mask decode (single launch, per-block dtype sniff)
    decode_mask_kernel<<<NTOK / 1024, 256>>>((const unsigned char*)mask);

    // 2) PE add + fp16 convert (Q, K, V in one launch)
    {
        int q4 = NTOK * DD / 4, qb = (q4 + 255) / 256;
        add_pe_all<<<dim3(qb, 3), 256>>>((const float4*)Q, (const float4*)K,
                                         (const float4*)V, pe, (float4*)pQpF,
                                         (__half2*)pQpH, (__half2*)pKpH, (__half2*)pVpH);
    }

    // 3) all weight conversions in one launch (grid.x = 256 — exact for the
    //    tiled transposes; the direct branch bounds-checks its surplus blocks)
    wconv_all<<<dim3(256, 6), 256>>>(W_q, W_k, W_v, W_o, w1, w2,
                                     (hf*)pWq, (hf*)pWk, (hf*)pWv, (hf*)pWo,
                                     (__half2*)pw1, (__half2*)pw2);

    // 4) ALL THREE projections in one launch:
    //    z=0: Qp@Wq -> Qh (headsplit), z=1: Kp@Wk -> Kh (headsplit),
    //    z=2: Wv@Vp -> Vt (swapped block map, transposed scatter)
    {
        dim3 g(HD / NT, NTOK / MT, 3);
        gemm_h<<<g, 256, NSTG * STG>>>((hf*)pQpH, (hf*)pWq, nullptr, (hf*)pQhH, nullptr,
                                       DD, 0, 0, 0, 0, MODE_HEADSPLIT, 1.0f, 0,
                                       (hf*)pKpH, (hf*)pWk, (hf*)pKhH,
                                       (hf*)pWv, (hf*)pVpH, (hf*)pVtH);
    }

    // 5) Vsum from Vt (warp per row)
    vsum_kernel<<<BH * DD / 8, 256>>>((const __half2*)pVtH, (float*)pVsum);

    // 6) fused flash attention -> merged (b, l, h*d); LPT: heavy q-tiles dispatch first
    {
        dim3 g(BH, LL / 128);
        flash_attn<<<g, 256, FSM_TOT>>>((hf*)pQhH, (hf*)pKhH, (hf*)pVtH,
                                        (float*)pVsum, (hf*)pVmH);
    }

    // 7) output projection: T1 = Vm @ W_o  (M=16384, N=256, K=1024)
    {
        dim3 g(DD / NT, NTOK / MT, 1);
        gemm_h<<<g, 256, NSTG * STG>>>((hf*)pVmH, (hf*)pWo, (float*)pT1, nullptr, nullptr,
                                       HD, 0, 0, 0, DD, MODE_PLAIN, 1.0f, 0,
                                       nullptr, nullptr, nullptr, nullptr, nullptr, nullptr);
    }

    // 8) X = LN(Qp + T1)
    ln_residual_kernel<<<NTOK / 8, 256>>>((float*)pQpF, (float*)pT1, gamma, beta,
                                          (float*)pXF, (hf*)pXH);

    // 9) FFN: Y = relu(X @ w1^T + b1); Z = Y @ w2^T + b2
    {
        dim3 g(DD / NT, NTOK / MT, 1);
        gemm_h<<<g, 256, NSTG * STG>>>((hf*)pXH, (hf*)pw1, nullptr, (hf*)pYH, b1,
                                       DD, 0, 0, 0, DD, MODE_PLAIN, 1.0f, 1,
                                       nullptr, nullptr, nullptr, nullptr, nullptr, nullptr);
        gemm_h<<<g, 256, NSTG * STG>>>((hf*)pYH, (hf*)pw2, (float*)pZF, nullptr, b2,
                                       DD, 0, 0, 0, DD, MODE_PLAIN, 1.0f, 0,
                                       nullptr, nullptr, nullptr, nullptr, nullptr, nullptr);
    }

    // 10) out = LN(Z + X)
    ln_residual_kernel<<<NTOK / 8, 256>>>((float*)pZF, (float*)pXF, gamma, beta, out, nullptr);
}